// round 10
// baseline (speedup 1.0000x reference)
#include <cuda_runtime.h>
#include <cuda_bf16.h>
#include <math.h>

// ---------------- problem constants ----------------
#define NN    50000
#define EE    800000
#define EP    850000          // EE + NN self loops
#define INC   1024
#define H1    4
#define C1    64
#define HC1   256             // H1*C1
#define OC    64
#define NEG_SLOPE 0.2f

#define SCAN_T 512
#define NTILES ((NN + SCAN_T - 1) / SCAN_T)

// ---------------- scratch (device globals) ----------------
__device__ float  g_h1[(size_t)NN * HC1];
__device__ float  g_x2[(size_t)NN * HC1];
__device__ float  g_as1[NN * H1];
__device__ float  g_ad1[NN * H1];
__device__ float4 g_alpha1[EP];               // per-edge exp values (4 heads), CSR order
__device__ float4 g_rd1[NN];                  // reciprocal softmax denominators

__device__ float  g_h2[(size_t)NN * OC];
__device__ float  g_as2[NN];
__device__ float  g_ad2[NN];
__device__ float  g_alpha2[EP];
__device__ float  g_rd2[NN];

// CSR
__device__ int g_deg[NN];
__device__ int g_rowptr[NN + 1];
__device__ int g_cursor[NN];
__device__ int g_srcidx[EP];
__device__ int g_bsum[NTILES];

__device__ __forceinline__ unsigned f2tf32(float f) {
    unsigned r;
    asm("cvt.rna.tf32.f32 %0, %1;" : "=r"(r) : "f"(f));
    return r;
}
__device__ __forceinline__ uint4 cvt4(float4 v) {
    uint4 r;
    r.x = f2tf32(v.x); r.y = f2tf32(v.y); r.z = f2tf32(v.z); r.w = f2tf32(v.w);
    return r;
}

// ================= init + CSR construction =================
__global__ void k_zero() {
    int i = blockIdx.x * blockDim.x + threadIdx.x;
    if (i >= NN) return;
    g_deg[i] = 0;
    g_as2[i] = 0.f; g_ad2[i] = 0.f;
    float4 z = make_float4(0.f, 0.f, 0.f, 0.f);
    ((float4*)g_as1)[i] = z;
    ((float4*)g_ad1)[i] = z;
}
__global__ void k_count(const int* __restrict__ ei) {
    int e = blockIdx.x * blockDim.x + threadIdx.x;
    if (e >= EP) return;
    int dn = (e < EE) ? ei[EE + e] : (e - EE);
    atomicAdd(&g_deg[dn], 1);
}
__global__ __launch_bounds__(SCAN_T) void k_scan1() {
    __shared__ int s[SCAN_T];
    int tid = threadIdx.x;
    int i = blockIdx.x * SCAN_T + tid;
    int v = (i < NN) ? g_deg[i] : 0;
    s[tid] = v;
    __syncthreads();
    #pragma unroll
    for (int off = 1; off < SCAN_T; off <<= 1) {
        int t = (tid >= off) ? s[tid - off] : 0;
        __syncthreads();
        s[tid] += t;
        __syncthreads();
    }
    if (i < NN) g_rowptr[i + 1] = s[tid];
    if (tid == SCAN_T - 1) g_bsum[blockIdx.x] = s[tid];
}
__global__ void k_scan2() {
    if (threadIdx.x == 0) {
        int run = 0;
        for (int t = 0; t < NTILES; t++) { int v = g_bsum[t]; g_bsum[t] = run; run += v; }
        g_rowptr[0] = 0;
    }
}
__global__ __launch_bounds__(SCAN_T) void k_scan3() {
    int i = blockIdx.x * SCAN_T + threadIdx.x;
    if (i < NN) g_rowptr[i + 1] += g_bsum[blockIdx.x];
}
__global__ void k_setcur() {
    int i = blockIdx.x * blockDim.x + threadIdx.x;
    if (i < NN) g_cursor[i] = g_rowptr[i];
}
__global__ void k_scatter(const int* __restrict__ ei) {
    int e = blockIdx.x * blockDim.x + threadIdx.x;
    if (e >= EP) return;
    int s, dn;
    if (e < EE) { s = ei[e]; dn = ei[EE + e]; }
    else        { s = e - EE; dn = s; }
    int pos = atomicAdd(&g_cursor[dn], 1);
    g_srcidx[pos] = s;
}

// ============= TF32 GEMM + fused attention-coefficient epilogue ==============
// TSS=36 layout (round-6 verified fragment geometry); STS.128 stores.
#define TBM 128
#define TBN 128
#define TBK 32
#define TSS 36
#define GEMM_SMEM_BYTES (4 * TBM * TSS * 4)

__global__ __launch_bounds__(256) void k_tf32gemm(
    const float* __restrict__ A, const float* __restrict__ B,
    float* __restrict__ C, int M, int N, int K,
    const float* __restrict__ avs, const float* __restrict__ avd,
    float* __restrict__ as_out, float* __restrict__ ad_out, int heads)
{
    extern __shared__ unsigned smem_u[];
    unsigned* Abase = smem_u;
    unsigned* Bbase = smem_u + 2 * TBM * TSS;

    int tid = threadIdx.x;
    int bm = blockIdx.y * TBM, bn = blockIdx.x * TBN;
    int wid = tid >> 5, lane = tid & 31;
    int wm = (wid >> 2) * 64;
    int wn = (wid & 3) * 32;
    int g  = lane >> 2;
    int t4 = lane & 3;

    int r0 = tid >> 3;
    int c4 = (tid & 7) * 4;

    float c[4][4][4];
    #pragma unroll
    for (int i = 0; i < 4; i++)
        #pragma unroll
        for (int j = 0; j < 4; j++)
            #pragma unroll
            for (int r = 0; r < 4; r++) c[i][j][r] = 0.f;

    const float4 zero4 = make_float4(0.f, 0.f, 0.f, 0.f);
    float4 pa[4], pb[4];
    int nt = K / TBK;

    // fetch + store tile 0 -> buf 0
    #pragma unroll
    for (int i = 0; i < 4; i++) {
        int ar = bm + r0 + 32 * i;
        pa[i] = (ar < M) ? *(const float4*)(A + (size_t)ar * K + c4) : zero4;
        int br = bn + r0 + 32 * i;
        pb[i] = (br < N) ? *(const float4*)(B + (size_t)br * K + c4) : zero4;
    }
    #pragma unroll
    for (int i = 0; i < 4; i++) {
        int rr = r0 + 32 * i;
        *(uint4*)&Abase[rr * TSS + c4] = cvt4(pa[i]);
        *(uint4*)&Bbase[rr * TSS + c4] = cvt4(pb[i]);
    }
    __syncthreads();

    for (int t = 0; t < nt; t++) {
        int cur = t & 1;
        bool more = (t + 1 < nt);
        if (more) {
            int k0 = (t + 1) * TBK;
            #pragma unroll
            for (int i = 0; i < 4; i++) {
                int ar = bm + r0 + 32 * i;
                pa[i] = (ar < M) ? *(const float4*)(A + (size_t)ar * K + k0 + c4) : zero4;
                int br = bn + r0 + 32 * i;
                pb[i] = (br < N) ? *(const float4*)(B + (size_t)br * K + k0 + c4) : zero4;
            }
        }
        const unsigned* Ab = Abase + cur * TBM * TSS;
        const unsigned* Bb = Bbase + cur * TBM * TSS;
        #pragma unroll
        for (int ks = 0; ks < 4; ks++) {
            int k8 = ks * 8;
            unsigned af[4][4], bf[4][2];
            #pragma unroll
            for (int mt = 0; mt < 4; mt++) {
                int row = wm + mt * 16 + g;
                af[mt][0] = Ab[row * TSS + k8 + t4];
                af[mt][1] = Ab[(row + 8) * TSS + k8 + t4];
                af[mt][2] = Ab[row * TSS + k8 + t4 + 4];
                af[mt][3] = Ab[(row + 8) * TSS + k8 + t4 + 4];
            }
            #pragma unroll
            for (int ntj = 0; ntj < 4; ntj++) {
                int col = wn + ntj * 8 + g;
                bf[ntj][0] = Bb[col * TSS + k8 + t4];
                bf[ntj][1] = Bb[col * TSS + k8 + t4 + 4];
            }
            #pragma unroll
            for (int mt = 0; mt < 4; mt++)
                #pragma unroll
                for (int ntj = 0; ntj < 4; ntj++) {
                    asm volatile(
                        "mma.sync.aligned.m16n8k8.row.col.f32.tf32.tf32.f32 "
                        "{%0,%1,%2,%3}, {%4,%5,%6,%7}, {%8,%9}, {%0,%1,%2,%3};"
                        : "+f"(c[mt][ntj][0]), "+f"(c[mt][ntj][1]),
                          "+f"(c[mt][ntj][2]), "+f"(c[mt][ntj][3])
                        : "r"(af[mt][0]), "r"(af[mt][1]), "r"(af[mt][2]), "r"(af[mt][3]),
                          "r"(bf[ntj][0]), "r"(bf[ntj][1]));
                }
        }
        if (more) {
            int nx = cur ^ 1;
            unsigned* Aw = Abase + nx * TBM * TSS;
            unsigned* Bw = Bbase + nx * TBM * TSS;
            #pragma unroll
            for (int i = 0; i < 4; i++) {
                int rr = r0 + 32 * i;
                *(uint4*)&Aw[rr * TSS + c4] = cvt4(pa[i]);
                *(uint4*)&Bw[rr * TSS + c4] = cvt4(pb[i]);
            }
            __syncthreads();
        }
    }

    // ---- C store ----
    #pragma unroll
    for (int mt = 0; mt < 4; mt++) {
        int row0 = bm + wm + mt * 16 + g;
        #pragma unroll
        for (int ntj = 0; ntj < 4; ntj++) {
            int col = bn + wn + ntj * 8 + t4 * 2;
            if (row0 < M && col + 1 < N) {
                C[(size_t)row0 * N + col]     = c[mt][ntj][0];
                C[(size_t)row0 * N + col + 1] = c[mt][ntj][1];
            }
            if (row0 + 8 < M && col + 1 < N) {
                C[(size_t)(row0 + 8) * N + col]     = c[mt][ntj][2];
                C[(size_t)(row0 + 8) * N + col + 1] = c[mt][ntj][3];
            }
        }
    }

    // ---- fused attention-coefficient partials ----
    int head = (bn + wn) >> 6;
    if (head < heads) {
        float asac[4][2] = {}, adac[4][2] = {};
        #pragma unroll
        for (int mt = 0; mt < 4; mt++)
            #pragma unroll
            for (int ntj = 0; ntj < 4; ntj++) {
                int colb = bn + wn + ntj * 8 + t4 * 2;
                if (colb + 1 < N) {
                    float s0 = avs[colb], s1 = avs[colb + 1];
                    float d0 = avd[colb], d1 = avd[colb + 1];
                    asac[mt][0] += c[mt][ntj][0] * s0 + c[mt][ntj][1] * s1;
                    adac[mt][0] += c[mt][ntj][0] * d0 + c[mt][ntj][1] * d1;
                    asac[mt][1] += c[mt][ntj][2] * s0 + c[mt][ntj][3] * s1;
                    adac[mt][1] += c[mt][ntj][2] * d0 + c[mt][ntj][3] * d1;
                }
            }
        #pragma unroll
        for (int mt = 0; mt < 4; mt++)
            #pragma unroll
            for (int hf = 0; hf < 2; hf++) {
                float v = asac[mt][hf];
                float w = adac[mt][hf];
                v += __shfl_xor_sync(0xFFFFFFFFu, v, 1);
                v += __shfl_xor_sync(0xFFFFFFFFu, v, 2);
                w += __shfl_xor_sync(0xFFFFFFFFu, w, 1);
                w += __shfl_xor_sync(0xFFFFFFFFu, w, 2);
                int row = bm + wm + mt * 16 + g + hf * 8;
                if (t4 == 0 && row < M) {
                    atomicAdd(&as_out[row * heads + head], v);
                    atomicAdd(&ad_out[row * heads + head], w);
                }
            }
    }
}

// ---------------- softmax layer 1: warp per dst node, 4 heads ----------------
__global__ __launch_bounds__(256) void k_softmax1()
{
    int w = (blockIdx.x * blockDim.x + threadIdx.x) >> 5;
    int lane = threadIdx.x & 31;
    if (w >= NN) return;
    int beg = g_rowptr[w], end = g_rowptr[w + 1];
    const float4* as4 = (const float4*)g_as1;
    float4 adv = ((const float4*)g_ad1)[w];
    float4 mx = make_float4(-1e30f, -1e30f, -1e30f, -1e30f);
    for (int i = beg + lane; i < end; i += 32) {
        float4 e = as4[g_srcidx[i]];
        e.x += adv.x; e.y += adv.y; e.z += adv.z; e.w += adv.w;
        e.x = (e.x > 0.f) ? e.x : NEG_SLOPE * e.x;
        e.y = (e.y > 0.f) ? e.y : NEG_SLOPE * e.y;
        e.z = (e.z > 0.f) ? e.z : NEG_SLOPE * e.z;
        e.w = (e.w > 0.f) ? e.w : NEG_SLOPE * e.w;
        g_alpha1[i] = e;
        mx.x = fmaxf(mx.x, e.x); mx.y = fmaxf(mx.y, e.y);
        mx.z = fmaxf(mx.z, e.z); mx.w = fmaxf(mx.w, e.w);
    }
    #pragma unroll
    for (int o = 16; o > 0; o >>= 1) {
        mx.x = fmaxf(mx.x, __shfl_xor_sync(0xFFFFFFFFu, mx.x, o));
        mx.y = fmaxf(mx.y, __shfl_xor_sync(0xFFFFFFFFu, mx.y, o));
        mx.z = fmaxf(mx.z, __shfl_xor_sync(0xFFFFFFFFu, mx.z, o));
        mx.w = fmaxf(mx.w, __shfl_xor_sync(0xFFFFFFFFu, mx.w, o));
    }
    float4 sum = make_float4(0.f, 0.f, 0.f, 0.f);
    for (int i = beg + lane; i < end; i += 32) {
        float4 e = g_alpha1[i];
        e.x = __expf(e.x - mx.x); e.y = __expf(e.y - mx.y);
        e.z = __expf(e.z - mx.z); e.w = __expf(e.w - mx.w);
        g_alpha1[i] = e;
        sum.x += e.x; sum.y += e.y; sum.z += e.z; sum.w += e.w;
    }
    #pragma unroll
    for (int o = 16; o > 0; o >>= 1) {
        sum.x += __shfl_xor_sync(0xFFFFFFFFu, sum.x, o);
        sum.y += __shfl_xor_sync(0xFFFFFFFFu, sum.y, o);
        sum.z += __shfl_xor_sync(0xFFFFFFFFu, sum.z, o);
        sum.w += __shfl_xor_sync(0xFFFFFFFFu, sum.w, o);
    }
    if (lane == 0)
        g_rd1[w] = make_float4(1.f / sum.x, 1.f / sum.y, 1.f / sum.z, 1.f / sum.w);
}

// ---------------- softmax layer 2 --------------------------------------------
__global__ __launch_bounds__(256) void k_softmax2()
{
    int w = (blockIdx.x * blockDim.x + threadIdx.x) >> 5;
    int lane = threadIdx.x & 31;
    if (w >= NN) return;
    int beg = g_rowptr[w], end = g_rowptr[w + 1];
    float adv = g_ad2[w];
    float mx = -1e30f;
    for (int i = beg + lane; i < end; i += 32) {
        float e = g_as2[g_srcidx[i]] + adv;
        e = (e > 0.f) ? e : NEG_SLOPE * e;
        g_alpha2[i] = e;
        mx = fmaxf(mx, e);
    }
    #pragma unroll
    for (int o = 16; o > 0; o >>= 1)
        mx = fmaxf(mx, __shfl_xor_sync(0xFFFFFFFFu, mx, o));
    float sum = 0.f;
    for (int i = beg + lane; i < end; i += 32) {
        float e = __expf(g_alpha2[i] - mx);
        g_alpha2[i] = e;
        sum += e;
    }
    #pragma unroll
    for (int o = 16; o > 0; o >>= 1)
        sum += __shfl_xor_sync(0xFFFFFFFFu, sum, o);
    if (lane == 0) g_rd2[w] = 1.f / sum;
}

// ---- aggregation layer 1: 64 threads per dst row, 4-way unroll --------------
__global__ __launch_bounds__(256) void k_agg1(const float* __restrict__ b1)
{
    int row = blockIdx.x * 4 + (threadIdx.x >> 6);
    if (row >= NN) return;
    int q = threadIdx.x & 63;
    int head = q >> 4;
    int beg = g_rowptr[row], end = g_rowptr[row + 1];
    float4 rdv = g_rd1[row];
    float rd = (head == 0) ? rdv.x : (head == 1) ? rdv.y : (head == 2) ? rdv.z : rdv.w;
    float4 acc0 = make_float4(0.f, 0.f, 0.f, 0.f);
    float4 acc1 = make_float4(0.f, 0.f, 0.f, 0.f);
    float4 acc2 = make_float4(0.f, 0.f, 0.f, 0.f);
    float4 acc3 = make_float4(0.f, 0.f, 0.f, 0.f);
    int i = beg;
    for (; i + 4 <= end; i += 4) {
        int s0 = g_srcidx[i],     s1 = g_srcidx[i + 1];
        int s2 = g_srcidx[i + 2], s3 = g_srcidx[i + 3];
        float4 a40 = g_alpha1[i],     a41 = g_alpha1[i + 1];
        float4 a42 = g_alpha1[i + 2], a43 = g_alpha1[i + 3];
        float a0 = (head == 0) ? a40.x : (head == 1) ? a40.y : (head == 2) ? a40.z : a40.w;
        float a1 = (head == 0) ? a41.x : (head == 1) ? a41.y : (head == 2) ? a41.z : a41.w;
        float a2 = (head == 0) ? a42.x : (head == 1) ? a42.y : (head == 2) ? a42.z : a42.w;
        float a3 = (head == 0) ? a43.x : (head == 1) ? a43.y : (head == 2) ? a43.z : a43.w;
        float4 h0 = *(const float4*)(g_h1 + (size_t)s0 * HC1 + q * 4);
        float4 h1 = *(const float4*)(g_h1 + (size_t)s1 * HC1 + q * 4);
        float4 h2 = *(const float4*)(g_h1 + (size_t)s2 * HC1 + q * 4);
        float4 h3 = *(const float4*)(g_h1 + (size_t)s3 * HC1 + q * 4);
        acc0.x += a0 * h0.x; acc0.y += a0 * h0.y; acc0.z += a0 * h0.z; acc0.w += a0 * h0.w;
        acc1.x += a1 * h1.x; acc1.y += a1 * h1.y; acc1.z += a1 * h1.z; acc1.w += a1 * h1.w;
        acc2.x += a2 * h2.x; acc2.y += a2 * h2.y; acc2.z += a2 * h2.z; acc2.w += a2 * h2.w;
        acc3.x += a3 * h3.x; acc3.y += a3 * h3.y; acc3.z += a3 * h3.z; acc3.w += a3 * h3.w;
    }
    for (; i < end; i++) {
        int s0 = g_srcidx[i];
        float4 a40 = g_alpha1[i];
        float a0 = (head == 0) ? a40.x : (head == 1) ? a40.y : (head == 2) ? a40.z : a40.w;
        float4 h0 = *(const float4*)(g_h1 + (size_t)s0 * HC1 + q * 4);
        acc0.x += a0 * h0.x; acc0.y += a0 * h0.y; acc0.z += a0 * h0.z; acc0.w += a0 * h0.w;
    }
    float4 acc = make_float4(((acc0.x + acc1.x) + (acc2.x + acc3.x)) * rd,
                             ((acc0.y + acc1.y) + (acc2.y + acc3.y)) * rd,
                             ((acc0.z + acc1.z) + (acc2.z + acc3.z)) * rd,
                             ((acc0.w + acc1.w) + (acc2.w + acc3.w)) * rd);
    float4 bb = *(const float4*)(b1 + q * 4);
    acc.x += bb.x; acc.y += bb.y; acc.z += bb.z; acc.w += bb.w;
    acc.x = (acc.x > 0.f) ? acc.x : expm1f(acc.x);
    acc.y = (acc.y > 0.f) ? acc.y : expm1f(acc.y);
    acc.z = (acc.z > 0.f) ? acc.z : expm1f(acc.z);
    acc.w = (acc.w > 0.f) ? acc.w : expm1f(acc.w);
    *(float4*)(g_x2 + (size_t)row * HC1 + q * 4) = acc;
}

// ---- aggregation layer 2: 16 threads per dst row, 4-way unroll --------------
__global__ __launch_bounds__(256) void k_agg2(const float* __restrict__ b2,
                                              float* __restrict__ out)
{
    int row = blockIdx.x * 16 + (threadIdx.x >> 4);
    if (row >= NN) return;
    int q = threadIdx.x & 15;
    int beg = g_rowptr[row], end = g_rowptr[row + 1];
    float rd = g_rd2[row];
    float4 acc0 = make_float4(0.f, 0.f, 0.f, 0.f);
    float4 acc1 = make_float4(0.f, 0.f, 0.f, 0.f);
    float4 acc2 = make_float4(0.f, 0.f, 0.f, 0.f);
    float4 acc3 = make_float4(0.f, 0.f, 0.f, 0.f);
    int i = beg;
    for (; i + 4 <= end; i += 4) {
        int s0 = g_srcidx[i],     s1 = g_srcidx[i + 1];
        int s2 = g_srcidx[i + 2], s3 = g_srcidx[i + 3];
        float a0 = g_alpha2[i],     a1 = g_alpha2[i + 1];
        float a2 = g_alpha2[i + 2], a3 = g_alpha2[i + 3];
        float4 h0 = *(const float4*)(g_h2 + (size_t)s0 * OC + q * 4);
        float4 h1 = *(const float4*)(g_h2 + (size_t)s1 * OC + q * 4);
        float4 h2 = *(const float4*)(g_h2 + (size_t)s2 * OC + q * 4);
        float4 h3 = *(const float4*)(g_h2 + (size_t)s3 * OC + q * 4);
        acc0.x += a0 * h0.x; acc0.y += a0 * h0.y; acc0.z += a0 * h0.z; acc0.w += a0 * h0.w;
        acc1.x += a1 * h1.x; acc1.y += a1 * h1.y; acc1.z += a1 * h1.z; acc1.w += a1 * h1.w;
        acc2.x += a2 * h2.x; acc2.y += a2 * h2.y; acc2.z += a2 * h2.z; acc2.w += a2 * h2.w;
        acc3.x += a3 * h3.x; acc3.y += a3 * h3.y; acc3.z += a3 * h3.z; acc3.w += a3 * h3.w;
    }
    for (; i < end; i++) {
        int s0 = g_srcidx[i];
        float a0 = g_alpha2[i];
        float4 h0 = *(const float4*)(g_h2 + (size_t)s0 * OC + q * 4);
        acc0.x += a0 * h0.x; acc0.y += a0 * h0.y; acc0.z += a0 * h0.z; acc0.w += a0 * h0.w;
    }
    float4 bb = *(const float4*)(b2 + q * 4);
    float4 acc = make_float4(((acc0.x + acc1.x) + (acc2.x + acc3.x)) * rd + bb.x,
                             ((acc0.y + acc1.y) + (acc2.y + acc3.y)) * rd + bb.y,
                             ((acc0.z + acc1.z) + (acc2.z + acc3.z)) * rd + bb.z,
                             ((acc0.w + acc1.w) + (acc2.w + acc3.w)) * rd + bb.w);
    *(float4*)(out + (size_t)row * OC + q * 4) = acc;
}

// =============================================================================
extern "C" void kernel_launch(void* const* d_in, const int* in_sizes, int n_in,
                              void* d_out, int out_size)
{
    const float* x     = (const float*)d_in[0];
    const int*   ei    = (const int*)d_in[1];
    const float* W1    = (const float*)d_in[2];
    const float* a_s1  = (const float*)d_in[3];
    const float* a_d1  = (const float*)d_in[4];
    const float* b1    = (const float*)d_in[5];
    const float* W2    = (const float*)d_in[6];
    const float* a_s2  = (const float*)d_in[7];
    const float* a_d2  = (const float*)d_in[8];
    const float* b2    = (const float*)d_in[9];
    float*       out   = (float*)d_out;

    float *h1, *x2, *as1, *ad1, *h2, *as2, *ad2;
    cudaGetSymbolAddress((void**)&h1,  g_h1);
    cudaGetSymbolAddress((void**)&x2,  g_x2);
    cudaGetSymbolAddress((void**)&as1, g_as1);
    cudaGetSymbolAddress((void**)&ad1, g_ad1);
    cudaGetSymbolAddress((void**)&h2,  g_h2);
    cudaGetSymbolAddress((void**)&as2, g_as2);
    cudaGetSymbolAddress((void**)&ad2, g_ad2);

    cudaFuncSetAttribute(k_tf32gemm,
                         cudaFuncAttributeMaxDynamicSharedMemorySize, GEMM_SMEM_BYTES);

    // ---- init + CSR build (multi-block scan; verified) ----
    k_zero<<<(NN + 255) / 256, 256>>>();
    k_count<<<(EP + 255) / 256, 256>>>(ei);
    k_scan1<<<NTILES, SCAN_T>>>();
    k_scan2<<<1, 32>>>();
    k_scan3<<<NTILES, SCAN_T>>>();
    k_setcur<<<(NN + 255) / 256, 256>>>();
    k_scatter<<<(EP + 255) / 256, 256>>>(ei);

    // ---- layer 1 ----
    {
        dim3 grid((HC1 + TBN - 1) / TBN, (NN + TBM - 1) / TBM);
        k_tf32gemm<<<grid, 256, GEMM_SMEM_BYTES>>>(x, W1, h1, NN, HC1, INC,
                                                   a_s1, a_d1, as1, ad1, H1);
    }
    k_softmax1<<<(NN * 32 + 255) / 256, 256>>>();
    k_agg1<<<(NN + 3) / 4, 256>>>(b1);

    // ---- layer 2 ----
    {
        dim3 grid((OC + TBN - 1) / TBN, (NN + TBM - 1) / TBM);
        k_tf32gemm<<<grid, 256, GEMM_SMEM_BYTES>>>(x2, W2, h2, NN, OC, HC1,
                                                   a_s2, a_d2, as2, ad2, 1);
    }
    k_softmax2<<<(NN * 32 + 255) / 256, 256>>>();
    k_agg2<<<(NN + 15) / 16, 256>>>(b2, out);
}

// round 11
// speedup vs baseline: 1.1629x; 1.1629x over previous
#include <cuda_runtime.h>
#include <cuda_bf16.h>
#include <math.h>

// ---------------- problem constants ----------------
#define NN    50000
#define EE    800000
#define EP    850000          // EE + NN self loops
#define INC   1024
#define H1    4
#define C1    64
#define HC1   256             // H1*C1
#define OC    64
#define NEG_SLOPE 0.2f

#define SCAN_T 512
#define NTILES ((NN + SCAN_T - 1) / SCAN_T)

// ---------------- scratch (device globals) ----------------
__device__ float  g_h1[(size_t)NN * HC1];
__device__ float  g_x2[(size_t)NN * HC1];
__device__ float  g_as1[NN * H1];
__device__ float  g_ad1[NN * H1];
__device__ float4 g_alpha1[EP];               // per-edge exp values (4 heads), CSR order
__device__ float4 g_rd1[NN];                  // reciprocal softmax denominators

__device__ float  g_h2[(size_t)NN * OC];
__device__ float  g_as2[NN];
__device__ float  g_ad2[NN];
__device__ float  g_alpha2[EP];
__device__ float  g_rd2[NN];

// CSR
__device__ int g_deg[NN];
__device__ int g_rowptr[NN + 1];
__device__ int g_cursor[NN];
__device__ int g_srcidx[EP];
__device__ int g_bsum[NTILES];

__device__ __forceinline__ unsigned f2tf32(float f) {
    unsigned r;
    asm("cvt.rna.tf32.f32 %0, %1;" : "=r"(r) : "f"(f));
    return r;
}

// ================= init + CSR construction =================
__global__ void k_zero() {
    int i = blockIdx.x * blockDim.x + threadIdx.x;
    if (i >= NN) return;
    g_deg[i] = 0;
    g_as2[i] = 0.f; g_ad2[i] = 0.f;
    float4 z = make_float4(0.f, 0.f, 0.f, 0.f);
    ((float4*)g_as1)[i] = z;
    ((float4*)g_ad1)[i] = z;
}
__global__ void k_count(const int* __restrict__ ei) {
    int e = blockIdx.x * blockDim.x + threadIdx.x;
    if (e >= EP) return;
    int dn = (e < EE) ? ei[EE + e] : (e - EE);
    atomicAdd(&g_deg[dn], 1);
}
__global__ __launch_bounds__(SCAN_T) void k_scan1() {
    __shared__ int s[SCAN_T];
    int tid = threadIdx.x;
    int i = blockIdx.x * SCAN_T + tid;
    int v = (i < NN) ? g_deg[i] : 0;
    s[tid] = v;
    __syncthreads();
    #pragma unroll
    for (int off = 1; off < SCAN_T; off <<= 1) {
        int t = (tid >= off) ? s[tid - off] : 0;
        __syncthreads();
        s[tid] += t;
        __syncthreads();
    }
    if (i < NN) g_rowptr[i + 1] = s[tid];
    if (tid == SCAN_T - 1) g_bsum[blockIdx.x] = s[tid];
}
__global__ void k_scan2() {
    if (threadIdx.x == 0) {
        int run = 0;
        for (int t = 0; t < NTILES; t++) { int v = g_bsum[t]; g_bsum[t] = run; run += v; }
        g_rowptr[0] = 0;
    }
}
__global__ __launch_bounds__(SCAN_T) void k_scan3() {
    int i = blockIdx.x * SCAN_T + threadIdx.x;
    if (i < NN) g_rowptr[i + 1] += g_bsum[blockIdx.x];
}
__global__ void k_setcur() {
    int i = blockIdx.x * blockDim.x + threadIdx.x;
    if (i < NN) g_cursor[i] = g_rowptr[i];
}
__global__ void k_scatter(const int* __restrict__ ei) {
    int e = blockIdx.x * blockDim.x + threadIdx.x;
    if (e >= EP) return;
    int s, dn;
    if (e < EE) { s = ei[e]; dn = ei[EE + e]; }
    else        { s = e - EE; dn = s; }
    int pos = atomicAdd(&g_cursor[dn], 1);
    g_srcidx[pos] = s;
}

// ============= TF32 GEMM + fused attention-coefficient epilogue ==============
// (round-6/9 verified layout: TSS=36, scalar fragment loads, double buffered)
// __launch_bounds__(256, 2): force 2 CTAs/SM for latency hiding.
#define TBM 128
#define TBN 128
#define TBK 32
#define TSS 36
#define GEMM_SMEM_BYTES (4 * TBM * TSS * 4)

__global__ __launch_bounds__(256, 2) void k_tf32gemm(
    const float* __restrict__ A, const float* __restrict__ B,
    float* __restrict__ C, int M, int N, int K,
    const float* __restrict__ avs, const float* __restrict__ avd,
    float* __restrict__ as_out, float* __restrict__ ad_out, int heads)
{
    extern __shared__ unsigned smem_u[];
    unsigned* Abase = smem_u;
    unsigned* Bbase = smem_u + 2 * TBM * TSS;

    int tid = threadIdx.x;
    int bm = blockIdx.y * TBM, bn = blockIdx.x * TBN;
    int wid = tid >> 5, lane = tid & 31;
    int wm = (wid >> 2) * 64;
    int wn = (wid & 3) * 32;
    int g  = lane >> 2;
    int t4 = lane & 3;

    int r0 = tid >> 3;
    int c4 = (tid & 7) * 4;

    float c[4][4][4];
    #pragma unroll
    for (int i = 0; i < 4; i++)
        #pragma unroll
        for (int j = 0; j < 4; j++)
            #pragma unroll
            for (int r = 0; r < 4; r++) c[i][j][r] = 0.f;

    const float4 zero4 = make_float4(0.f, 0.f, 0.f, 0.f);
    float4 pa[4], pb[4];
    int nt = K / TBK;

    #pragma unroll
    for (int i = 0; i < 4; i++) {
        int ar = bm + r0 + 32 * i;
        pa[i] = (ar < M) ? *(const float4*)(A + (size_t)ar * K + c4) : zero4;
        int br = bn + r0 + 32 * i;
        pb[i] = (br < N) ? *(const float4*)(B + (size_t)br * K + c4) : zero4;
    }
    {
        unsigned* Ab = Abase;
        unsigned* Bb = Bbase;
        #pragma unroll
        for (int i = 0; i < 4; i++) {
            int rr = r0 + 32 * i;
            Ab[rr * TSS + c4 + 0] = f2tf32(pa[i].x); Ab[rr * TSS + c4 + 1] = f2tf32(pa[i].y);
            Ab[rr * TSS + c4 + 2] = f2tf32(pa[i].z); Ab[rr * TSS + c4 + 3] = f2tf32(pa[i].w);
            Bb[rr * TSS + c4 + 0] = f2tf32(pb[i].x); Bb[rr * TSS + c4 + 1] = f2tf32(pb[i].y);
            Bb[rr * TSS + c4 + 2] = f2tf32(pb[i].z); Bb[rr * TSS + c4 + 3] = f2tf32(pb[i].w);
        }
    }
    __syncthreads();

    for (int t = 0; t < nt; t++) {
        int cur = t & 1;
        bool more = (t + 1 < nt);
        if (more) {
            int k0 = (t + 1) * TBK;
            #pragma unroll
            for (int i = 0; i < 4; i++) {
                int ar = bm + r0 + 32 * i;
                pa[i] = (ar < M) ? *(const float4*)(A + (size_t)ar * K + k0 + c4) : zero4;
                int br = bn + r0 + 32 * i;
                pb[i] = (br < N) ? *(const float4*)(B + (size_t)br * K + k0 + c4) : zero4;
            }
        }
        const unsigned* Ab = Abase + cur * TBM * TSS;
        const unsigned* Bb = Bbase + cur * TBM * TSS;
        #pragma unroll
        for (int ks = 0; ks < 4; ks++) {
            int k8 = ks * 8;
            unsigned af[4][4], bf[4][2];
            #pragma unroll
            for (int mt = 0; mt < 4; mt++) {
                int row = wm + mt * 16 + g;
                af[mt][0] = Ab[row * TSS + k8 + t4];
                af[mt][1] = Ab[(row + 8) * TSS + k8 + t4];
                af[mt][2] = Ab[row * TSS + k8 + t4 + 4];
                af[mt][3] = Ab[(row + 8) * TSS + k8 + t4 + 4];
            }
            #pragma unroll
            for (int ntj = 0; ntj < 4; ntj++) {
                int col = wn + ntj * 8 + g;
                bf[ntj][0] = Bb[col * TSS + k8 + t4];
                bf[ntj][1] = Bb[col * TSS + k8 + t4 + 4];
            }
            #pragma unroll
            for (int mt = 0; mt < 4; mt++)
                #pragma unroll
                for (int ntj = 0; ntj < 4; ntj++) {
                    asm volatile(
                        "mma.sync.aligned.m16n8k8.row.col.f32.tf32.tf32.f32 "
                        "{%0,%1,%2,%3}, {%4,%5,%6,%7}, {%8,%9}, {%0,%1,%2,%3};"
                        : "+f"(c[mt][ntj][0]), "+f"(c[mt][ntj][1]),
                          "+f"(c[mt][ntj][2]), "+f"(c[mt][ntj][3])
                        : "r"(af[mt][0]), "r"(af[mt][1]), "r"(af[mt][2]), "r"(af[mt][3]),
                          "r"(bf[ntj][0]), "r"(bf[ntj][1]));
                }
        }
        if (more) {
            int nx = cur ^ 1;
            unsigned* Aw = Abase + nx * TBM * TSS;
            unsigned* Bw = Bbase + nx * TBM * TSS;
            #pragma unroll
            for (int i = 0; i < 4; i++) {
                int rr = r0 + 32 * i;
                Aw[rr * TSS + c4 + 0] = f2tf32(pa[i].x); Aw[rr * TSS + c4 + 1] = f2tf32(pa[i].y);
                Aw[rr * TSS + c4 + 2] = f2tf32(pa[i].z); Aw[rr * TSS + c4 + 3] = f2tf32(pa[i].w);
                Bw[rr * TSS + c4 + 0] = f2tf32(pb[i].x); Bw[rr * TSS + c4 + 1] = f2tf32(pb[i].y);
                Bw[rr * TSS + c4 + 2] = f2tf32(pb[i].z); Bw[rr * TSS + c4 + 3] = f2tf32(pb[i].w);
            }
            __syncthreads();
        }
    }

    // ---- C store ----
    #pragma unroll
    for (int mt = 0; mt < 4; mt++) {
        int row0 = bm + wm + mt * 16 + g;
        #pragma unroll
        for (int ntj = 0; ntj < 4; ntj++) {
            int col = bn + wn + ntj * 8 + t4 * 2;
            if (row0 < M && col + 1 < N) {
                C[(size_t)row0 * N + col]     = c[mt][ntj][0];
                C[(size_t)row0 * N + col + 1] = c[mt][ntj][1];
            }
            if (row0 + 8 < M && col + 1 < N) {
                C[(size_t)(row0 + 8) * N + col]     = c[mt][ntj][2];
                C[(size_t)(row0 + 8) * N + col + 1] = c[mt][ntj][3];
            }
        }
    }

    // ---- fused attention-coefficient partials ----
    int head = (bn + wn) >> 6;
    if (head < heads) {
        float asac[4][2] = {}, adac[4][2] = {};
        #pragma unroll
        for (int mt = 0; mt < 4; mt++)
            #pragma unroll
            for (int ntj = 0; ntj < 4; ntj++) {
                int colb = bn + wn + ntj * 8 + t4 * 2;
                if (colb + 1 < N) {
                    float s0 = avs[colb], s1 = avs[colb + 1];
                    float d0 = avd[colb], d1 = avd[colb + 1];
                    asac[mt][0] += c[mt][ntj][0] * s0 + c[mt][ntj][1] * s1;
                    adac[mt][0] += c[mt][ntj][0] * d0 + c[mt][ntj][1] * d1;
                    asac[mt][1] += c[mt][ntj][2] * s0 + c[mt][ntj][3] * s1;
                    adac[mt][1] += c[mt][ntj][2] * d0 + c[mt][ntj][3] * d1;
                }
            }
        #pragma unroll
        for (int mt = 0; mt < 4; mt++)
            #pragma unroll
            for (int hf = 0; hf < 2; hf++) {
                float v = asac[mt][hf];
                float w = adac[mt][hf];
                v += __shfl_xor_sync(0xFFFFFFFFu, v, 1);
                v += __shfl_xor_sync(0xFFFFFFFFu, v, 2);
                w += __shfl_xor_sync(0xFFFFFFFFu, w, 1);
                w += __shfl_xor_sync(0xFFFFFFFFu, w, 2);
                int row = bm + wm + mt * 16 + g + hf * 8;
                if (t4 == 0 && row < M) {
                    atomicAdd(&as_out[row * heads + head], v);
                    atomicAdd(&ad_out[row * heads + head], w);
                }
            }
    }
}

// ---------------- softmax layer 1: warp per dst node, 4 heads ----------------
__global__ __launch_bounds__(256) void k_softmax1()
{
    int w = (blockIdx.x * blockDim.x + threadIdx.x) >> 5;
    int lane = threadIdx.x & 31;
    if (w >= NN) return;
    int beg = g_rowptr[w], end = g_rowptr[w + 1];
    const float4* as4 = (const float4*)g_as1;
    float4 adv = ((const float4*)g_ad1)[w];
    float4 mx = make_float4(-1e30f, -1e30f, -1e30f, -1e30f);
    for (int i = beg + lane; i < end; i += 32) {
        float4 e = as4[g_srcidx[i]];
        e.x += adv.x; e.y += adv.y; e.z += adv.z; e.w += adv.w;
        e.x = (e.x > 0.f) ? e.x : NEG_SLOPE * e.x;
        e.y = (e.y > 0.f) ? e.y : NEG_SLOPE * e.y;
        e.z = (e.z > 0.f) ? e.z : NEG_SLOPE * e.z;
        e.w = (e.w > 0.f) ? e.w : NEG_SLOPE * e.w;
        g_alpha1[i] = e;
        mx.x = fmaxf(mx.x, e.x); mx.y = fmaxf(mx.y, e.y);
        mx.z = fmaxf(mx.z, e.z); mx.w = fmaxf(mx.w, e.w);
    }
    #pragma unroll
    for (int o = 16; o > 0; o >>= 1) {
        mx.x = fmaxf(mx.x, __shfl_xor_sync(0xFFFFFFFFu, mx.x, o));
        mx.y = fmaxf(mx.y, __shfl_xor_sync(0xFFFFFFFFu, mx.y, o));
        mx.z = fmaxf(mx.z, __shfl_xor_sync(0xFFFFFFFFu, mx.z, o));
        mx.w = fmaxf(mx.w, __shfl_xor_sync(0xFFFFFFFFu, mx.w, o));
    }
    float4 sum = make_float4(0.f, 0.f, 0.f, 0.f);
    for (int i = beg + lane; i < end; i += 32) {
        float4 e = g_alpha1[i];
        e.x = __expf(e.x - mx.x); e.y = __expf(e.y - mx.y);
        e.z = __expf(e.z - mx.z); e.w = __expf(e.w - mx.w);
        g_alpha1[i] = e;
        sum.x += e.x; sum.y += e.y; sum.z += e.z; sum.w += e.w;
    }
    #pragma unroll
    for (int o = 16; o > 0; o >>= 1) {
        sum.x += __shfl_xor_sync(0xFFFFFFFFu, sum.x, o);
        sum.y += __shfl_xor_sync(0xFFFFFFFFu, sum.y, o);
        sum.z += __shfl_xor_sync(0xFFFFFFFFu, sum.z, o);
        sum.w += __shfl_xor_sync(0xFFFFFFFFu, sum.w, o);
    }
    if (lane == 0)
        g_rd1[w] = make_float4(1.f / sum.x, 1.f / sum.y, 1.f / sum.z, 1.f / sum.w);
}

// ---------------- softmax layer 2 --------------------------------------------
__global__ __launch_bounds__(256) void k_softmax2()
{
    int w = (blockIdx.x * blockDim.x + threadIdx.x) >> 5;
    int lane = threadIdx.x & 31;
    if (w >= NN) return;
    int beg = g_rowptr[w], end = g_rowptr[w + 1];
    float adv = g_ad2[w];
    float mx = -1e30f;
    for (int i = beg + lane; i < end; i += 32) {
        float e = g_as2[g_srcidx[i]] + adv;
        e = (e > 0.f) ? e : NEG_SLOPE * e;
        g_alpha2[i] = e;
        mx = fmaxf(mx, e);
    }
    #pragma unroll
    for (int o = 16; o > 0; o >>= 1)
        mx = fmaxf(mx, __shfl_xor_sync(0xFFFFFFFFu, mx, o));
    float sum = 0.f;
    for (int i = beg + lane; i < end; i += 32) {
        float e = __expf(g_alpha2[i] - mx);
        g_alpha2[i] = e;
        sum += e;
    }
    #pragma unroll
    for (int o = 16; o > 0; o >>= 1)
        sum += __shfl_xor_sync(0xFFFFFFFFu, sum, o);
    if (lane == 0) g_rd2[w] = 1.f / sum;
}

// ---- aggregation layer 1: 64 threads per dst row, 2-way unroll --------------
__global__ __launch_bounds__(256) void k_agg1(const float* __restrict__ b1)
{
    int row = blockIdx.x * 4 + (threadIdx.x >> 6);
    if (row >= NN) return;
    int q = threadIdx.x & 63;
    int head = q >> 4;
    int beg = g_rowptr[row], end = g_rowptr[row + 1];
    float4 rdv = g_rd1[row];
    float rd = (head == 0) ? rdv.x : (head == 1) ? rdv.y : (head == 2) ? rdv.z : rdv.w;
    float4 acc0 = make_float4(0.f, 0.f, 0.f, 0.f);
    float4 acc1 = make_float4(0.f, 0.f, 0.f, 0.f);
    int i = beg;
    for (; i + 2 <= end; i += 2) {
        int s0 = g_srcidx[i], s1 = g_srcidx[i + 1];
        float4 a40 = g_alpha1[i], a41 = g_alpha1[i + 1];
        float a0 = (head == 0) ? a40.x : (head == 1) ? a40.y : (head == 2) ? a40.z : a40.w;
        float a1 = (head == 0) ? a41.x : (head == 1) ? a41.y : (head == 2) ? a41.z : a41.w;
        float4 h0 = *(const float4*)(g_h1 + (size_t)s0 * HC1 + q * 4);
        float4 h1 = *(const float4*)(g_h1 + (size_t)s1 * HC1 + q * 4);
        acc0.x += a0 * h0.x; acc0.y += a0 * h0.y; acc0.z += a0 * h0.z; acc0.w += a0 * h0.w;
        acc1.x += a1 * h1.x; acc1.y += a1 * h1.y; acc1.z += a1 * h1.z; acc1.w += a1 * h1.w;
    }
    if (i < end) {
        int s0 = g_srcidx[i];
        float4 a40 = g_alpha1[i];
        float a0 = (head == 0) ? a40.x : (head == 1) ? a40.y : (head == 2) ? a40.z : a40.w;
        float4 h0 = *(const float4*)(g_h1 + (size_t)s0 * HC1 + q * 4);
        acc0.x += a0 * h0.x; acc0.y += a0 * h0.y; acc0.z += a0 * h0.z; acc0.w += a0 * h0.w;
    }
    float4 acc = make_float4((acc0.x + acc1.x) * rd, (acc0.y + acc1.y) * rd,
                             (acc0.z + acc1.z) * rd, (acc0.w + acc1.w) * rd);
    float4 bb = *(const float4*)(b1 + q * 4);
    acc.x += bb.x; acc.y += bb.y; acc.z += bb.z; acc.w += bb.w;
    acc.x = (acc.x > 0.f) ? acc.x : expm1f(acc.x);
    acc.y = (acc.y > 0.f) ? acc.y : expm1f(acc.y);
    acc.z = (acc.z > 0.f) ? acc.z : expm1f(acc.z);
    acc.w = (acc.w > 0.f) ? acc.w : expm1f(acc.w);
    *(float4*)(g_x2 + (size_t)row * HC1 + q * 4) = acc;
}

// ---- aggregation layer 2: 16 threads per dst row, 2-way unroll --------------
__global__ __launch_bounds__(256) void k_agg2(const float* __restrict__ b2,
                                              float* __restrict__ out)
{
    int row = blockIdx.x * 16 + (threadIdx.x >> 4);
    if (row >= NN) return;
    int q = threadIdx.x & 15;
    int beg = g_rowptr[row], end = g_rowptr[row + 1];
    float rd = g_rd2[row];
    float4 acc0 = make_float4(0.f, 0.f, 0.f, 0.f);
    float4 acc1 = make_float4(0.f, 0.f, 0.f, 0.f);
    int i = beg;
    for (; i + 2 <= end; i += 2) {
        int s0 = g_srcidx[i], s1 = g_srcidx[i + 1];
        float a0 = g_alpha2[i], a1 = g_alpha2[i + 1];
        float4 h0 = *(const float4*)(g_h2 + (size_t)s0 * OC + q * 4);
        float4 h1 = *(const float4*)(g_h2 + (size_t)s1 * OC + q * 4);
        acc0.x += a0 * h0.x; acc0.y += a0 * h0.y; acc0.z += a0 * h0.z; acc0.w += a0 * h0.w;
        acc1.x += a1 * h1.x; acc1.y += a1 * h1.y; acc1.z += a1 * h1.z; acc1.w += a1 * h1.w;
    }
    if (i < end) {
        int s0 = g_srcidx[i];
        float a0 = g_alpha2[i];
        float4 h0 = *(const float4*)(g_h2 + (size_t)s0 * OC + q * 4);
        acc0.x += a0 * h0.x; acc0.y += a0 * h0.y; acc0.z += a0 * h0.z; acc0.w += a0 * h0.w;
    }
    float4 bb = *(const float4*)(b2 + q * 4);
    float4 acc = make_float4((acc0.x + acc1.x) * rd + bb.x, (acc0.y + acc1.y) * rd + bb.y,
                             (acc0.z + acc1.z) * rd + bb.z, (acc0.w + acc1.w) * rd + bb.w);
    *(float4*)(out + (size_t)row * OC + q * 4) = acc;
}

// =============================================================================
extern "C" void kernel_launch(void* const* d_in, const int* in_sizes, int n_in,
                              void* d_out, int out_size)
{
    const float* x     = (const float*)d_in[0];
    const int*   ei    = (const int*)d_in[1];
    const float* W1    = (const float*)d_in[2];
    const float* a_s1  = (const float*)d_in[3];
    const float* a_d1  = (const float*)d_in[4];
    const float* b1    = (const float*)d_in[5];
    const float* W2    = (const float*)d_in[6];
    const float* a_s2  = (const float*)d_in[7];
    const float* a_d2  = (const float*)d_in[8];
    const float* b2    = (const float*)d_in[9];
    float*       out   = (float*)d_out;

    float *h1, *x2, *as1, *ad1, *h2, *as2, *ad2;
    cudaGetSymbolAddress((void**)&h1,  g_h1);
    cudaGetSymbolAddress((void**)&x2,  g_x2);
    cudaGetSymbolAddress((void**)&as1, g_as1);
    cudaGetSymbolAddress((void**)&ad1, g_ad1);
    cudaGetSymbolAddress((void**)&h2,  g_h2);
    cudaGetSymbolAddress((void**)&as2, g_as2);
    cudaGetSymbolAddress((void**)&ad2, g_ad2);

    cudaFuncSetAttribute(k_tf32gemm,
                         cudaFuncAttributeMaxDynamicSharedMemorySize, GEMM_SMEM_BYTES);

    // ---- init + CSR build (multi-block scan; verified) ----
    k_zero<<<(NN + 255) / 256, 256>>>();
    k_count<<<(EP + 255) / 256, 256>>>(ei);
    k_scan1<<<NTILES, SCAN_T>>>();
    k_scan2<<<1, 32>>>();
    k_scan3<<<NTILES, SCAN_T>>>();
    k_setcur<<<(NN + 255) / 256, 256>>>();
    k_scatter<<<(EP + 255) / 256, 256>>>(ei);

    // ---- layer 1 ----
    {
        dim3 grid((HC1 + TBN - 1) / TBN, (NN + TBM - 1) / TBM);
        k_tf32gemm<<<grid, 256, GEMM_SMEM_BYTES>>>(x, W1, h1, NN, HC1, INC,
                                                   a_s1, a_d1, as1, ad1, H1);
    }
    k_softmax1<<<(NN * 32 + 255) / 256, 256>>>();
    k_agg1<<<(NN + 3) / 4, 256>>>(b1);

    // ---- layer 2 ----
    {
        dim3 grid((OC + TBN - 1) / TBN, (NN + TBM - 1) / TBM);
        k_tf32gemm<<<grid, 256, GEMM_SMEM_BYTES>>>(x2, W2, h2, NN, OC, HC1,
                                                   a_s2, a_d2, as2, ad2, 1);
    }
    k_softmax2<<<(NN * 32 + 255) / 256, 256>>>();
    k_agg2<<<(NN + 15) / 16, 256>>>(b2, out);
}

// round 12
// speedup vs baseline: 1.2334x; 1.0606x over previous
#include <cuda_runtime.h>
#include <cuda_bf16.h>
#include <math.h>

// ---------------- problem constants ----------------
#define NN    50000
#define EE    800000
#define EP    850000          // EE + NN self loops
#define INC   1024
#define H1    4
#define C1    64
#define HC1   256             // H1*C1
#define OC    64
#define NEG_SLOPE 0.2f

#define SCAN_T 512
#define NTILES ((NN + SCAN_T - 1) / SCAN_T)

// ---------------- scratch (device globals) ----------------
__device__ float  g_h1[(size_t)NN * HC1];
__device__ float  g_x2[(size_t)NN * HC1];
__device__ float  g_as1[NN * H1];
__device__ float  g_ad1[NN * H1];
__device__ float4 g_alpha1[EP];               // per-edge exp values (4 heads), CSR order
__device__ float4 g_rd1[NN];                  // reciprocal softmax denominators

__device__ float  g_h2[(size_t)NN * OC];
__device__ float  g_as2[NN];
__device__ float  g_ad2[NN];
__device__ float  g_alpha2[EP];
__device__ float  g_rd2[NN];

// CSR
__device__ int g_deg[NN];
__device__ int g_rowptr[NN + 1];
__device__ int g_cursor[NN];
__device__ int g_srcidx[EP];
__device__ int g_bsum[NTILES];

__device__ __forceinline__ unsigned f2tf32(float f) {
    unsigned r;
    asm("cvt.rna.tf32.f32 %0, %1;" : "=r"(r) : "f"(f));
    return r;
}

// ================= init + CSR construction =================
__global__ void k_zero_attn() {
    int i = blockIdx.x * blockDim.x + threadIdx.x;
    if (i >= NN) return;
    g_as2[i] = 0.f; g_ad2[i] = 0.f;
    float4 z = make_float4(0.f, 0.f, 0.f, 0.f);
    ((float4*)g_as1)[i] = z;
    ((float4*)g_ad1)[i] = z;
}
__global__ void k_zero_deg() {
    int i = blockIdx.x * blockDim.x + threadIdx.x;
    if (i < NN) g_deg[i] = 0;
}
__global__ void k_count(const int* __restrict__ ei) {
    int e = blockIdx.x * blockDim.x + threadIdx.x;
    if (e >= EP) return;
    int dn = (e < EE) ? ei[EE + e] : (e - EE);
    atomicAdd(&g_deg[dn], 1);
}
__global__ __launch_bounds__(SCAN_T) void k_scan1() {
    __shared__ int s[SCAN_T];
    int tid = threadIdx.x;
    int i = blockIdx.x * SCAN_T + tid;
    int v = (i < NN) ? g_deg[i] : 0;
    s[tid] = v;
    __syncthreads();
    #pragma unroll
    for (int off = 1; off < SCAN_T; off <<= 1) {
        int t = (tid >= off) ? s[tid - off] : 0;
        __syncthreads();
        s[tid] += t;
        __syncthreads();
    }
    if (i < NN) g_rowptr[i + 1] = s[tid];
    if (tid == SCAN_T - 1) g_bsum[blockIdx.x] = s[tid];
}
// merged: bsum prefix (per-block warp reduce) + rowptr offset + cursor init
__global__ __launch_bounds__(SCAN_T) void k_scan3m() {
    __shared__ int off_s;
    int blk = blockIdx.x;
    if (threadIdx.x < 32) {
        int lane = threadIdx.x;
        int s = 0;
        for (int j = lane; j < blk; j += 32) s += g_bsum[j];
        #pragma unroll
        for (int o = 16; o > 0; o >>= 1) s += __shfl_xor_sync(0xFFFFFFFFu, s, o);
        if (lane == 0) off_s = s;
    }
    __syncthreads();
    int off = off_s;
    int i = blk * SCAN_T + threadIdx.x;
    if (i < NN) {
        int r = g_rowptr[i + 1] + off;
        g_rowptr[i + 1] = r;
        g_cursor[i] = r - g_deg[i];
    }
    if (i == 0) g_rowptr[0] = 0;
}
__global__ void k_scatter(const int* __restrict__ ei) {
    int e = blockIdx.x * blockDim.x + threadIdx.x;
    if (e >= EP) return;
    int s, dn;
    if (e < EE) { s = ei[e]; dn = ei[EE + e]; }
    else        { s = e - EE; dn = s; }
    int pos = atomicAdd(&g_cursor[dn], 1);
    g_srcidx[pos] = s;
}

// ============= TF32 GEMM + fused attention-coefficient epilogue ==============
// (verified layout: TSS=36, scalar fragment loads, double buffered, 2 CTAs/SM)
#define TBM 128
#define TBN 128
#define TBK 32
#define TSS 36
#define GEMM_SMEM_BYTES (4 * TBM * TSS * 4)

__global__ __launch_bounds__(256, 2) void k_tf32gemm(
    const float* __restrict__ A, const float* __restrict__ B,
    float* __restrict__ C, int M, int N, int K,
    const float* __restrict__ avs, const float* __restrict__ avd,
    float* __restrict__ as_out, float* __restrict__ ad_out, int heads)
{
    extern __shared__ unsigned smem_u[];
    unsigned* Abase = smem_u;
    unsigned* Bbase = smem_u + 2 * TBM * TSS;

    int tid = threadIdx.x;
    int bm = blockIdx.y * TBM, bn = blockIdx.x * TBN;
    int wid = tid >> 5, lane = tid & 31;
    int wm = (wid >> 2) * 64;
    int wn = (wid & 3) * 32;
    int g  = lane >> 2;
    int t4 = lane & 3;

    int r0 = tid >> 3;
    int c4 = (tid & 7) * 4;

    float c[4][4][4];
    #pragma unroll
    for (int i = 0; i < 4; i++)
        #pragma unroll
        for (int j = 0; j < 4; j++)
            #pragma unroll
            for (int r = 0; r < 4; r++) c[i][j][r] = 0.f;

    const float4 zero4 = make_float4(0.f, 0.f, 0.f, 0.f);
    float4 pa[4], pb[4];
    int nt = K / TBK;

    #pragma unroll
    for (int i = 0; i < 4; i++) {
        int ar = bm + r0 + 32 * i;
        pa[i] = (ar < M) ? *(const float4*)(A + (size_t)ar * K + c4) : zero4;
        int br = bn + r0 + 32 * i;
        pb[i] = (br < N) ? *(const float4*)(B + (size_t)br * K + c4) : zero4;
    }
    {
        unsigned* Ab = Abase;
        unsigned* Bb = Bbase;
        #pragma unroll
        for (int i = 0; i < 4; i++) {
            int rr = r0 + 32 * i;
            Ab[rr * TSS + c4 + 0] = f2tf32(pa[i].x); Ab[rr * TSS + c4 + 1] = f2tf32(pa[i].y);
            Ab[rr * TSS + c4 + 2] = f2tf32(pa[i].z); Ab[rr * TSS + c4 + 3] = f2tf32(pa[i].w);
            Bb[rr * TSS + c4 + 0] = f2tf32(pb[i].x); Bb[rr * TSS + c4 + 1] = f2tf32(pb[i].y);
            Bb[rr * TSS + c4 + 2] = f2tf32(pb[i].z); Bb[rr * TSS + c4 + 3] = f2tf32(pb[i].w);
        }
    }
    __syncthreads();

    for (int t = 0; t < nt; t++) {
        int cur = t & 1;
        bool more = (t + 1 < nt);
        if (more) {
            int k0 = (t + 1) * TBK;
            #pragma unroll
            for (int i = 0; i < 4; i++) {
                int ar = bm + r0 + 32 * i;
                pa[i] = (ar < M) ? *(const float4*)(A + (size_t)ar * K + k0 + c4) : zero4;
                int br = bn + r0 + 32 * i;
                pb[i] = (br < N) ? *(const float4*)(B + (size_t)br * K + k0 + c4) : zero4;
            }
        }
        const unsigned* Ab = Abase + cur * TBM * TSS;
        const unsigned* Bb = Bbase + cur * TBM * TSS;
        #pragma unroll
        for (int ks = 0; ks < 4; ks++) {
            int k8 = ks * 8;
            unsigned af[4][4], bf[4][2];
            #pragma unroll
            for (int mt = 0; mt < 4; mt++) {
                int row = wm + mt * 16 + g;
                af[mt][0] = Ab[row * TSS + k8 + t4];
                af[mt][1] = Ab[(row + 8) * TSS + k8 + t4];
                af[mt][2] = Ab[row * TSS + k8 + t4 + 4];
                af[mt][3] = Ab[(row + 8) * TSS + k8 + t4 + 4];
            }
            #pragma unroll
            for (int ntj = 0; ntj < 4; ntj++) {
                int col = wn + ntj * 8 + g;
                bf[ntj][0] = Bb[col * TSS + k8 + t4];
                bf[ntj][1] = Bb[col * TSS + k8 + t4 + 4];
            }
            #pragma unroll
            for (int mt = 0; mt < 4; mt++)
                #pragma unroll
                for (int ntj = 0; ntj < 4; ntj++) {
                    asm volatile(
                        "mma.sync.aligned.m16n8k8.row.col.f32.tf32.tf32.f32 "
                        "{%0,%1,%2,%3}, {%4,%5,%6,%7}, {%8,%9}, {%0,%1,%2,%3};"
                        : "+f"(c[mt][ntj][0]), "+f"(c[mt][ntj][1]),
                          "+f"(c[mt][ntj][2]), "+f"(c[mt][ntj][3])
                        : "r"(af[mt][0]), "r"(af[mt][1]), "r"(af[mt][2]), "r"(af[mt][3]),
                          "r"(bf[ntj][0]), "r"(bf[ntj][1]));
                }
        }
        if (more) {
            int nx = cur ^ 1;
            unsigned* Aw = Abase + nx * TBM * TSS;
            unsigned* Bw = Bbase + nx * TBM * TSS;
            #pragma unroll
            for (int i = 0; i < 4; i++) {
                int rr = r0 + 32 * i;
                Aw[rr * TSS + c4 + 0] = f2tf32(pa[i].x); Aw[rr * TSS + c4 + 1] = f2tf32(pa[i].y);
                Aw[rr * TSS + c4 + 2] = f2tf32(pa[i].z); Aw[rr * TSS + c4 + 3] = f2tf32(pa[i].w);
                Bw[rr * TSS + c4 + 0] = f2tf32(pb[i].x); Bw[rr * TSS + c4 + 1] = f2tf32(pb[i].y);
                Bw[rr * TSS + c4 + 2] = f2tf32(pb[i].z); Bw[rr * TSS + c4 + 3] = f2tf32(pb[i].w);
            }
            __syncthreads();
        }
    }

    // ---- C store ----
    #pragma unroll
    for (int mt = 0; mt < 4; mt++) {
        int row0 = bm + wm + mt * 16 + g;
        #pragma unroll
        for (int ntj = 0; ntj < 4; ntj++) {
            int col = bn + wn + ntj * 8 + t4 * 2;
            if (row0 < M && col + 1 < N) {
                C[(size_t)row0 * N + col]     = c[mt][ntj][0];
                C[(size_t)row0 * N + col + 1] = c[mt][ntj][1];
            }
            if (row0 + 8 < M && col + 1 < N) {
                C[(size_t)(row0 + 8) * N + col]     = c[mt][ntj][2];
                C[(size_t)(row0 + 8) * N + col + 1] = c[mt][ntj][3];
            }
        }
    }

    // ---- fused attention-coefficient partials ----
    int head = (bn + wn) >> 6;
    if (head < heads) {
        float asac[4][2] = {}, adac[4][2] = {};
        #pragma unroll
        for (int mt = 0; mt < 4; mt++)
            #pragma unroll
            for (int ntj = 0; ntj < 4; ntj++) {
                int colb = bn + wn + ntj * 8 + t4 * 2;
                if (colb + 1 < N) {
                    float s0 = avs[colb], s1 = avs[colb + 1];
                    float d0 = avd[colb], d1 = avd[colb + 1];
                    asac[mt][0] += c[mt][ntj][0] * s0 + c[mt][ntj][1] * s1;
                    adac[mt][0] += c[mt][ntj][0] * d0 + c[mt][ntj][1] * d1;
                    asac[mt][1] += c[mt][ntj][2] * s0 + c[mt][ntj][3] * s1;
                    adac[mt][1] += c[mt][ntj][2] * d0 + c[mt][ntj][3] * d1;
                }
            }
        #pragma unroll
        for (int mt = 0; mt < 4; mt++)
            #pragma unroll
            for (int hf = 0; hf < 2; hf++) {
                float v = asac[mt][hf];
                float w = adac[mt][hf];
                v += __shfl_xor_sync(0xFFFFFFFFu, v, 1);
                v += __shfl_xor_sync(0xFFFFFFFFu, v, 2);
                w += __shfl_xor_sync(0xFFFFFFFFu, w, 1);
                w += __shfl_xor_sync(0xFFFFFFFFu, w, 2);
                int row = bm + wm + mt * 16 + g + hf * 8;
                if (t4 == 0 && row < M) {
                    atomicAdd(&as_out[row * heads + head], v);
                    atomicAdd(&ad_out[row * heads + head], w);
                }
            }
    }
}

// ---------------- softmax layer 1: warp per dst node, 4 heads ----------------
__global__ __launch_bounds__(256) void k_softmax1()
{
    int w = (blockIdx.x * blockDim.x + threadIdx.x) >> 5;
    int lane = threadIdx.x & 31;
    if (w >= NN) return;
    int beg = g_rowptr[w], end = g_rowptr[w + 1];
    const float4* as4 = (const float4*)g_as1;
    float4 adv = ((const float4*)g_ad1)[w];
    float4 mx = make_float4(-1e30f, -1e30f, -1e30f, -1e30f);
    for (int i = beg + lane; i < end; i += 32) {
        float4 e = as4[g_srcidx[i]];
        e.x += adv.x; e.y += adv.y; e.z += adv.z; e.w += adv.w;
        e.x = (e.x > 0.f) ? e.x : NEG_SLOPE * e.x;
        e.y = (e.y > 0.f) ? e.y : NEG_SLOPE * e.y;
        e.z = (e.z > 0.f) ? e.z : NEG_SLOPE * e.z;
        e.w = (e.w > 0.f) ? e.w : NEG_SLOPE * e.w;
        g_alpha1[i] = e;
        mx.x = fmaxf(mx.x, e.x); mx.y = fmaxf(mx.y, e.y);
        mx.z = fmaxf(mx.z, e.z); mx.w = fmaxf(mx.w, e.w);
    }
    #pragma unroll
    for (int o = 16; o > 0; o >>= 1) {
        mx.x = fmaxf(mx.x, __shfl_xor_sync(0xFFFFFFFFu, mx.x, o));
        mx.y = fmaxf(mx.y, __shfl_xor_sync(0xFFFFFFFFu, mx.y, o));
        mx.z = fmaxf(mx.z, __shfl_xor_sync(0xFFFFFFFFu, mx.z, o));
        mx.w = fmaxf(mx.w, __shfl_xor_sync(0xFFFFFFFFu, mx.w, o));
    }
    float4 sum = make_float4(0.f, 0.f, 0.f, 0.f);
    for (int i = beg + lane; i < end; i += 32) {
        float4 e = g_alpha1[i];
        e.x = __expf(e.x - mx.x); e.y = __expf(e.y - mx.y);
        e.z = __expf(e.z - mx.z); e.w = __expf(e.w - mx.w);
        g_alpha1[i] = e;
        sum.x += e.x; sum.y += e.y; sum.z += e.z; sum.w += e.w;
    }
    #pragma unroll
    for (int o = 16; o > 0; o >>= 1) {
        sum.x += __shfl_xor_sync(0xFFFFFFFFu, sum.x, o);
        sum.y += __shfl_xor_sync(0xFFFFFFFFu, sum.y, o);
        sum.z += __shfl_xor_sync(0xFFFFFFFFu, sum.z, o);
        sum.w += __shfl_xor_sync(0xFFFFFFFFu, sum.w, o);
    }
    if (lane == 0)
        g_rd1[w] = make_float4(1.f / sum.x, 1.f / sum.y, 1.f / sum.z, 1.f / sum.w);
}

// ---------------- softmax layer 2 --------------------------------------------
__global__ __launch_bounds__(256) void k_softmax2()
{
    int w = (blockIdx.x * blockDim.x + threadIdx.x) >> 5;
    int lane = threadIdx.x & 31;
    if (w >= NN) return;
    int beg = g_rowptr[w], end = g_rowptr[w + 1];
    float adv = g_ad2[w];
    float mx = -1e30f;
    for (int i = beg + lane; i < end; i += 32) {
        float e = g_as2[g_srcidx[i]] + adv;
        e = (e > 0.f) ? e : NEG_SLOPE * e;
        g_alpha2[i] = e;
        mx = fmaxf(mx, e);
    }
    #pragma unroll
    for (int o = 16; o > 0; o >>= 1)
        mx = fmaxf(mx, __shfl_xor_sync(0xFFFFFFFFu, mx, o));
    float sum = 0.f;
    for (int i = beg + lane; i < end; i += 32) {
        float e = __expf(g_alpha2[i] - mx);
        g_alpha2[i] = e;
        sum += e;
    }
    #pragma unroll
    for (int o = 16; o > 0; o >>= 1)
        sum += __shfl_xor_sync(0xFFFFFFFFu, sum, o);
    if (lane == 0) g_rd2[w] = 1.f / sum;
}

// ---- aggregation layer 1: 64 threads per dst row, 2-way unroll --------------
__global__ __launch_bounds__(256) void k_agg1(const float* __restrict__ b1)
{
    int row = blockIdx.x * 4 + (threadIdx.x >> 6);
    if (row >= NN) return;
    int q = threadIdx.x & 63;
    int head = q >> 4;
    int beg = g_rowptr[row], end = g_rowptr[row + 1];
    float4 rdv = g_rd1[row];
    float rd = (head == 0) ? rdv.x : (head == 1) ? rdv.y : (head == 2) ? rdv.z : rdv.w;
    float4 acc0 = make_float4(0.f, 0.f, 0.f, 0.f);
    float4 acc1 = make_float4(0.f, 0.f, 0.f, 0.f);
    int i = beg;
    for (; i + 2 <= end; i += 2) {
        int s0 = g_srcidx[i], s1 = g_srcidx[i + 1];
        float4 a40 = g_alpha1[i], a41 = g_alpha1[i + 1];
        float a0 = (head == 0) ? a40.x : (head == 1) ? a40.y : (head == 2) ? a40.z : a40.w;
        float a1 = (head == 0) ? a41.x : (head == 1) ? a41.y : (head == 2) ? a41.z : a41.w;
        float4 h0 = *(const float4*)(g_h1 + (size_t)s0 * HC1 + q * 4);
        float4 h1 = *(const float4*)(g_h1 + (size_t)s1 * HC1 + q * 4);
        acc0.x += a0 * h0.x; acc0.y += a0 * h0.y; acc0.z += a0 * h0.z; acc0.w += a0 * h0.w;
        acc1.x += a1 * h1.x; acc1.y += a1 * h1.y; acc1.z += a1 * h1.z; acc1.w += a1 * h1.w;
    }
    if (i < end) {
        int s0 = g_srcidx[i];
        float4 a40 = g_alpha1[i];
        float a0 = (head == 0) ? a40.x : (head == 1) ? a40.y : (head == 2) ? a40.z : a40.w;
        float4 h0 = *(const float4*)(g_h1 + (size_t)s0 * HC1 + q * 4);
        acc0.x += a0 * h0.x; acc0.y += a0 * h0.y; acc0.z += a0 * h0.z; acc0.w += a0 * h0.w;
    }
    float4 acc = make_float4((acc0.x + acc1.x) * rd, (acc0.y + acc1.y) * rd,
                             (acc0.z + acc1.z) * rd, (acc0.w + acc1.w) * rd);
    float4 bb = *(const float4*)(b1 + q * 4);
    acc.x += bb.x; acc.y += bb.y; acc.z += bb.z; acc.w += bb.w;
    acc.x = (acc.x > 0.f) ? acc.x : expm1f(acc.x);
    acc.y = (acc.y > 0.f) ? acc.y : expm1f(acc.y);
    acc.z = (acc.z > 0.f) ? acc.z : expm1f(acc.z);
    acc.w = (acc.w > 0.f) ? acc.w : expm1f(acc.w);
    *(float4*)(g_x2 + (size_t)row * HC1 + q * 4) = acc;
}

// ---- aggregation layer 2: 16 threads per dst row, 2-way unroll --------------
__global__ __launch_bounds__(256) void k_agg2(const float* __restrict__ b2,
                                              float* __restrict__ out)
{
    int row = blockIdx.x * 16 + (threadIdx.x >> 4);
    if (row >= NN) return;
    int q = threadIdx.x & 15;
    int beg = g_rowptr[row], end = g_rowptr[row + 1];
    float rd = g_rd2[row];
    float4 acc0 = make_float4(0.f, 0.f, 0.f, 0.f);
    float4 acc1 = make_float4(0.f, 0.f, 0.f, 0.f);
    int i = beg;
    for (; i + 2 <= end; i += 2) {
        int s0 = g_srcidx[i], s1 = g_srcidx[i + 1];
        float a0 = g_alpha2[i], a1 = g_alpha2[i + 1];
        float4 h0 = *(const float4*)(g_h2 + (size_t)s0 * OC + q * 4);
        float4 h1 = *(const float4*)(g_h2 + (size_t)s1 * OC + q * 4);
        acc0.x += a0 * h0.x; acc0.y += a0 * h0.y; acc0.z += a0 * h0.z; acc0.w += a0 * h0.w;
        acc1.x += a1 * h1.x; acc1.y += a1 * h1.y; acc1.z += a1 * h1.z; acc1.w += a1 * h1.w;
    }
    if (i < end) {
        int s0 = g_srcidx[i];
        float a0 = g_alpha2[i];
        float4 h0 = *(const float4*)(g_h2 + (size_t)s0 * OC + q * 4);
        acc0.x += a0 * h0.x; acc0.y += a0 * h0.y; acc0.z += a0 * h0.z; acc0.w += a0 * h0.w;
    }
    float4 bb = *(const float4*)(b2 + q * 4);
    float4 acc = make_float4((acc0.x + acc1.x) * rd + bb.x, (acc0.y + acc1.y) * rd + bb.y,
                             (acc0.z + acc1.z) * rd + bb.z, (acc0.w + acc1.w) * rd + bb.w);
    *(float4*)(out + (size_t)row * OC + q * 4) = acc;
}

// =============================================================================
extern "C" void kernel_launch(void* const* d_in, const int* in_sizes, int n_in,
                              void* d_out, int out_size)
{
    const float* x     = (const float*)d_in[0];
    const int*   ei    = (const int*)d_in[1];
    const float* W1    = (const float*)d_in[2];
    const float* a_s1  = (const float*)d_in[3];
    const float* a_d1  = (const float*)d_in[4];
    const float* b1    = (const float*)d_in[5];
    const float* W2    = (const float*)d_in[6];
    const float* a_s2  = (const float*)d_in[7];
    const float* a_d2  = (const float*)d_in[8];
    const float* b2    = (const float*)d_in[9];
    float*       out   = (float*)d_out;

    float *h1, *x2, *as1, *ad1, *h2, *as2, *ad2;
    cudaGetSymbolAddress((void**)&h1,  g_h1);
    cudaGetSymbolAddress((void**)&x2,  g_x2);
    cudaGetSymbolAddress((void**)&as1, g_as1);
    cudaGetSymbolAddress((void**)&ad1, g_ad1);
    cudaGetSymbolAddress((void**)&h2,  g_h2);
    cudaGetSymbolAddress((void**)&as2, g_as2);
    cudaGetSymbolAddress((void**)&ad2, g_ad2);

    cudaFuncSetAttribute(k_tf32gemm,
                         cudaFuncAttributeMaxDynamicSharedMemorySize, GEMM_SMEM_BYTES);

    // second stream + fork/join events (created per call; capture-compatible)
    cudaStream_t s2;
    cudaStreamCreate(&s2);
    cudaEvent_t evFork, evJoin;
    cudaEventCreateWithFlags(&evFork, cudaEventDisableTiming);
    cudaEventCreateWithFlags(&evJoin, cudaEventDisableTiming);

    // ---- fork: CSR build on s2, concurrent with GEMM1 on default stream ----
    cudaEventRecord(evFork, 0);
    cudaStreamWaitEvent(s2, evFork, 0);
    k_zero_deg<<<(NN + 255) / 256, 256, 0, s2>>>();
    k_count<<<(EP + 255) / 256, 256, 0, s2>>>(ei);
    k_scan1<<<NTILES, SCAN_T, 0, s2>>>();
    k_scan3m<<<NTILES, SCAN_T, 0, s2>>>();
    k_scatter<<<(EP + 255) / 256, 256, 0, s2>>>(ei);
    cudaEventRecord(evJoin, s2);

    // ---- main stream: attn-accumulator zero + GEMM1 (independent of CSR) ----
    k_zero_attn<<<(NN + 255) / 256, 256>>>();
    {
        dim3 grid((HC1 + TBN - 1) / TBN, (NN + TBM - 1) / TBM);
        k_tf32gemm<<<grid, 256, GEMM_SMEM_BYTES>>>(x, W1, h1, NN, HC1, INC,
                                                   a_s1, a_d1, as1, ad1, H1);
    }

    // ---- join: softmax needs both CSR and GEMM1 results ----
    cudaStreamWaitEvent(0, evJoin, 0);
    k_softmax1<<<(NN * 32 + 255) / 256, 256>>>();
    k_agg1<<<(NN + 3) / 4, 256>>>(b1);

    // ---- layer 2 ----
    {
        dim3 grid((OC + TBN - 1) / TBN, (NN + TBM - 1) / TBM);
        k_tf32gemm<<<grid, 256, GEMM_SMEM_BYTES>>>(x2, W2, h2, NN, OC, HC1,
                                                   a_s2, a_d2, as2, ad2, 1);
    }
    k_softmax2<<<(NN * 32 + 255) / 256, 256>>>();
    k_agg2<<<(NN + 15) / 16, 256>>>(b2, out);
}

// round 13
// speedup vs baseline: 1.2829x; 1.0401x over previous
#include <cuda_runtime.h>
#include <cuda_fp16.h>
#include <math.h>

// ---------------- problem constants ----------------
#define NN    50000
#define EE    800000
#define EP    850000          // EE + NN self loops
#define INC   1024
#define H1    4
#define C1    64
#define HC1   256             // H1*C1
#define OC    64
#define NEG_SLOPE 0.2f

#define SCAN_T 512
#define NTILES ((NN + SCAN_T - 1) / SCAN_T)

// ---------------- scratch (device globals) ----------------
__device__ __half  g_h1h[(size_t)NN * HC1];   // layer1 features, fp16 (agg path)
__device__ float   g_x2[(size_t)NN * HC1];
__device__ float   g_as1[NN * H1];
__device__ float   g_ad1[NN * H1];
__device__ float4  g_alpha1[EP];              // per-edge exp values (4 heads), CSR order
__device__ float4  g_rd1[NN];                 // reciprocal softmax denominators

__device__ float   g_h2[(size_t)NN * OC];
__device__ float   g_as2[NN];
__device__ float   g_ad2[NN];
__device__ float   g_alpha2[EP];
__device__ float   g_rd2[NN];

// CSR
__device__ int g_deg[NN];
__device__ int g_rowptr[NN + 1];
__device__ int g_cursor[NN];
__device__ int g_srcidx[EP];
__device__ int g_bsum[NTILES];

__device__ __forceinline__ unsigned f2tf32(float f) {
    unsigned r;
    asm("cvt.rna.tf32.f32 %0, %1;" : "=r"(r) : "f"(f));
    return r;
}

// ================= init + CSR construction =================
__global__ void k_zero_attn() {
    int i = blockIdx.x * blockDim.x + threadIdx.x;
    if (i >= NN) return;
    g_as2[i] = 0.f; g_ad2[i] = 0.f;
    float4 z = make_float4(0.f, 0.f, 0.f, 0.f);
    ((float4*)g_as1)[i] = z;
    ((float4*)g_ad1)[i] = z;
}
__global__ void k_zero_deg() {
    int i = blockIdx.x * blockDim.x + threadIdx.x;
    if (i < NN) g_deg[i] = 0;
}
__global__ void k_count(const int* __restrict__ ei) {
    int e = blockIdx.x * blockDim.x + threadIdx.x;
    if (e >= EP) return;
    int dn = (e < EE) ? ei[EE + e] : (e - EE);
    atomicAdd(&g_deg[dn], 1);
}
__global__ __launch_bounds__(SCAN_T) void k_scan1() {
    __shared__ int s[SCAN_T];
    int tid = threadIdx.x;
    int i = blockIdx.x * SCAN_T + tid;
    int v = (i < NN) ? g_deg[i] : 0;
    s[tid] = v;
    __syncthreads();
    #pragma unroll
    for (int off = 1; off < SCAN_T; off <<= 1) {
        int t = (tid >= off) ? s[tid - off] : 0;
        __syncthreads();
        s[tid] += t;
        __syncthreads();
    }
    if (i < NN) g_rowptr[i + 1] = s[tid];
    if (tid == SCAN_T - 1) g_bsum[blockIdx.x] = s[tid];
}
__global__ __launch_bounds__(SCAN_T) void k_scan3m() {
    __shared__ int off_s;
    int blk = blockIdx.x;
    if (threadIdx.x < 32) {
        int lane = threadIdx.x;
        int s = 0;
        for (int j = lane; j < blk; j += 32) s += g_bsum[j];
        #pragma unroll
        for (int o = 16; o > 0; o >>= 1) s += __shfl_xor_sync(0xFFFFFFFFu, s, o);
        if (lane == 0) off_s = s;
    }
    __syncthreads();
    int off = off_s;
    int i = blk * SCAN_T + threadIdx.x;
    if (i < NN) {
        int r = g_rowptr[i + 1] + off;
        g_rowptr[i + 1] = r;
        g_cursor[i] = r - g_deg[i];
    }
    if (i == 0) g_rowptr[0] = 0;
}
__global__ void k_scatter(const int* __restrict__ ei) {
    int e = blockIdx.x * blockDim.x + threadIdx.x;
    if (e >= EP) return;
    int s, dn;
    if (e < EE) { s = ei[e]; dn = ei[EE + e]; }
    else        { s = e - EE; dn = s; }
    int pos = atomicAdd(&g_cursor[dn], 1);
    g_srcidx[pos] = s;
}

// ============= TF32 GEMM + fused attention-coefficient epilogue ==============
// template: NTJ = n-subtiles per warp (4 -> TBN 128, 2 -> TBN 64)
//           HOUT = store C as __half (layer1) or float (layer2)
#define TBM 128
#define TBK 32
#define TSS 36

template<int NTJ, bool HOUT>
__global__ __launch_bounds__(256, 2) void k_tf32gemm(
    const float* __restrict__ A, const float* __restrict__ B,
    void* __restrict__ Cout, int M, int N, int K,
    const float* __restrict__ avs, const float* __restrict__ avd,
    float* __restrict__ as_out, float* __restrict__ ad_out, int heads)
{
    const int TBNE = 32 * NTJ;              // 128 or 64
    extern __shared__ unsigned smem_u[];
    unsigned* Abase = smem_u;                       // [2][128][TSS]
    unsigned* Bbase = smem_u + 2 * TBM * TSS;       // [2][TBNE][TSS]

    int tid = threadIdx.x;
    int bm = blockIdx.y * TBM, bn = blockIdx.x * (4 * 8 * NTJ);
    int wid = tid >> 5, lane = tid & 31;
    int wm = (wid >> 2) * 64;
    int wn = (wid & 3) * (8 * NTJ);
    int g  = lane >> 2;
    int t4 = lane & 3;

    int r0 = tid >> 3;
    int c4 = (tid & 7) * 4;

    float c[4][NTJ][4];
    #pragma unroll
    for (int i = 0; i < 4; i++)
        #pragma unroll
        for (int j = 0; j < NTJ; j++)
            #pragma unroll
            for (int r = 0; r < 4; r++) c[i][j][r] = 0.f;

    const float4 zero4 = make_float4(0.f, 0.f, 0.f, 0.f);
    float4 pa[4], pb[NTJ];
    int nt = K / TBK;

    // fetch tile 0
    #pragma unroll
    for (int i = 0; i < 4; i++) {
        int ar = bm + r0 + 32 * i;
        pa[i] = (ar < M) ? *(const float4*)(A + (size_t)ar * K + c4) : zero4;
    }
    #pragma unroll
    for (int i = 0; i < NTJ; i++) {
        int br = bn + r0 + 32 * i;
        pb[i] = (br < N) ? *(const float4*)(B + (size_t)br * K + c4) : zero4;
    }
    {
        unsigned* Ab = Abase;
        unsigned* Bb = Bbase;
        #pragma unroll
        for (int i = 0; i < 4; i++) {
            int rr = r0 + 32 * i;
            Ab[rr * TSS + c4 + 0] = f2tf32(pa[i].x); Ab[rr * TSS + c4 + 1] = f2tf32(pa[i].y);
            Ab[rr * TSS + c4 + 2] = f2tf32(pa[i].z); Ab[rr * TSS + c4 + 3] = f2tf32(pa[i].w);
        }
        #pragma unroll
        for (int i = 0; i < NTJ; i++) {
            int rr = r0 + 32 * i;
            Bb[rr * TSS + c4 + 0] = f2tf32(pb[i].x); Bb[rr * TSS + c4 + 1] = f2tf32(pb[i].y);
            Bb[rr * TSS + c4 + 2] = f2tf32(pb[i].z); Bb[rr * TSS + c4 + 3] = f2tf32(pb[i].w);
        }
    }
    __syncthreads();

    for (int t = 0; t < nt; t++) {
        int cur = t & 1;
        bool more = (t + 1 < nt);
        if (more) {
            int k0 = (t + 1) * TBK;
            #pragma unroll
            for (int i = 0; i < 4; i++) {
                int ar = bm + r0 + 32 * i;
                pa[i] = (ar < M) ? *(const float4*)(A + (size_t)ar * K + k0 + c4) : zero4;
            }
            #pragma unroll
            for (int i = 0; i < NTJ; i++) {
                int br = bn + r0 + 32 * i;
                pb[i] = (br < N) ? *(const float4*)(B + (size_t)br * K + k0 + c4) : zero4;
            }
        }
        const unsigned* Ab = Abase + cur * TBM * TSS;
        const unsigned* Bb = Bbase + cur * TBNE * TSS;
        #pragma unroll
        for (int ks = 0; ks < 4; ks++) {
            int k8 = ks * 8;
            unsigned af[4][4], bf[NTJ][2];
            #pragma unroll
            for (int mt = 0; mt < 4; mt++) {
                int row = wm + mt * 16 + g;
                af[mt][0] = Ab[row * TSS + k8 + t4];
                af[mt][1] = Ab[(row + 8) * TSS + k8 + t4];
                af[mt][2] = Ab[row * TSS + k8 + t4 + 4];
                af[mt][3] = Ab[(row + 8) * TSS + k8 + t4 + 4];
            }
            #pragma unroll
            for (int ntj = 0; ntj < NTJ; ntj++) {
                int col = wn + ntj * 8 + g;
                bf[ntj][0] = Bb[col * TSS + k8 + t4];
                bf[ntj][1] = Bb[col * TSS + k8 + t4 + 4];
            }
            #pragma unroll
            for (int mt = 0; mt < 4; mt++)
                #pragma unroll
                for (int ntj = 0; ntj < NTJ; ntj++) {
                    asm volatile(
                        "mma.sync.aligned.m16n8k8.row.col.f32.tf32.tf32.f32 "
                        "{%0,%1,%2,%3}, {%4,%5,%6,%7}, {%8,%9}, {%0,%1,%2,%3};"
                        : "+f"(c[mt][ntj][0]), "+f"(c[mt][ntj][1]),
                          "+f"(c[mt][ntj][2]), "+f"(c[mt][ntj][3])
                        : "r"(af[mt][0]), "r"(af[mt][1]), "r"(af[mt][2]), "r"(af[mt][3]),
                          "r"(bf[ntj][0]), "r"(bf[ntj][1]));
                }
        }
        if (more) {
            int nx = cur ^ 1;
            unsigned* Aw = Abase + nx * TBM * TSS;
            unsigned* Bw = Bbase + nx * TBNE * TSS;
            #pragma unroll
            for (int i = 0; i < 4; i++) {
                int rr = r0 + 32 * i;
                Aw[rr * TSS + c4 + 0] = f2tf32(pa[i].x); Aw[rr * TSS + c4 + 1] = f2tf32(pa[i].y);
                Aw[rr * TSS + c4 + 2] = f2tf32(pa[i].z); Aw[rr * TSS + c4 + 3] = f2tf32(pa[i].w);
            }
            #pragma unroll
            for (int i = 0; i < NTJ; i++) {
                int rr = r0 + 32 * i;
                Bw[rr * TSS + c4 + 0] = f2tf32(pb[i].x); Bw[rr * TSS + c4 + 1] = f2tf32(pb[i].y);
                Bw[rr * TSS + c4 + 2] = f2tf32(pb[i].z); Bw[rr * TSS + c4 + 3] = f2tf32(pb[i].w);
            }
            __syncthreads();
        }
    }

    // ---- C store ----
    #pragma unroll
    for (int mt = 0; mt < 4; mt++) {
        int row0 = bm + wm + mt * 16 + g;
        #pragma unroll
        for (int ntj = 0; ntj < NTJ; ntj++) {
            int col = bn + wn + ntj * 8 + t4 * 2;
            if (HOUT) {
                __half* Ch = (__half*)Cout;
                if (row0 < M && col + 1 < N)
                    *(__half2*)(Ch + (size_t)row0 * N + col) =
                        __floats2half2_rn(c[mt][ntj][0], c[mt][ntj][1]);
                if (row0 + 8 < M && col + 1 < N)
                    *(__half2*)(Ch + (size_t)(row0 + 8) * N + col) =
                        __floats2half2_rn(c[mt][ntj][2], c[mt][ntj][3]);
            } else {
                float* Cf = (float*)Cout;
                if (row0 < M && col + 1 < N) {
                    Cf[(size_t)row0 * N + col]     = c[mt][ntj][0];
                    Cf[(size_t)row0 * N + col + 1] = c[mt][ntj][1];
                }
                if (row0 + 8 < M && col + 1 < N) {
                    Cf[(size_t)(row0 + 8) * N + col]     = c[mt][ntj][2];
                    Cf[(size_t)(row0 + 8) * N + col + 1] = c[mt][ntj][3];
                }
            }
        }
    }

    // ---- fused attention-coefficient partials ----
    int head = (bn + wn) >> 6;
    if (head < heads) {
        float asac[4][2] = {}, adac[4][2] = {};
        #pragma unroll
        for (int mt = 0; mt < 4; mt++)
            #pragma unroll
            for (int ntj = 0; ntj < NTJ; ntj++) {
                int colb = bn + wn + ntj * 8 + t4 * 2;
                if (colb + 1 < N) {
                    float s0 = avs[colb], s1 = avs[colb + 1];
                    float d0 = avd[colb], d1 = avd[colb + 1];
                    asac[mt][0] += c[mt][ntj][0] * s0 + c[mt][ntj][1] * s1;
                    adac[mt][0] += c[mt][ntj][0] * d0 + c[mt][ntj][1] * d1;
                    asac[mt][1] += c[mt][ntj][2] * s0 + c[mt][ntj][3] * s1;
                    adac[mt][1] += c[mt][ntj][2] * d0 + c[mt][ntj][3] * d1;
                }
            }
        #pragma unroll
        for (int mt = 0; mt < 4; mt++)
            #pragma unroll
            for (int hf = 0; hf < 2; hf++) {
                float v = asac[mt][hf];
                float w = adac[mt][hf];
                v += __shfl_xor_sync(0xFFFFFFFFu, v, 1);
                v += __shfl_xor_sync(0xFFFFFFFFu, v, 2);
                w += __shfl_xor_sync(0xFFFFFFFFu, w, 1);
                w += __shfl_xor_sync(0xFFFFFFFFu, w, 2);
                int row = bm + wm + mt * 16 + g + hf * 8;
                if (t4 == 0 && row < M) {
                    atomicAdd(&as_out[row * heads + head], v);
                    atomicAdd(&ad_out[row * heads + head], w);
                }
            }
    }
}

// ---------------- softmax layer 1: warp per dst node, 4 heads ----------------
__global__ __launch_bounds__(256) void k_softmax1()
{
    int w = (blockIdx.x * blockDim.x + threadIdx.x) >> 5;
    int lane = threadIdx.x & 31;
    if (w >= NN) return;
    int beg = g_rowptr[w], end = g_rowptr[w + 1];
    const float4* as4 = (const float4*)g_as1;
    float4 adv = ((const float4*)g_ad1)[w];
    float4 mx = make_float4(-1e30f, -1e30f, -1e30f, -1e30f);
    for (int i = beg + lane; i < end; i += 32) {
        float4 e = as4[g_srcidx[i]];
        e.x += adv.x; e.y += adv.y; e.z += adv.z; e.w += adv.w;
        e.x = (e.x > 0.f) ? e.x : NEG_SLOPE * e.x;
        e.y = (e.y > 0.f) ? e.y : NEG_SLOPE * e.y;
        e.z = (e.z > 0.f) ? e.z : NEG_SLOPE * e.z;
        e.w = (e.w > 0.f) ? e.w : NEG_SLOPE * e.w;
        g_alpha1[i] = e;
        mx.x = fmaxf(mx.x, e.x); mx.y = fmaxf(mx.y, e.y);
        mx.z = fmaxf(mx.z, e.z); mx.w = fmaxf(mx.w, e.w);
    }
    #pragma unroll
    for (int o = 16; o > 0; o >>= 1) {
        mx.x = fmaxf(mx.x, __shfl_xor_sync(0xFFFFFFFFu, mx.x, o));
        mx.y = fmaxf(mx.y, __shfl_xor_sync(0xFFFFFFFFu, mx.y, o));
        mx.z = fmaxf(mx.z, __shfl_xor_sync(0xFFFFFFFFu, mx.z, o));
        mx.w = fmaxf(mx.w, __shfl_xor_sync(0xFFFFFFFFu, mx.w, o));
    }
    float4 sum = make_float4(0.f, 0.f, 0.f, 0.f);
    for (int i = beg + lane; i < end; i += 32) {
        float4 e = g_alpha1[i];
        e.x = __expf(e.x - mx.x); e.y = __expf(e.y - mx.y);
        e.z = __expf(e.z - mx.z); e.w = __expf(e.w - mx.w);
        g_alpha1[i] = e;
        sum.x += e.x; sum.y += e.y; sum.z += e.z; sum.w += e.w;
    }
    #pragma unroll
    for (int o = 16; o > 0; o >>= 1) {
        sum.x += __shfl_xor_sync(0xFFFFFFFFu, sum.x, o);
        sum.y += __shfl_xor_sync(0xFFFFFFFFu, sum.y, o);
        sum.z += __shfl_xor_sync(0xFFFFFFFFu, sum.z, o);
        sum.w += __shfl_xor_sync(0xFFFFFFFFu, sum.w, o);
    }
    if (lane == 0)
        g_rd1[w] = make_float4(1.f / sum.x, 1.f / sum.y, 1.f / sum.z, 1.f / sum.w);
}

// ---------------- softmax layer 2 --------------------------------------------
__global__ __launch_bounds__(256) void k_softmax2()
{
    int w = (blockIdx.x * blockDim.x + threadIdx.x) >> 5;
    int lane = threadIdx.x & 31;
    if (w >= NN) return;
    int beg = g_rowptr[w], end = g_rowptr[w + 1];
    float adv = g_ad2[w];
    float mx = -1e30f;
    for (int i = beg + lane; i < end; i += 32) {
        float e = g_as2[g_srcidx[i]] + adv;
        e = (e > 0.f) ? e : NEG_SLOPE * e;
        g_alpha2[i] = e;
        mx = fmaxf(mx, e);
    }
    #pragma unroll
    for (int o = 16; o > 0; o >>= 1)
        mx = fmaxf(mx, __shfl_xor_sync(0xFFFFFFFFu, mx, o));
    float sum = 0.f;
    for (int i = beg + lane; i < end; i += 32) {
        float e = __expf(g_alpha2[i] - mx);
        g_alpha2[i] = e;
        sum += e;
    }
    #pragma unroll
    for (int o = 16; o > 0; o >>= 1)
        sum += __shfl_xor_sync(0xFFFFFFFFu, sum, o);
    if (lane == 0) g_rd2[w] = 1.f / sum;
}

// ---- aggregation layer 1: 64 threads per dst row, fp16 gathers --------------
__global__ __launch_bounds__(256) void k_agg1(const float* __restrict__ b1)
{
    int row = blockIdx.x * 4 + (threadIdx.x >> 6);
    if (row >= NN) return;
    int q = threadIdx.x & 63;
    int head = q >> 4;
    int beg = g_rowptr[row], end = g_rowptr[row + 1];
    float4 rdv = g_rd1[row];
    float rd = (head == 0) ? rdv.x : (head == 1) ? rdv.y : (head == 2) ? rdv.z : rdv.w;
    float4 acc0 = make_float4(0.f, 0.f, 0.f, 0.f);
    float4 acc1 = make_float4(0.f, 0.f, 0.f, 0.f);
    int i = beg;
    for (; i + 2 <= end; i += 2) {
        int s0 = g_srcidx[i], s1 = g_srcidx[i + 1];
        float4 a40 = g_alpha1[i], a41 = g_alpha1[i + 1];
        float a0 = (head == 0) ? a40.x : (head == 1) ? a40.y : (head == 2) ? a40.z : a40.w;
        float a1 = (head == 0) ? a41.x : (head == 1) ? a41.y : (head == 2) ? a41.z : a41.w;
        const __half2* p0 = (const __half2*)(g_h1h + (size_t)s0 * HC1 + q * 4);
        const __half2* p1 = (const __half2*)(g_h1h + (size_t)s1 * HC1 + q * 4);
        float2 h0a = __half22float2(p0[0]), h0b = __half22float2(p0[1]);
        float2 h1a = __half22float2(p1[0]), h1b = __half22float2(p1[1]);
        acc0.x += a0 * h0a.x; acc0.y += a0 * h0a.y; acc0.z += a0 * h0b.x; acc0.w += a0 * h0b.y;
        acc1.x += a1 * h1a.x; acc1.y += a1 * h1a.y; acc1.z += a1 * h1b.x; acc1.w += a1 * h1b.y;
    }
    if (i < end) {
        int s0 = g_srcidx[i];
        float4 a40 = g_alpha1[i];
        float a0 = (head == 0) ? a40.x : (head == 1) ? a40.y : (head == 2) ? a40.z : a40.w;
        const __half2* p0 = (const __half2*)(g_h1h + (size_t)s0 * HC1 + q * 4);
        float2 h0a = __half22float2(p0[0]), h0b = __half22float2(p0[1]);
        acc0.x += a0 * h0a.x; acc0.y += a0 * h0a.y; acc0.z += a0 * h0b.x; acc0.w += a0 * h0b.y;
    }
    float4 acc = make_float4((acc0.x + acc1.x) * rd, (acc0.y + acc1.y) * rd,
                             (acc0.z + acc1.z) * rd, (acc0.w + acc1.w) * rd);
    float4 bb = *(const float4*)(b1 + q * 4);
    acc.x += bb.x; acc.y += bb.y; acc.z += bb.z; acc.w += bb.w;
    acc.x = (acc.x > 0.f) ? acc.x : expm1f(acc.x);
    acc.y = (acc.y > 0.f) ? acc.y : expm1f(acc.y);
    acc.z = (acc.z > 0.f) ? acc.z : expm1f(acc.z);
    acc.w = (acc.w > 0.f) ? acc.w : expm1f(acc.w);
    *(float4*)(g_x2 + (size_t)row * HC1 + q * 4) = acc;
}

// ---- aggregation layer 2: 16 threads per dst row (fp32, unchanged) ----------
__global__ __launch_bounds__(256) void k_agg2(const float* __restrict__ b2,
                                              float* __restrict__ out)
{
    int row = blockIdx.x * 16 + (threadIdx.x >> 4);
    if (row >= NN) return;
    int q = threadIdx.x & 15;
    int beg = g_rowptr[row], end = g_rowptr[row + 1];
    float rd = g_rd2[row];
    float4 acc0 = make_float4(0.f, 0.f, 0.f, 0.f);
    float4 acc1 = make_float4(0.f, 0.f, 0.f, 0.f);
    int i = beg;
    for (; i + 2 <= end; i += 2) {
        int s0 = g_srcidx[i], s1 = g_srcidx[i + 1];
        float a0 = g_alpha2[i], a1 = g_alpha2[i + 1];
        float4 h0 = *(const float4*)(g_h2 + (size_t)s0 * OC + q * 4);
        float4 h1 = *(const float4*)(g_h2 + (size_t)s1 * OC + q * 4);
        acc0.x += a0 * h0.x; acc0.y += a0 * h0.y; acc0.z += a0 * h0.z; acc0.w += a0 * h0.w;
        acc1.x += a1 * h1.x; acc1.y += a1 * h1.y; acc1.z += a1 * h1.z; acc1.w += a1 * h1.w;
    }
    if (i < end) {
        int s0 = g_srcidx[i];
        float a0 = g_alpha2[i];
        float4 h0 = *(const float4*)(g_h2 + (size_t)s0 * OC + q * 4);
        acc0.x += a0 * h0.x; acc0.y += a0 * h0.y; acc0.z += a0 * h0.z; acc0.w += a0 * h0.w;
    }
    float4 bb = *(const float4*)(b2 + q * 4);
    float4 acc = make_float4((acc0.x + acc1.x) * rd + bb.x, (acc0.y + acc1.y) * rd + bb.y,
                             (acc0.z + acc1.z) * rd + bb.z, (acc0.w + acc1.w) * rd + bb.w);
    *(float4*)(out + (size_t)row * OC + q * 4) = acc;
}

// =============================================================================
extern "C" void kernel_launch(void* const* d_in, const int* in_sizes, int n_in,
                              void* d_out, int out_size)
{
    const float* x     = (const float*)d_in[0];
    const int*   ei    = (const int*)d_in[1];
    const float* W1    = (const float*)d_in[2];
    const float* a_s1  = (const float*)d_in[3];
    const float* a_d1  = (const float*)d_in[4];
    const float* b1    = (const float*)d_in[5];
    const float* W2    = (const float*)d_in[6];
    const float* a_s2  = (const float*)d_in[7];
    const float* a_d2  = (const float*)d_in[8];
    const float* b2    = (const float*)d_in[9];
    float*       out   = (float*)d_out;

    __half* h1h;
    float *x2, *as1, *ad1, *h2, *as2, *ad2;
    cudaGetSymbolAddress((void**)&h1h, g_h1h);
    cudaGetSymbolAddress((void**)&x2,  g_x2);
    cudaGetSymbolAddress((void**)&as1, g_as1);
    cudaGetSymbolAddress((void**)&ad1, g_ad1);
    cudaGetSymbolAddress((void**)&h2,  g_h2);
    cudaGetSymbolAddress((void**)&as2, g_as2);
    cudaGetSymbolAddress((void**)&ad2, g_ad2);

    const int SMEM_L1 = (2 * TBM * TSS + 2 * 128 * TSS) * 4;   // NTJ=4
    const int SMEM_L2 = (2 * TBM * TSS + 2 * 64  * TSS) * 4;   // NTJ=2
    cudaFuncSetAttribute(k_tf32gemm<4, true>,
                         cudaFuncAttributeMaxDynamicSharedMemorySize, SMEM_L1);
    cudaFuncSetAttribute(k_tf32gemm<2, false>,
                         cudaFuncAttributeMaxDynamicSharedMemorySize, SMEM_L2);

    cudaStream_t s2;
    cudaStreamCreate(&s2);
    cudaEvent_t evFork, evJoin;
    cudaEventCreateWithFlags(&evFork, cudaEventDisableTiming);
    cudaEventCreateWithFlags(&evJoin, cudaEventDisableTiming);

    // ---- fork: CSR build on s2, concurrent with GEMM1 ----
    cudaEventRecord(evFork, 0);
    cudaStreamWaitEvent(s2, evFork, 0);
    k_zero_deg<<<(NN + 255) / 256, 256, 0, s2>>>();
    k_count<<<(EP + 255) / 256, 256, 0, s2>>>(ei);
    k_scan1<<<NTILES, SCAN_T, 0, s2>>>();
    k_scan3m<<<NTILES, SCAN_T, 0, s2>>>();
    k_scatter<<<(EP + 255) / 256, 256, 0, s2>>>(ei);
    cudaEventRecord(evJoin, s2);

    // ---- main stream: attn zero + GEMM1 (fp16 C out) ----
    k_zero_attn<<<(NN + 255) / 256, 256>>>();
    {
        dim3 grid(HC1 / 128, (NN + TBM - 1) / TBM);
        k_tf32gemm<4, true><<<grid, 256, SMEM_L1>>>(x, W1, h1h, NN, HC1, INC,
                                                    a_s1, a_d1, as1, ad1, H1);
    }

    // ---- join ----
    cudaStreamWaitEvent(0, evJoin, 0);
    k_softmax1<<<(NN * 32 + 255) / 256, 256>>>();
    k_agg1<<<(NN + 3) / 4, 256>>>(b1);

    // ---- layer 2 (fp32 C out, 64-wide tile) ----
    {
        dim3 grid(OC / 64, (NN + TBM - 1) / TBM);
        k_tf32gemm<2, false><<<grid, 256, SMEM_L2>>>(x2, W2, h2, NN, OC, HC1,
                                                     a_s2, a_d2, as2, ad2, 1);
    }
    k_softmax2<<<(NN * 32 + 255) / 256, 256>>>();
    k_agg2<<<(NN + 15) / 16, 256>>>(b2, out);
}

// round 14
// speedup vs baseline: 1.5320x; 1.1942x over previous
#include <cuda_runtime.h>
#include <cuda_fp16.h>
#include <math.h>

// ---------------- problem constants ----------------
#define NN    50000
#define EE    800000
#define EP    850000          // EE + NN self loops
#define INC   1024
#define H1    4
#define C1    64
#define HC1   256             // H1*C1
#define OC    64
#define NEG_SLOPE 0.2f

#define SCAN_T 512
#define NTILES ((NN + SCAN_T - 1) / SCAN_T)

// ---------------- scratch (device globals) ----------------
__device__ __half  g_h1h[(size_t)NN * HC1];   // layer1 features, fp16 (agg path)
__device__ float   g_x2[(size_t)NN * HC1];
__device__ float   g_as1[NN * H1];
__device__ float   g_ad1[NN * H1];
__device__ float4  g_alpha1[EP];              // per-edge exp values (4 heads), CSR order
__device__ float4  g_rd1[NN];                 // reciprocal softmax denominators

__device__ float   g_h2[(size_t)NN * OC];
__device__ float   g_as2[NN];
__device__ float   g_ad2[NN];
__device__ float   g_alpha2[EP];
__device__ float   g_rd2[NN];

// CSR
__device__ int g_deg[NN];
__device__ int g_rowptr[NN + 1];
__device__ int g_cursor[NN];
__device__ int g_srcidx[EP];
__device__ int g_bsum[NTILES];

// ================= init + CSR construction =================
__global__ void k_zero_attn() {
    int i = blockIdx.x * blockDim.x + threadIdx.x;
    if (i >= NN) return;
    g_as2[i] = 0.f; g_ad2[i] = 0.f;
    float4 z = make_float4(0.f, 0.f, 0.f, 0.f);
    ((float4*)g_as1)[i] = z;
    ((float4*)g_ad1)[i] = z;
}
__global__ void k_zero_deg() {
    int i = blockIdx.x * blockDim.x + threadIdx.x;
    if (i < NN) g_deg[i] = 0;
}
__global__ void k_count(const int* __restrict__ ei) {
    int e = blockIdx.x * blockDim.x + threadIdx.x;
    if (e >= EP) return;
    int dn = (e < EE) ? ei[EE + e] : (e - EE);
    atomicAdd(&g_deg[dn], 1);
}
__global__ __launch_bounds__(SCAN_T) void k_scan1() {
    __shared__ int s[SCAN_T];
    int tid = threadIdx.x;
    int i = blockIdx.x * SCAN_T + tid;
    int v = (i < NN) ? g_deg[i] : 0;
    s[tid] = v;
    __syncthreads();
    #pragma unroll
    for (int off = 1; off < SCAN_T; off <<= 1) {
        int t = (tid >= off) ? s[tid - off] : 0;
        __syncthreads();
        s[tid] += t;
        __syncthreads();
    }
    if (i < NN) g_rowptr[i + 1] = s[tid];
    if (tid == SCAN_T - 1) g_bsum[blockIdx.x] = s[tid];
}
__global__ __launch_bounds__(SCAN_T) void k_scan3m() {
    __shared__ int off_s;
    int blk = blockIdx.x;
    if (threadIdx.x < 32) {
        int lane = threadIdx.x;
        int s = 0;
        for (int j = lane; j < blk; j += 32) s += g_bsum[j];
        #pragma unroll
        for (int o = 16; o > 0; o >>= 1) s += __shfl_xor_sync(0xFFFFFFFFu, s, o);
        if (lane == 0) off_s = s;
    }
    __syncthreads();
    int off = off_s;
    int i = blk * SCAN_T + threadIdx.x;
    if (i < NN) {
        int r = g_rowptr[i + 1] + off;
        g_rowptr[i + 1] = r;
        g_cursor[i] = r - g_deg[i];
    }
    if (i == 0) g_rowptr[0] = 0;
}
__global__ void k_scatter(const int* __restrict__ ei) {
    int e = blockIdx.x * blockDim.x + threadIdx.x;
    if (e >= EP) return;
    int s, dn;
    if (e < EE) { s = ei[e]; dn = ei[EE + e]; }
    else        { s = e - EE; dn = s; }
    int pos = atomicAdd(&g_cursor[dn], 1);
    g_srcidx[pos] = s;
}

// ============= FP16 GEMM (m16n8k16) + fused attention epilogue ===============
// smem: half rows of 32 k-values, row stride TSH=40 halves (word stride 20:
// fragment LDS conflict-free since 20*dg+dt4 != 0 mod 32 for dg in 1..7,|dt4|<=3)
#define TBM 128
#define TBK 32
#define TSH 40

template<int NTJ, bool HOUT>
__global__ __launch_bounds__(256, 2) void k_h16gemm(
    const float* __restrict__ A, const float* __restrict__ B,
    void* __restrict__ Cout, int M, int N, int K,
    const float* __restrict__ avs, const float* __restrict__ avd,
    float* __restrict__ as_out, float* __restrict__ ad_out, int heads)
{
    const int TBNE = 32 * NTJ;              // 128 or 64
    extern __shared__ __half smem_h[];
    __half* Abase = smem_h;                         // [2][TBM][TSH]
    __half* Bbase = smem_h + 2 * TBM * TSH;         // [2][TBNE][TSH]

    int tid = threadIdx.x;
    int bm = blockIdx.y * TBM, bn = blockIdx.x * (4 * 8 * NTJ);
    int wid = tid >> 5, lane = tid & 31;
    int wm = (wid >> 2) * 64;
    int wn = (wid & 3) * (8 * NTJ);
    int g  = lane >> 2;
    int t4 = lane & 3;

    int r0 = tid >> 3;
    int c4 = (tid & 7) * 4;

    float c[4][NTJ][4];
    #pragma unroll
    for (int i = 0; i < 4; i++)
        #pragma unroll
        for (int j = 0; j < NTJ; j++)
            #pragma unroll
            for (int r = 0; r < 4; r++) c[i][j][r] = 0.f;

    const float4 zero4 = make_float4(0.f, 0.f, 0.f, 0.f);
    float4 pa[4], pb[NTJ];
    int nt = K / TBK;

    // fetch tile 0
    #pragma unroll
    for (int i = 0; i < 4; i++) {
        int ar = bm + r0 + 32 * i;
        pa[i] = (ar < M) ? *(const float4*)(A + (size_t)ar * K + c4) : zero4;
    }
    #pragma unroll
    for (int i = 0; i < NTJ; i++) {
        int br = bn + r0 + 32 * i;
        pb[i] = (br < N) ? *(const float4*)(B + (size_t)br * K + c4) : zero4;
    }
    {
        #pragma unroll
        for (int i = 0; i < 4; i++) {
            __half2* ap = (__half2*)(Abase + (r0 + 32 * i) * TSH + c4);
            ap[0] = __floats2half2_rn(pa[i].x, pa[i].y);
            ap[1] = __floats2half2_rn(pa[i].z, pa[i].w);
        }
        #pragma unroll
        for (int i = 0; i < NTJ; i++) {
            __half2* bp = (__half2*)(Bbase + (r0 + 32 * i) * TSH + c4);
            bp[0] = __floats2half2_rn(pb[i].x, pb[i].y);
            bp[1] = __floats2half2_rn(pb[i].z, pb[i].w);
        }
    }
    __syncthreads();

    for (int t = 0; t < nt; t++) {
        int cur = t & 1;
        bool more = (t + 1 < nt);
        if (more) {
            int k0 = (t + 1) * TBK;
            #pragma unroll
            for (int i = 0; i < 4; i++) {
                int ar = bm + r0 + 32 * i;
                pa[i] = (ar < M) ? *(const float4*)(A + (size_t)ar * K + k0 + c4) : zero4;
            }
            #pragma unroll
            for (int i = 0; i < NTJ; i++) {
                int br = bn + r0 + 32 * i;
                pb[i] = (br < N) ? *(const float4*)(B + (size_t)br * K + k0 + c4) : zero4;
            }
        }
        const __half* Ab = Abase + cur * TBM * TSH;
        const __half* Bb = Bbase + cur * TBNE * TSH;
        #pragma unroll
        for (int kc = 0; kc < 2; kc++) {          // two k16 chunks per 32-k tile
            int k0 = kc * 16 + 2 * t4;
            unsigned af[4][4], bf[NTJ][2];
            #pragma unroll
            for (int mt = 0; mt < 4; mt++) {
                int row = wm + mt * 16 + g;
                af[mt][0] = *(const unsigned*)(Ab + row * TSH + k0);
                af[mt][1] = *(const unsigned*)(Ab + (row + 8) * TSH + k0);
                af[mt][2] = *(const unsigned*)(Ab + row * TSH + k0 + 8);
                af[mt][3] = *(const unsigned*)(Ab + (row + 8) * TSH + k0 + 8);
            }
            #pragma unroll
            for (int ntj = 0; ntj < NTJ; ntj++) {
                int col = wn + ntj * 8 + g;
                bf[ntj][0] = *(const unsigned*)(Bb + col * TSH + k0);
                bf[ntj][1] = *(const unsigned*)(Bb + col * TSH + k0 + 8);
            }
            #pragma unroll
            for (int mt = 0; mt < 4; mt++)
                #pragma unroll
                for (int ntj = 0; ntj < NTJ; ntj++) {
                    asm volatile(
                        "mma.sync.aligned.m16n8k16.row.col.f32.f16.f16.f32 "
                        "{%0,%1,%2,%3}, {%4,%5,%6,%7}, {%8,%9}, {%0,%1,%2,%3};"
                        : "+f"(c[mt][ntj][0]), "+f"(c[mt][ntj][1]),
                          "+f"(c[mt][ntj][2]), "+f"(c[mt][ntj][3])
                        : "r"(af[mt][0]), "r"(af[mt][1]), "r"(af[mt][2]), "r"(af[mt][3]),
                          "r"(bf[ntj][0]), "r"(bf[ntj][1]));
                }
        }
        if (more) {
            int nx = cur ^ 1;
            __half* Aw = Abase + nx * TBM * TSH;
            __half* Bw = Bbase + nx * TBNE * TSH;
            #pragma unroll
            for (int i = 0; i < 4; i++) {
                __half2* ap = (__half2*)(Aw + (r0 + 32 * i) * TSH + c4);
                ap[0] = __floats2half2_rn(pa[i].x, pa[i].y);
                ap[1] = __floats2half2_rn(pa[i].z, pa[i].w);
            }
            #pragma unroll
            for (int i = 0; i < NTJ; i++) {
                __half2* bp = (__half2*)(Bw + (r0 + 32 * i) * TSH + c4);
                bp[0] = __floats2half2_rn(pb[i].x, pb[i].y);
                bp[1] = __floats2half2_rn(pb[i].z, pb[i].w);
            }
            __syncthreads();
        }
    }

    // ---- C store (fragment layout identical to m16n8k8) ----
    #pragma unroll
    for (int mt = 0; mt < 4; mt++) {
        int row0 = bm + wm + mt * 16 + g;
        #pragma unroll
        for (int ntj = 0; ntj < NTJ; ntj++) {
            int col = bn + wn + ntj * 8 + t4 * 2;
            if (HOUT) {
                __half* Ch = (__half*)Cout;
                if (row0 < M && col + 1 < N)
                    *(__half2*)(Ch + (size_t)row0 * N + col) =
                        __floats2half2_rn(c[mt][ntj][0], c[mt][ntj][1]);
                if (row0 + 8 < M && col + 1 < N)
                    *(__half2*)(Ch + (size_t)(row0 + 8) * N + col) =
                        __floats2half2_rn(c[mt][ntj][2], c[mt][ntj][3]);
            } else {
                float* Cf = (float*)Cout;
                if (row0 < M && col + 1 < N) {
                    Cf[(size_t)row0 * N + col]     = c[mt][ntj][0];
                    Cf[(size_t)row0 * N + col + 1] = c[mt][ntj][1];
                }
                if (row0 + 8 < M && col + 1 < N) {
                    Cf[(size_t)(row0 + 8) * N + col]     = c[mt][ntj][2];
                    Cf[(size_t)(row0 + 8) * N + col + 1] = c[mt][ntj][3];
                }
            }
        }
    }

    // ---- fused attention-coefficient partials ----
    int head = (bn + wn) >> 6;
    if (head < heads) {
        float asac[4][2] = {}, adac[4][2] = {};
        #pragma unroll
        for (int mt = 0; mt < 4; mt++)
            #pragma unroll
            for (int ntj = 0; ntj < NTJ; ntj++) {
                int colb = bn + wn + ntj * 8 + t4 * 2;
                if (colb + 1 < N) {
                    float s0 = avs[colb], s1 = avs[colb + 1];
                    float d0 = avd[colb], d1 = avd[colb + 1];
                    asac[mt][0] += c[mt][ntj][0] * s0 + c[mt][ntj][1] * s1;
                    adac[mt][0] += c[mt][ntj][0] * d0 + c[mt][ntj][1] * d1;
                    asac[mt][1] += c[mt][ntj][2] * s0 + c[mt][ntj][3] * s1;
                    adac[mt][1] += c[mt][ntj][2] * d0 + c[mt][ntj][3] * d1;
                }
            }
        #pragma unroll
        for (int mt = 0; mt < 4; mt++)
            #pragma unroll
            for (int hf = 0; hf < 2; hf++) {
                float v = asac[mt][hf];
                float w = adac[mt][hf];
                v += __shfl_xor_sync(0xFFFFFFFFu, v, 1);
                v += __shfl_xor_sync(0xFFFFFFFFu, v, 2);
                w += __shfl_xor_sync(0xFFFFFFFFu, w, 1);
                w += __shfl_xor_sync(0xFFFFFFFFu, w, 2);
                int row = bm + wm + mt * 16 + g + hf * 8;
                if (t4 == 0 && row < M) {
                    atomicAdd(&as_out[row * heads + head], v);
                    atomicAdd(&ad_out[row * heads + head], w);
                }
            }
    }
}

// ---------------- softmax layer 1: warp per dst node, 4 heads ----------------
__global__ __launch_bounds__(256) void k_softmax1()
{
    int w = (blockIdx.x * blockDim.x + threadIdx.x) >> 5;
    int lane = threadIdx.x & 31;
    if (w >= NN) return;
    int beg = g_rowptr[w], end = g_rowptr[w + 1];
    const float4* as4 = (const float4*)g_as1;
    float4 adv = ((const float4*)g_ad1)[w];
    float4 mx = make_float4(-1e30f, -1e30f, -1e30f, -1e30f);
    for (int i = beg + lane; i < end; i += 32) {
        float4 e = as4[g_srcidx[i]];
        e.x += adv.x; e.y += adv.y; e.z += adv.z; e.w += adv.w;
        e.x = (e.x > 0.f) ? e.x : NEG_SLOPE * e.x;
        e.y = (e.y > 0.f) ? e.y : NEG_SLOPE * e.y;
        e.z = (e.z > 0.f) ? e.z : NEG_SLOPE * e.z;
        e.w = (e.w > 0.f) ? e.w : NEG_SLOPE * e.w;
        g_alpha1[i] = e;
        mx.x = fmaxf(mx.x, e.x); mx.y = fmaxf(mx.y, e.y);
        mx.z = fmaxf(mx.z, e.z); mx.w = fmaxf(mx.w, e.w);
    }
    #pragma unroll
    for (int o = 16; o > 0; o >>= 1) {
        mx.x = fmaxf(mx.x, __shfl_xor_sync(0xFFFFFFFFu, mx.x, o));
        mx.y = fmaxf(mx.y, __shfl_xor_sync(0xFFFFFFFFu, mx.y, o));
        mx.z = fmaxf(mx.z, __shfl_xor_sync(0xFFFFFFFFu, mx.z, o));
        mx.w = fmaxf(mx.w, __shfl_xor_sync(0xFFFFFFFFu, mx.w, o));
    }
    float4 sum = make_float4(0.f, 0.f, 0.f, 0.f);
    for (int i = beg + lane; i < end; i += 32) {
        float4 e = g_alpha1[i];
        e.x = __expf(e.x - mx.x); e.y = __expf(e.y - mx.y);
        e.z = __expf(e.z - mx.z); e.w = __expf(e.w - mx.w);
        g_alpha1[i] = e;
        sum.x += e.x; sum.y += e.y; sum.z += e.z; sum.w += e.w;
    }
    #pragma unroll
    for (int o = 16; o > 0; o >>= 1) {
        sum.x += __shfl_xor_sync(0xFFFFFFFFu, sum.x, o);
        sum.y += __shfl_xor_sync(0xFFFFFFFFu, sum.y, o);
        sum.z += __shfl_xor_sync(0xFFFFFFFFu, sum.z, o);
        sum.w += __shfl_xor_sync(0xFFFFFFFFu, sum.w, o);
    }
    if (lane == 0)
        g_rd1[w] = make_float4(1.f / sum.x, 1.f / sum.y, 1.f / sum.z, 1.f / sum.w);
}

// ---------------- softmax layer 2 --------------------------------------------
__global__ __launch_bounds__(256) void k_softmax2()
{
    int w = (blockIdx.x * blockDim.x + threadIdx.x) >> 5;
    int lane = threadIdx.x & 31;
    if (w >= NN) return;
    int beg = g_rowptr[w], end = g_rowptr[w + 1];
    float adv = g_ad2[w];
    float mx = -1e30f;
    for (int i = beg + lane; i < end; i += 32) {
        float e = g_as2[g_srcidx[i]] + adv;
        e = (e > 0.f) ? e : NEG_SLOPE * e;
        g_alpha2[i] = e;
        mx = fmaxf(mx, e);
    }
    #pragma unroll
    for (int o = 16; o > 0; o >>= 1)
        mx = fmaxf(mx, __shfl_xor_sync(0xFFFFFFFFu, mx, o));
    float sum = 0.f;
    for (int i = beg + lane; i < end; i += 32) {
        float e = __expf(g_alpha2[i] - mx);
        g_alpha2[i] = e;
        sum += e;
    }
    #pragma unroll
    for (int o = 16; o > 0; o >>= 1)
        sum += __shfl_xor_sync(0xFFFFFFFFu, sum, o);
    if (lane == 0) g_rd2[w] = 1.f / sum;
}

// ---- aggregation layer 1: 64 threads per dst row, fp16 gathers --------------
__global__ __launch_bounds__(256) void k_agg1(const float* __restrict__ b1)
{
    int row = blockIdx.x * 4 + (threadIdx.x >> 6);
    if (row >= NN) return;
    int q = threadIdx.x & 63;
    int head = q >> 4;
    int beg = g_rowptr[row], end = g_rowptr[row + 1];
    float4 rdv = g_rd1[row];
    float rd = (head == 0) ? rdv.x : (head == 1) ? rdv.y : (head == 2) ? rdv.z : rdv.w;
    float4 acc0 = make_float4(0.f, 0.f, 0.f, 0.f);
    float4 acc1 = make_float4(0.f, 0.f, 0.f, 0.f);
    int i = beg;
    for (; i + 2 <= end; i += 2) {
        int s0 = g_srcidx[i], s1 = g_srcidx[i + 1];
        float4 a40 = g_alpha1[i], a41 = g_alpha1[i + 1];
        float a0 = (head == 0) ? a40.x : (head == 1) ? a40.y : (head == 2) ? a40.z : a40.w;
        float a1 = (head == 0) ? a41.x : (head == 1) ? a41.y : (head == 2) ? a41.z : a41.w;
        const __half2* p0 = (const __half2*)(g_h1h + (size_t)s0 * HC1 + q * 4);
        const __half2* p1 = (const __half2*)(g_h1h + (size_t)s1 * HC1 + q * 4);
        float2 h0a = __half22float2(p0[0]), h0b = __half22float2(p0[1]);
        float2 h1a = __half22float2(p1[0]), h1b = __half22float2(p1[1]);
        acc0.x += a0 * h0a.x; acc0.y += a0 * h0a.y; acc0.z += a0 * h0b.x; acc0.w += a0 * h0b.y;
        acc1.x += a1 * h1a.x; acc1.y += a1 * h1a.y; acc1.z += a1 * h1b.x; acc1.w += a1 * h1b.y;
    }
    if (i < end) {
        int s0 = g_srcidx[i];
        float4 a40 = g_alpha1[i];
        float a0 = (head == 0) ? a40.x : (head == 1) ? a40.y : (head == 2) ? a40.z : a40.w;
        const __half2* p0 = (const __half2*)(g_h1h + (size_t)s0 * HC1 + q * 4);
        float2 h0a = __half22float2(p0[0]), h0b = __half22float2(p0[1]);
        acc0.x += a0 * h0a.x; acc0.y += a0 * h0a.y; acc0.z += a0 * h0b.x; acc0.w += a0 * h0b.y;
    }
    float4 acc = make_float4((acc0.x + acc1.x) * rd, (acc0.y + acc1.y) * rd,
                             (acc0.z + acc1.z) * rd, (acc0.w + acc1.w) * rd);
    float4 bb = *(const float4*)(b1 + q * 4);
    acc.x += bb.x; acc.y += bb.y; acc.z += bb.z; acc.w += bb.w;
    acc.x = (acc.x > 0.f) ? acc.x : expm1f(acc.x);
    acc.y = (acc.y > 0.f) ? acc.y : expm1f(acc.y);
    acc.z = (acc.z > 0.f) ? acc.z : expm1f(acc.z);
    acc.w = (acc.w > 0.f) ? acc.w : expm1f(acc.w);
    *(float4*)(g_x2 + (size_t)row * HC1 + q * 4) = acc;
}

// ---- aggregation layer 2: 16 threads per dst row (fp32) ---------------------
__global__ __launch_bounds__(256) void k_agg2(const float* __restrict__ b2,
                                              float* __restrict__ out)
{
    int row = blockIdx.x * 16 + (threadIdx.x >> 4);
    if (row >= NN) return;
    int q = threadIdx.x & 15;
    int beg = g_rowptr[row], end = g_rowptr[row + 1];
    float rd = g_rd2[row];
    float4 acc0 = make_float4(0.f, 0.f, 0.f, 0.f);
    float4 acc1 = make_float4(0.f, 0.f, 0.f, 0.f);
    int i = beg;
    for (; i + 2 <= end; i += 2) {
        int s0 = g_srcidx[i], s1 = g_srcidx[i + 1];
        float a0 = g_alpha2[i], a1 = g_alpha2[i + 1];
        float4 h0 = *(const float4*)(g_h2 + (size_t)s0 * OC + q * 4);
        float4 h1 = *(const float4*)(g_h2 + (size_t)s1 * OC + q * 4);
        acc0.x += a0 * h0.x; acc0.y += a0 * h0.y; acc0.z += a0 * h0.z; acc0.w += a0 * h0.w;
        acc1.x += a1 * h1.x; acc1.y += a1 * h1.y; acc1.z += a1 * h1.z; acc1.w += a1 * h1.w;
    }
    if (i < end) {
        int s0 = g_srcidx[i];
        float a0 = g_alpha2[i];
        float4 h0 = *(const float4*)(g_h2 + (size_t)s0 * OC + q * 4);
        acc0.x += a0 * h0.x; acc0.y += a0 * h0.y; acc0.z += a0 * h0.z; acc0.w += a0 * h0.w;
    }
    float4 bb = *(const float4*)(b2 + q * 4);
    float4 acc = make_float4((acc0.x + acc1.x) * rd + bb.x, (acc0.y + acc1.y) * rd + bb.y,
                             (acc0.z + acc1.z) * rd + bb.z, (acc0.w + acc1.w) * rd + bb.w);
    *(float4*)(out + (size_t)row * OC + q * 4) = acc;
}

// =============================================================================
extern "C" void kernel_launch(void* const* d_in, const int* in_sizes, int n_in,
                              void* d_out, int out_size)
{
    const float* x     = (const float*)d_in[0];
    const int*   ei    = (const int*)d_in[1];
    const float* W1    = (const float*)d_in[2];
    const float* a_s1  = (const float*)d_in[3];
    const float* a_d1  = (const float*)d_in[4];
    const float* b1    = (const float*)d_in[5];
    const float* W2    = (const float*)d_in[6];
    const float* a_s2  = (const float*)d_in[7];
    const float* a_d2  = (const float*)d_in[8];
    const float* b2    = (const float*)d_in[9];
    float*       out   = (float*)d_out;

    __half* h1h;
    float *x2, *as1, *ad1, *h2, *as2, *ad2;
    cudaGetSymbolAddress((void**)&h1h, g_h1h);
    cudaGetSymbolAddress((void**)&x2,  g_x2);
    cudaGetSymbolAddress((void**)&as1, g_as1);
    cudaGetSymbolAddress((void**)&ad1, g_ad1);
    cudaGetSymbolAddress((void**)&h2,  g_h2);
    cudaGetSymbolAddress((void**)&as2, g_as2);
    cudaGetSymbolAddress((void**)&ad2, g_ad2);

    const int SMEM_L1 = (2 * TBM * TSH + 2 * 128 * TSH) * 2;   // NTJ=4: 40960 B
    const int SMEM_L2 = (2 * TBM * TSH + 2 * 64  * TSH) * 2;   // NTJ=2: 30720 B
    cudaFuncSetAttribute(k_h16gemm<4, true>,
                         cudaFuncAttributeMaxDynamicSharedMemorySize, SMEM_L1);
    cudaFuncSetAttribute(k_h16gemm<2, false>,
                         cudaFuncAttributeMaxDynamicSharedMemorySize, SMEM_L2);

    cudaStream_t s2;
    cudaStreamCreate(&s2);
    cudaEvent_t evFork, evJoin;
    cudaEventCreateWithFlags(&evFork, cudaEventDisableTiming);
    cudaEventCreateWithFlags(&evJoin, cudaEventDisableTiming);

    // ---- fork: CSR build on s2, concurrent with GEMM1 ----
    cudaEventRecord(evFork, 0);
    cudaStreamWaitEvent(s2, evFork, 0);
    k_zero_deg<<<(NN + 255) / 256, 256, 0, s2>>>();
    k_count<<<(EP + 255) / 256, 256, 0, s2>>>(ei);
    k_scan1<<<NTILES, SCAN_T, 0, s2>>>();
    k_scan3m<<<NTILES, SCAN_T, 0, s2>>>();
    k_scatter<<<(EP + 255) / 256, 256, 0, s2>>>(ei);
    cudaEventRecord(evJoin, s2);

    // ---- main stream: attn zero + GEMM1 (fp16 C out) ----
    k_zero_attn<<<(NN + 255) / 256, 256>>>();
    {
        dim3 grid(HC1 / 128, (NN + TBM - 1) / TBM);
        k_h16gemm<4, true><<<grid, 256, SMEM_L1>>>(x, W1, h1h, NN, HC1, INC,
                                                   a_s1, a_d1, as1, ad1, H1);
    }

    // ---- join ----
    cudaStreamWaitEvent(0, evJoin, 0);
    k_softmax1<<<(NN * 32 + 255) / 256, 256>>>();
    k_agg1<<<(NN + 3) / 4, 256>>>(b1);

    // ---- layer 2 (fp32 C out, 64-wide tile) ----
    {
        dim3 grid(OC / 64, (NN + TBM - 1) / TBM);
        k_h16gemm<2, false><<<grid, 256, SMEM_L2>>>(x2, W2, h2, NN, OC, HC1,
                                                    a_s2, a_d2, as2, ad2, 1);
    }
    k_softmax2<<<(NN * 32 + 255) / 256, 256>>>();
    k_agg2<<<(NN + 15) / 16, 256>>>(b2, out);
}

// round 15
// speedup vs baseline: 1.5860x; 1.0353x over previous
#include <cuda_runtime.h>
#include <cuda_fp16.h>
#include <math.h>

// ---------------- problem constants ----------------
#define NN    50000
#define EE    800000
#define EP    850000          // EE + NN self loops
#define INC   1024
#define H1    4
#define C1    64
#define HC1   256             // H1*C1
#define OC    64
#define NEG_SLOPE 0.2f

#define SCAN_T 512
#define NTILES ((NN + SCAN_T - 1) / SCAN_T)

// ---------------- scratch (device globals) ----------------
__device__ __half  g_h1h[(size_t)NN * HC1];   // layer1 features (agg path), fp16
__device__ __half  g_x2h[(size_t)NN * HC1];   // elu(agg1+b1), fp16 (GEMM2 A input)
__device__ float   g_as1[NN * H1];
__device__ float   g_ad1[NN * H1];
__device__ float4  g_alpha1[EP];              // per-edge exp values (4 heads), CSR order
__device__ float4  g_rd1[NN];                 // reciprocal softmax denominators

__device__ __half  g_h2h[(size_t)NN * OC];    // layer2 features, fp16
__device__ float   g_as2[NN];
__device__ float   g_ad2[NN];
__device__ float   g_alpha2[EP];
__device__ float   g_rd2[NN];

// CSR
__device__ int g_deg[NN];
__device__ int g_rowptr[NN + 1];
__device__ int g_cursor[NN];
__device__ int g_srcidx[EP];
__device__ int g_bsum[NTILES];

// ================= init + CSR construction =================
__global__ void k_zero_attn() {
    int i = blockIdx.x * blockDim.x + threadIdx.x;
    if (i >= NN) return;
    g_as2[i] = 0.f; g_ad2[i] = 0.f;
    float4 z = make_float4(0.f, 0.f, 0.f, 0.f);
    ((float4*)g_as1)[i] = z;
    ((float4*)g_ad1)[i] = z;
}
__global__ void k_zero_deg() {
    int i = blockIdx.x * blockDim.x + threadIdx.x;
    if (i < NN) g_deg[i] = 0;
}
__global__ void k_count(const int* __restrict__ ei) {
    int e = blockIdx.x * blockDim.x + threadIdx.x;
    if (e >= EP) return;
    int dn = (e < EE) ? ei[EE + e] : (e - EE);
    atomicAdd(&g_deg[dn], 1);
}
__global__ __launch_bounds__(SCAN_T) void k_scan1() {
    __shared__ int s[SCAN_T];
    int tid = threadIdx.x;
    int i = blockIdx.x * SCAN_T + tid;
    int v = (i < NN) ? g_deg[i] : 0;
    s[tid] = v;
    __syncthreads();
    #pragma unroll
    for (int off = 1; off < SCAN_T; off <<= 1) {
        int t = (tid >= off) ? s[tid - off] : 0;
        __syncthreads();
        s[tid] += t;
        __syncthreads();
    }
    if (i < NN) g_rowptr[i + 1] = s[tid];
    if (tid == SCAN_T - 1) g_bsum[blockIdx.x] = s[tid];
}
__global__ __launch_bounds__(SCAN_T) void k_scan3m() {
    __shared__ int off_s;
    int blk = blockIdx.x;
    if (threadIdx.x < 32) {
        int lane = threadIdx.x;
        int s = 0;
        for (int j = lane; j < blk; j += 32) s += g_bsum[j];
        #pragma unroll
        for (int o = 16; o > 0; o >>= 1) s += __shfl_xor_sync(0xFFFFFFFFu, s, o);
        if (lane == 0) off_s = s;
    }
    __syncthreads();
    int off = off_s;
    int i = blk * SCAN_T + threadIdx.x;
    if (i < NN) {
        int r = g_rowptr[i + 1] + off;
        g_rowptr[i + 1] = r;
        g_cursor[i] = r - g_deg[i];
    }
    if (i == 0) g_rowptr[0] = 0;
}
__global__ void k_scatter(const int* __restrict__ ei) {
    int e = blockIdx.x * blockDim.x + threadIdx.x;
    if (e >= EP) return;
    int s, dn;
    if (e < EE) { s = ei[e]; dn = ei[EE + e]; }
    else        { s = e - EE; dn = s; }
    int pos = atomicAdd(&g_cursor[dn], 1);
    g_srcidx[pos] = s;
}

// ============= FP16 GEMM (m16n8k16) + fused attention epilogue ===============
// HIN:  A is fp16 (load uint2 = 4 halves, store to smem directly)
// HOUT: C written as fp16
#define TBM 128
#define TBK 32
#define TSH 40

template<int NTJ, bool HIN, bool HOUT>
__global__ __launch_bounds__(256, 2) void k_h16gemm(
    const void* __restrict__ Ain, const float* __restrict__ B,
    void* __restrict__ Cout, int M, int N, int K,
    const float* __restrict__ avs, const float* __restrict__ avd,
    float* __restrict__ as_out, float* __restrict__ ad_out, int heads)
{
    const int TBNE = 32 * NTJ;              // 128 or 64
    extern __shared__ __half smem_h[];
    __half* Abase = smem_h;                         // [2][TBM][TSH]
    __half* Bbase = smem_h + 2 * TBM * TSH;         // [2][TBNE][TSH]

    int tid = threadIdx.x;
    int bm = blockIdx.y * TBM, bn = blockIdx.x * (4 * 8 * NTJ);
    int wid = tid >> 5, lane = tid & 31;
    int wm = (wid >> 2) * 64;
    int wn = (wid & 3) * (8 * NTJ);
    int g  = lane >> 2;
    int t4 = lane & 3;

    int r0 = tid >> 3;
    int c4 = (tid & 7) * 4;

    float c[4][NTJ][4];
    #pragma unroll
    for (int i = 0; i < 4; i++)
        #pragma unroll
        for (int j = 0; j < NTJ; j++)
            #pragma unroll
            for (int r = 0; r < 4; r++) c[i][j][r] = 0.f;

    const float4 zero4 = make_float4(0.f, 0.f, 0.f, 0.f);
    const uint2  zero2 = make_uint2(0u, 0u);
    float4 pa[4], pb[NTJ];
    uint2  pah[4];
    int nt = K / TBK;

    // ---- prologue fetch ----
    #pragma unroll
    for (int i = 0; i < 4; i++) {
        int ar = bm + r0 + 32 * i;
        if (HIN) {
            const __half* Ah = (const __half*)Ain;
            pah[i] = (ar < M) ? *(const uint2*)(Ah + (size_t)ar * K + c4) : zero2;
        } else {
            const float* Af = (const float*)Ain;
            pa[i] = (ar < M) ? *(const float4*)(Af + (size_t)ar * K + c4) : zero4;
        }
    }
    #pragma unroll
    for (int i = 0; i < NTJ; i++) {
        int br = bn + r0 + 32 * i;
        pb[i] = (br < N) ? *(const float4*)(B + (size_t)br * K + c4) : zero4;
    }
    {
        #pragma unroll
        for (int i = 0; i < 4; i++) {
            __half* ap = Abase + (r0 + 32 * i) * TSH + c4;
            if (HIN) {
                *(uint2*)ap = pah[i];
            } else {
                ((__half2*)ap)[0] = __floats2half2_rn(pa[i].x, pa[i].y);
                ((__half2*)ap)[1] = __floats2half2_rn(pa[i].z, pa[i].w);
            }
        }
        #pragma unroll
        for (int i = 0; i < NTJ; i++) {
            __half2* bp = (__half2*)(Bbase + (r0 + 32 * i) * TSH + c4);
            bp[0] = __floats2half2_rn(pb[i].x, pb[i].y);
            bp[1] = __floats2half2_rn(pb[i].z, pb[i].w);
        }
    }
    __syncthreads();

    for (int t = 0; t < nt; t++) {
        int cur = t & 1;
        bool more = (t + 1 < nt);
        if (more) {
            int k0 = (t + 1) * TBK;
            #pragma unroll
            for (int i = 0; i < 4; i++) {
                int ar = bm + r0 + 32 * i;
                if (HIN) {
                    const __half* Ah = (const __half*)Ain;
                    pah[i] = (ar < M) ? *(const uint2*)(Ah + (size_t)ar * K + k0 + c4) : zero2;
                } else {
                    const float* Af = (const float*)Ain;
                    pa[i] = (ar < M) ? *(const float4*)(Af + (size_t)ar * K + k0 + c4) : zero4;
                }
            }
            #pragma unroll
            for (int i = 0; i < NTJ; i++) {
                int br = bn + r0 + 32 * i;
                pb[i] = (br < N) ? *(const float4*)(B + (size_t)br * K + k0 + c4) : zero4;
            }
        }
        const __half* Ab = Abase + cur * TBM * TSH;
        const __half* Bb = Bbase + cur * TBNE * TSH;
        #pragma unroll
        for (int kc = 0; kc < 2; kc++) {
            int k0 = kc * 16 + 2 * t4;
            unsigned af[4][4], bf[NTJ][2];
            #pragma unroll
            for (int mt = 0; mt < 4; mt++) {
                int row = wm + mt * 16 + g;
                af[mt][0] = *(const unsigned*)(Ab + row * TSH + k0);
                af[mt][1] = *(const unsigned*)(Ab + (row + 8) * TSH + k0);
                af[mt][2] = *(const unsigned*)(Ab + row * TSH + k0 + 8);
                af[mt][3] = *(const unsigned*)(Ab + (row + 8) * TSH + k0 + 8);
            }
            #pragma unroll
            for (int ntj = 0; ntj < NTJ; ntj++) {
                int col = wn + ntj * 8 + g;
                bf[ntj][0] = *(const unsigned*)(Bb + col * TSH + k0);
                bf[ntj][1] = *(const unsigned*)(Bb + col * TSH + k0 + 8);
            }
            #pragma unroll
            for (int mt = 0; mt < 4; mt++)
                #pragma unroll
                for (int ntj = 0; ntj < NTJ; ntj++) {
                    asm volatile(
                        "mma.sync.aligned.m16n8k16.row.col.f32.f16.f16.f32 "
                        "{%0,%1,%2,%3}, {%4,%5,%6,%7}, {%8,%9}, {%0,%1,%2,%3};"
                        : "+f"(c[mt][ntj][0]), "+f"(c[mt][ntj][1]),
                          "+f"(c[mt][ntj][2]), "+f"(c[mt][ntj][3])
                        : "r"(af[mt][0]), "r"(af[mt][1]), "r"(af[mt][2]), "r"(af[mt][3]),
                          "r"(bf[ntj][0]), "r"(bf[ntj][1]));
                }
        }
        if (more) {
            int nx = cur ^ 1;
            __half* Aw = Abase + nx * TBM * TSH;
            __half* Bw = Bbase + nx * TBNE * TSH;
            #pragma unroll
            for (int i = 0; i < 4; i++) {
                __half* ap = Aw + (r0 + 32 * i) * TSH + c4;
                if (HIN) {
                    *(uint2*)ap = pah[i];
                } else {
                    ((__half2*)ap)[0] = __floats2half2_rn(pa[i].x, pa[i].y);
                    ((__half2*)ap)[1] = __floats2half2_rn(pa[i].z, pa[i].w);
                }
            }
            #pragma unroll
            for (int i = 0; i < NTJ; i++) {
                __half2* bp = (__half2*)(Bw + (r0 + 32 * i) * TSH + c4);
                bp[0] = __floats2half2_rn(pb[i].x, pb[i].y);
                bp[1] = __floats2half2_rn(pb[i].z, pb[i].w);
            }
            __syncthreads();
        }
    }

    // ---- C store ----
    #pragma unroll
    for (int mt = 0; mt < 4; mt++) {
        int row0 = bm + wm + mt * 16 + g;
        #pragma unroll
        for (int ntj = 0; ntj < NTJ; ntj++) {
            int col = bn + wn + ntj * 8 + t4 * 2;
            if (HOUT) {
                __half* Ch = (__half*)Cout;
                if (row0 < M && col + 1 < N)
                    *(__half2*)(Ch + (size_t)row0 * N + col) =
                        __floats2half2_rn(c[mt][ntj][0], c[mt][ntj][1]);
                if (row0 + 8 < M && col + 1 < N)
                    *(__half2*)(Ch + (size_t)(row0 + 8) * N + col) =
                        __floats2half2_rn(c[mt][ntj][2], c[mt][ntj][3]);
            } else {
                float* Cf = (float*)Cout;
                if (row0 < M && col + 1 < N) {
                    Cf[(size_t)row0 * N + col]     = c[mt][ntj][0];
                    Cf[(size_t)row0 * N + col + 1] = c[mt][ntj][1];
                }
                if (row0 + 8 < M && col + 1 < N) {
                    Cf[(size_t)(row0 + 8) * N + col]     = c[mt][ntj][2];
                    Cf[(size_t)(row0 + 8) * N + col + 1] = c[mt][ntj][3];
                }
            }
        }
    }

    // ---- fused attention-coefficient partials ----
    int head = (bn + wn) >> 6;
    if (head < heads) {
        float asac[4][2] = {}, adac[4][2] = {};
        #pragma unroll
        for (int mt = 0; mt < 4; mt++)
            #pragma unroll
            for (int ntj = 0; ntj < NTJ; ntj++) {
                int colb = bn + wn + ntj * 8 + t4 * 2;
                if (colb + 1 < N) {
                    float s0 = avs[colb], s1 = avs[colb + 1];
                    float d0 = avd[colb], d1 = avd[colb + 1];
                    asac[mt][0] += c[mt][ntj][0] * s0 + c[mt][ntj][1] * s1;
                    adac[mt][0] += c[mt][ntj][0] * d0 + c[mt][ntj][1] * d1;
                    asac[mt][1] += c[mt][ntj][2] * s0 + c[mt][ntj][3] * s1;
                    adac[mt][1] += c[mt][ntj][2] * d0 + c[mt][ntj][3] * d1;
                }
            }
        #pragma unroll
        for (int mt = 0; mt < 4; mt++)
            #pragma unroll
            for (int hf = 0; hf < 2; hf++) {
                float v = asac[mt][hf];
                float w = adac[mt][hf];
                v += __shfl_xor_sync(0xFFFFFFFFu, v, 1);
                v += __shfl_xor_sync(0xFFFFFFFFu, v, 2);
                w += __shfl_xor_sync(0xFFFFFFFFu, w, 1);
                w += __shfl_xor_sync(0xFFFFFFFFu, w, 2);
                int row = bm + wm + mt * 16 + g + hf * 8;
                if (t4 == 0 && row < M) {
                    atomicAdd(&as_out[row * heads + head], v);
                    atomicAdd(&ad_out[row * heads + head], w);
                }
            }
    }
}

// ---------------- softmax layer 1: warp per dst node, 4 heads ----------------
__global__ __launch_bounds__(256) void k_softmax1()
{
    int w = (blockIdx.x * blockDim.x + threadIdx.x) >> 5;
    int lane = threadIdx.x & 31;
    if (w >= NN) return;
    int beg = g_rowptr[w], end = g_rowptr[w + 1];
    const float4* as4 = (const float4*)g_as1;
    float4 adv = ((const float4*)g_ad1)[w];
    float4 mx = make_float4(-1e30f, -1e30f, -1e30f, -1e30f);
    for (int i = beg + lane; i < end; i += 32) {
        float4 e = as4[g_srcidx[i]];
        e.x += adv.x; e.y += adv.y; e.z += adv.z; e.w += adv.w;
        e.x = (e.x > 0.f) ? e.x : NEG_SLOPE * e.x;
        e.y = (e.y > 0.f) ? e.y : NEG_SLOPE * e.y;
        e.z = (e.z > 0.f) ? e.z : NEG_SLOPE * e.z;
        e.w = (e.w > 0.f) ? e.w : NEG_SLOPE * e.w;
        g_alpha1[i] = e;
        mx.x = fmaxf(mx.x, e.x); mx.y = fmaxf(mx.y, e.y);
        mx.z = fmaxf(mx.z, e.z); mx.w = fmaxf(mx.w, e.w);
    }
    #pragma unroll
    for (int o = 16; o > 0; o >>= 1) {
        mx.x = fmaxf(mx.x, __shfl_xor_sync(0xFFFFFFFFu, mx.x, o));
        mx.y = fmaxf(mx.y, __shfl_xor_sync(0xFFFFFFFFu, mx.y, o));
        mx.z = fmaxf(mx.z, __shfl_xor_sync(0xFFFFFFFFu, mx.z, o));
        mx.w = fmaxf(mx.w, __shfl_xor_sync(0xFFFFFFFFu, mx.w, o));
    }
    float4 sum = make_float4(0.f, 0.f, 0.f, 0.f);
    for (int i = beg + lane; i < end; i += 32) {
        float4 e = g_alpha1[i];
        e.x = __expf(e.x - mx.x); e.y = __expf(e.y - mx.y);
        e.z = __expf(e.z - mx.z); e.w = __expf(e.w - mx.w);
        g_alpha1[i] = e;
        sum.x += e.x; sum.y += e.y; sum.z += e.z; sum.w += e.w;
    }
    #pragma unroll
    for (int o = 16; o > 0; o >>= 1) {
        sum.x += __shfl_xor_sync(0xFFFFFFFFu, sum.x, o);
        sum.y += __shfl_xor_sync(0xFFFFFFFFu, sum.y, o);
        sum.z += __shfl_xor_sync(0xFFFFFFFFu, sum.z, o);
        sum.w += __shfl_xor_sync(0xFFFFFFFFu, sum.w, o);
    }
    if (lane == 0)
        g_rd1[w] = make_float4(1.f / sum.x, 1.f / sum.y, 1.f / sum.z, 1.f / sum.w);
}

// ---------------- softmax layer 2 --------------------------------------------
__global__ __launch_bounds__(256) void k_softmax2()
{
    int w = (blockIdx.x * blockDim.x + threadIdx.x) >> 5;
    int lane = threadIdx.x & 31;
    if (w >= NN) return;
    int beg = g_rowptr[w], end = g_rowptr[w + 1];
    float adv = g_ad2[w];
    float mx = -1e30f;
    for (int i = beg + lane; i < end; i += 32) {
        float e = g_as2[g_srcidx[i]] + adv;
        e = (e > 0.f) ? e : NEG_SLOPE * e;
        g_alpha2[i] = e;
        mx = fmaxf(mx, e);
    }
    #pragma unroll
    for (int o = 16; o > 0; o >>= 1)
        mx = fmaxf(mx, __shfl_xor_sync(0xFFFFFFFFu, mx, o));
    float sum = 0.f;
    for (int i = beg + lane; i < end; i += 32) {
        float e = __expf(g_alpha2[i] - mx);
        g_alpha2[i] = e;
        sum += e;
    }
    #pragma unroll
    for (int o = 16; o > 0; o >>= 1)
        sum += __shfl_xor_sync(0xFFFFFFFFu, sum, o);
    if (lane == 0) g_rd2[w] = 1.f / sum;
}

// ---- aggregation layer 1: 64 threads per dst row, fp16 gathers, fp16 out ----
__global__ __launch_bounds__(256) void k_agg1(const float* __restrict__ b1)
{
    int row = blockIdx.x * 4 + (threadIdx.x >> 6);
    if (row >= NN) return;
    int q = threadIdx.x & 63;
    int head = q >> 4;
    int beg = g_rowptr[row], end = g_rowptr[row + 1];
    float4 rdv = g_rd1[row];
    float rd = (head == 0) ? rdv.x : (head == 1) ? rdv.y : (head == 2) ? rdv.z : rdv.w;
    float4 acc0 = make_float4(0.f, 0.f, 0.f, 0.f);
    float4 acc1 = make_float4(0.f, 0.f, 0.f, 0.f);
    int i = beg;
    for (; i + 2 <= end; i += 2) {
        int s0 = g_srcidx[i], s1 = g_srcidx[i + 1];
        float4 a40 = g_alpha1[i], a41 = g_alpha1[i + 1];
        float a0 = (head == 0) ? a40.x : (head == 1) ? a40.y : (head == 2) ? a40.z : a40.w;
        float a1 = (head == 0) ? a41.x : (head == 1) ? a41.y : (head == 2) ? a41.z : a41.w;
        const __half2* p0 = (const __half2*)(g_h1h + (size_t)s0 * HC1 + q * 4);
        const __half2* p1 = (const __half2*)(g_h1h + (size_t)s1 * HC1 + q * 4);
        float2 h0a = __half22float2(p0[0]), h0b = __half22float2(p0[1]);
        float2 h1a = __half22float2(p1[0]), h1b = __half22float2(p1[1]);
        acc0.x += a0 * h0a.x; acc0.y += a0 * h0a.y; acc0.z += a0 * h0b.x; acc0.w += a0 * h0b.y;
        acc1.x += a1 * h1a.x; acc1.y += a1 * h1a.y; acc1.z += a1 * h1b.x; acc1.w += a1 * h1b.y;
    }
    if (i < end) {
        int s0 = g_srcidx[i];
        float4 a40 = g_alpha1[i];
        float a0 = (head == 0) ? a40.x : (head == 1) ? a40.y : (head == 2) ? a40.z : a40.w;
        const __half2* p0 = (const __half2*)(g_h1h + (size_t)s0 * HC1 + q * 4);
        float2 h0a = __half22float2(p0[0]), h0b = __half22float2(p0[1]);
        acc0.x += a0 * h0a.x; acc0.y += a0 * h0a.y; acc0.z += a0 * h0b.x; acc0.w += a0 * h0b.y;
    }
    float4 acc = make_float4((acc0.x + acc1.x) * rd, (acc0.y + acc1.y) * rd,
                             (acc0.z + acc1.z) * rd, (acc0.w + acc1.w) * rd);
    float4 bb = *(const float4*)(b1 + q * 4);
    acc.x += bb.x; acc.y += bb.y; acc.z += bb.z; acc.w += bb.w;
    acc.x = (acc.x > 0.f) ? acc.x : expm1f(acc.x);
    acc.y = (acc.y > 0.f) ? acc.y : expm1f(acc.y);
    acc.z = (acc.z > 0.f) ? acc.z : expm1f(acc.z);
    acc.w = (acc.w > 0.f) ? acc.w : expm1f(acc.w);
    __half2* xp = (__half2*)(g_x2h + (size_t)row * HC1 + q * 4);
    xp[0] = __floats2half2_rn(acc.x, acc.y);
    xp[1] = __floats2half2_rn(acc.z, acc.w);
}

// ---- aggregation layer 2: 16 threads per dst row, fp16 gathers --------------
__global__ __launch_bounds__(256) void k_agg2(const float* __restrict__ b2,
                                              float* __restrict__ out)
{
    int row = blockIdx.x * 16 + (threadIdx.x >> 4);
    if (row >= NN) return;
    int q = threadIdx.x & 15;
    int beg = g_rowptr[row], end = g_rowptr[row + 1];
    float rd = g_rd2[row];
    float4 acc0 = make_float4(0.f, 0.f, 0.f, 0.f);
    float4 acc1 = make_float4(0.f, 0.f, 0.f, 0.f);
    int i = beg;
    for (; i + 2 <= end; i += 2) {
        int s0 = g_srcidx[i], s1 = g_srcidx[i + 1];
        float a0 = g_alpha2[i], a1 = g_alpha2[i + 1];
        const __half2* p0 = (const __half2*)(g_h2h + (size_t)s0 * OC + q * 4);
        const __half2* p1 = (const __half2*)(g_h2h + (size_t)s1 * OC + q * 4);
        float2 h0a = __half22float2(p0[0]), h0b = __half22float2(p0[1]);
        float2 h1a = __half22float2(p1[0]), h1b = __half22float2(p1[1]);
        acc0.x += a0 * h0a.x; acc0.y += a0 * h0a.y; acc0.z += a0 * h0b.x; acc0.w += a0 * h0b.y;
        acc1.x += a1 * h1a.x; acc1.y += a1 * h1a.y; acc1.z += a1 * h1b.x; acc1.w += a1 * h1b.y;
    }
    if (i < end) {
        int s0 = g_srcidx[i];
        float a0 = g_alpha2[i];
        const __half2* p0 = (const __half2*)(g_h2h + (size_t)s0 * OC + q * 4);
        float2 h0a = __half22float2(p0[0]), h0b = __half22float2(p0[1]);
        acc0.x += a0 * h0a.x; acc0.y += a0 * h0a.y; acc0.z += a0 * h0b.x; acc0.w += a0 * h0b.y;
    }
    float4 bb = *(const float4*)(b2 + q * 4);
    float4 acc = make_float4((acc0.x + acc1.x) * rd + bb.x, (acc0.y + acc1.y) * rd + bb.y,
                             (acc0.z + acc1.z) * rd + bb.z, (acc0.w + acc1.w) * rd + bb.w);
    *(float4*)(out + (size_t)row * OC + q * 4) = acc;
}

// =============================================================================
extern "C" void kernel_launch(void* const* d_in, const int* in_sizes, int n_in,
                              void* d_out, int out_size)
{
    const float* x     = (const float*)d_in[0];
    const int*   ei    = (const int*)d_in[1];
    const float* W1    = (const float*)d_in[2];
    const float* a_s1  = (const float*)d_in[3];
    const float* a_d1  = (const float*)d_in[4];
    const float* b1    = (const float*)d_in[5];
    const float* W2    = (const float*)d_in[6];
    const float* a_s2  = (const float*)d_in[7];
    const float* a_d2  = (const float*)d_in[8];
    const float* b2    = (const float*)d_in[9];
    float*       out   = (float*)d_out;

    __half *h1h, *x2h, *h2h;
    float *as1, *ad1, *as2, *ad2;
    cudaGetSymbolAddress((void**)&h1h, g_h1h);
    cudaGetSymbolAddress((void**)&x2h, g_x2h);
    cudaGetSymbolAddress((void**)&h2h, g_h2h);
    cudaGetSymbolAddress((void**)&as1, g_as1);
    cudaGetSymbolAddress((void**)&ad1, g_ad1);
    cudaGetSymbolAddress((void**)&as2, g_as2);
    cudaGetSymbolAddress((void**)&ad2, g_ad2);

    const int SMEM_L1 = (2 * TBM * TSH + 2 * 128 * TSH) * 2;   // NTJ=4
    const int SMEM_L2 = (2 * TBM * TSH + 2 * 64  * TSH) * 2;   // NTJ=2
    cudaFuncSetAttribute((const void*)k_h16gemm<4, false, true>,
                         cudaFuncAttributeMaxDynamicSharedMemorySize, SMEM_L1);
    cudaFuncSetAttribute((const void*)k_h16gemm<2, true, true>,
                         cudaFuncAttributeMaxDynamicSharedMemorySize, SMEM_L2);

    cudaStream_t s2;
    cudaStreamCreate(&s2);
    cudaEvent_t evFork, evJoin;
    cudaEventCreateWithFlags(&evFork, cudaEventDisableTiming);
    cudaEventCreateWithFlags(&evJoin, cudaEventDisableTiming);

    // ---- fork: CSR build on s2, concurrent with GEMM1 ----
    cudaEventRecord(evFork, 0);
    cudaStreamWaitEvent(s2, evFork, 0);
    k_zero_deg<<<(NN + 255) / 256, 256, 0, s2>>>();
    k_count<<<(EP + 255) / 256, 256, 0, s2>>>(ei);
    k_scan1<<<NTILES, SCAN_T, 0, s2>>>();
    k_scan3m<<<NTILES, SCAN_T, 0, s2>>>();
    k_scatter<<<(EP + 255) / 256, 256, 0, s2>>>(ei);
    cudaEventRecord(evJoin, s2);

    // ---- main stream: attn zero + GEMM1 (fp32 in, fp16 out) ----
    k_zero_attn<<<(NN + 255) / 256, 256>>>();
    {
        dim3 grid(HC1 / 128, (NN + TBM - 1) / TBM);
        k_h16gemm<4, false, true><<<grid, 256, SMEM_L1>>>(x, W1, h1h, NN, HC1, INC,
                                                          a_s1, a_d1, as1, ad1, H1);
    }

    // ---- join ----
    cudaStreamWaitEvent(0, evJoin, 0);
    k_softmax1<<<(NN * 32 + 255) / 256, 256>>>();
    k_agg1<<<(NN + 3) / 4, 256>>>(b1);

    // ---- layer 2 (fp16 in, fp16 out, 64-wide tile) ----
    {
        dim3 grid(OC / 64, (NN + TBM - 1) / TBM);
        k_h16gemm<2, true, true><<<grid, 256, SMEM_L2>>>(x2h, W2, h2h, NN, OC, HC1,
                                                         a_s2, a_d2, as2, ad2, 1);
    }
    k_softmax2<<<(NN * 32 + 255) / 256, 256>>>();
    k_agg2<<<(NN + 15) / 16, 256>>>(b2, out);
}

// round 16
// speedup vs baseline: 1.6460x; 1.0378x over previous
#include <cuda_runtime.h>
#include <cuda_fp16.h>
#include <math.h>

// ---------------- problem constants ----------------
#define NN    50000
#define EE    800000
#define EP    850000          // EE + NN self loops
#define INC   1024
#define H1    4
#define C1    64
#define HC1   256             // H1*C1
#define OC    64
#define NEG_SLOPE 0.2f

#define SCAN_T 512
#define NTILES ((NN + SCAN_T - 1) / SCAN_T)

// ---------------- scratch (device globals) ----------------
__device__ __half  g_h1h[(size_t)NN * HC1];   // layer1 features (agg path), fp16
__device__ __half  g_x2h[(size_t)NN * HC1];   // elu(agg1+b1), fp16 (GEMM2 A input)
__device__ float   g_as1[NN * H1];
__device__ float   g_ad1[NN * H1];
__device__ float4  g_alpha1[EP];              // per-edge exp values (4 heads), CSR order
__device__ float4  g_rd1[NN];                 // reciprocal softmax denominators

__device__ __half  g_h2h[(size_t)NN * OC];    // layer2 features, fp16
__device__ float   g_as2[NN];
__device__ float   g_ad2[NN];
__device__ float   g_alpha2[EP];
__device__ float   g_rd2[NN];

// CSR
__device__ int g_deg[NN];
__device__ int g_rowptr[NN + 1];
__device__ int g_cursor[NN];
__device__ int g_srcidx[EP];
__device__ int g_bsum[NTILES];

// ================= init + CSR construction =================
__global__ void k_zero_attn() {
    int i = blockIdx.x * blockDim.x + threadIdx.x;
    if (i >= NN) return;
    g_as2[i] = 0.f; g_ad2[i] = 0.f;
    float4 z = make_float4(0.f, 0.f, 0.f, 0.f);
    ((float4*)g_as1)[i] = z;
    ((float4*)g_ad1)[i] = z;
}
__global__ void k_zero_deg() {
    int i = blockIdx.x * blockDim.x + threadIdx.x;
    if (i < NN) g_deg[i] = 0;
}
__global__ void k_count(const int* __restrict__ ei) {
    int e = blockIdx.x * blockDim.x + threadIdx.x;
    if (e >= EP) return;
    int dn = (e < EE) ? ei[EE + e] : (e - EE);
    atomicAdd(&g_deg[dn], 1);
}
__global__ __launch_bounds__(SCAN_T) void k_scan1() {
    __shared__ int s[SCAN_T];
    int tid = threadIdx.x;
    int i = blockIdx.x * SCAN_T + tid;
    int v = (i < NN) ? g_deg[i] : 0;
    s[tid] = v;
    __syncthreads();
    #pragma unroll
    for (int off = 1; off < SCAN_T; off <<= 1) {
        int t = (tid >= off) ? s[tid - off] : 0;
        __syncthreads();
        s[tid] += t;
        __syncthreads();
    }
    if (i < NN) g_rowptr[i + 1] = s[tid];
    if (tid == SCAN_T - 1) g_bsum[blockIdx.x] = s[tid];
}
__global__ __launch_bounds__(SCAN_T) void k_scan3m() {
    __shared__ int off_s;
    int blk = blockIdx.x;
    if (threadIdx.x < 32) {
        int lane = threadIdx.x;
        int s = 0;
        for (int j = lane; j < blk; j += 32) s += g_bsum[j];
        #pragma unroll
        for (int o = 16; o > 0; o >>= 1) s += __shfl_xor_sync(0xFFFFFFFFu, s, o);
        if (lane == 0) off_s = s;
    }
    __syncthreads();
    int off = off_s;
    int i = blk * SCAN_T + threadIdx.x;
    if (i < NN) {
        int r = g_rowptr[i + 1] + off;
        g_rowptr[i + 1] = r;
        g_cursor[i] = r - g_deg[i];
    }
    if (i == 0) g_rowptr[0] = 0;
}
__global__ void k_scatter(const int* __restrict__ ei) {
    int e = blockIdx.x * blockDim.x + threadIdx.x;
    if (e >= EP) return;
    int s, dn;
    if (e < EE) { s = ei[e]; dn = ei[EE + e]; }
    else        { s = e - EE; dn = s; }
    int pos = atomicAdd(&g_cursor[dn], 1);
    g_srcidx[pos] = s;
}

// ============= FP16 GEMM (m16n8k16, ldmatrix) + fused attention epilogue =====
#define TBM 128
#define TBK 32
#define TSH 40

__device__ __forceinline__ void ldsm_x4(unsigned& r0, unsigned& r1,
                                        unsigned& r2, unsigned& r3, unsigned addr) {
    asm volatile("ldmatrix.sync.aligned.m8n8.x4.shared.b16 {%0,%1,%2,%3}, [%4];"
                 : "=r"(r0), "=r"(r1), "=r"(r2), "=r"(r3) : "r"(addr));
}
__device__ __forceinline__ void ldsm_x2(unsigned& r0, unsigned& r1, unsigned addr) {
    asm volatile("ldmatrix.sync.aligned.m8n8.x2.shared.b16 {%0,%1}, [%2];"
                 : "=r"(r0), "=r"(r1) : "r"(addr));
}

template<int NTJ, bool HIN, bool HOUT>
__global__ __launch_bounds__(256, 2) void k_h16gemm(
    const void* __restrict__ Ain, const float* __restrict__ B,
    void* __restrict__ Cout, int M, int N, int K,
    const float* __restrict__ avs, const float* __restrict__ avd,
    float* __restrict__ as_out, float* __restrict__ ad_out, int heads)
{
    const int TBNE = 32 * NTJ;              // 128 or 64
    extern __shared__ __half smem_h[];
    __half* Abase = smem_h;                         // [2][TBM][TSH]
    __half* Bbase = smem_h + 2 * TBM * TSH;         // [2][TBNE][TSH]

    int tid = threadIdx.x;
    int bm = blockIdx.y * TBM, bn = blockIdx.x * (4 * 8 * NTJ);
    int wid = tid >> 5, lane = tid & 31;
    int wm = (wid >> 2) * 64;
    int wn = (wid & 3) * (8 * NTJ);
    int g  = lane >> 2;
    int t4 = lane & 3;

    int r0 = tid >> 3;
    int c4 = (tid & 7) * 4;

    // ldmatrix per-lane address components
    int lane7 = lane & 7;
    int seg   = lane >> 3;                  // 0..3
    unsigned sA = (unsigned)__cvta_generic_to_shared(Abase);
    unsigned sB = (unsigned)__cvta_generic_to_shared(Bbase);
    // A: seg0 rows+0/k+0, seg1 rows+8/k+0, seg2 rows+0/k+8, seg3 rows+8/k+8
    unsigned aAddr[4];
    #pragma unroll
    for (int mt = 0; mt < 4; mt++) {
        int row = wm + mt * 16 + (seg & 1) * 8 + lane7;
        aAddr[mt] = sA + (unsigned)((row * TSH + (seg >> 1) * 8) * 2);
    }
    // B: lanes 0-7 -> k+0, lanes 8-15 -> k+8 (upper lanes ignored by .x2)
    unsigned bAddr[NTJ];
    #pragma unroll
    for (int ntj = 0; ntj < NTJ; ntj++) {
        int col = wn + ntj * 8 + lane7;
        bAddr[ntj] = sB + (unsigned)((col * TSH + (seg & 1) * 8) * 2);
    }
    const unsigned ABUF = (unsigned)(TBM * TSH * 2);
    const unsigned BBUF = (unsigned)(TBNE * TSH * 2);

    float c[4][NTJ][4];
    #pragma unroll
    for (int i = 0; i < 4; i++)
        #pragma unroll
        for (int j = 0; j < NTJ; j++)
            #pragma unroll
            for (int r = 0; r < 4; r++) c[i][j][r] = 0.f;

    const float4 zero4 = make_float4(0.f, 0.f, 0.f, 0.f);
    const uint2  zero2 = make_uint2(0u, 0u);
    float4 pa[4], pb[NTJ];
    uint2  pah[4];
    int nt = K / TBK;

    // ---- prologue fetch ----
    #pragma unroll
    for (int i = 0; i < 4; i++) {
        int ar = bm + r0 + 32 * i;
        if (HIN) {
            const __half* Ah = (const __half*)Ain;
            pah[i] = (ar < M) ? *(const uint2*)(Ah + (size_t)ar * K + c4) : zero2;
        } else {
            const float* Af = (const float*)Ain;
            pa[i] = (ar < M) ? *(const float4*)(Af + (size_t)ar * K + c4) : zero4;
        }
    }
    #pragma unroll
    for (int i = 0; i < NTJ; i++) {
        int br = bn + r0 + 32 * i;
        pb[i] = (br < N) ? *(const float4*)(B + (size_t)br * K + c4) : zero4;
    }
    {
        #pragma unroll
        for (int i = 0; i < 4; i++) {
            __half* ap = Abase + (r0 + 32 * i) * TSH + c4;
            if (HIN) {
                *(uint2*)ap = pah[i];
            } else {
                ((__half2*)ap)[0] = __floats2half2_rn(pa[i].x, pa[i].y);
                ((__half2*)ap)[1] = __floats2half2_rn(pa[i].z, pa[i].w);
            }
        }
        #pragma unroll
        for (int i = 0; i < NTJ; i++) {
            __half2* bp = (__half2*)(Bbase + (r0 + 32 * i) * TSH + c4);
            bp[0] = __floats2half2_rn(pb[i].x, pb[i].y);
            bp[1] = __floats2half2_rn(pb[i].z, pb[i].w);
        }
    }
    __syncthreads();

    for (int t = 0; t < nt; t++) {
        int cur = t & 1;
        bool more = (t + 1 < nt);
        if (more) {
            int k0 = (t + 1) * TBK;
            #pragma unroll
            for (int i = 0; i < 4; i++) {
                int ar = bm + r0 + 32 * i;
                if (HIN) {
                    const __half* Ah = (const __half*)Ain;
                    pah[i] = (ar < M) ? *(const uint2*)(Ah + (size_t)ar * K + k0 + c4) : zero2;
                } else {
                    const float* Af = (const float*)Ain;
                    pa[i] = (ar < M) ? *(const float4*)(Af + (size_t)ar * K + k0 + c4) : zero4;
                }
            }
            #pragma unroll
            for (int i = 0; i < NTJ; i++) {
                int br = bn + r0 + 32 * i;
                pb[i] = (br < N) ? *(const float4*)(B + (size_t)br * K + k0 + c4) : zero4;
            }
        }
        unsigned aOff = cur * ABUF;
        unsigned bOff = cur * BBUF;
        #pragma unroll
        for (int kc = 0; kc < 2; kc++) {
            unsigned kb = kc * 32;            // 16 halves = 32 bytes
            unsigned af[4][4], bf[NTJ][2];
            #pragma unroll
            for (int mt = 0; mt < 4; mt++)
                ldsm_x4(af[mt][0], af[mt][1], af[mt][2], af[mt][3],
                        aAddr[mt] + aOff + kb);
            #pragma unroll
            for (int ntj = 0; ntj < NTJ; ntj++)
                ldsm_x2(bf[ntj][0], bf[ntj][1], bAddr[ntj] + bOff + kb);
            #pragma unroll
            for (int mt = 0; mt < 4; mt++)
                #pragma unroll
                for (int ntj = 0; ntj < NTJ; ntj++) {
                    asm volatile(
                        "mma.sync.aligned.m16n8k16.row.col.f32.f16.f16.f32 "
                        "{%0,%1,%2,%3}, {%4,%5,%6,%7}, {%8,%9}, {%0,%1,%2,%3};"
                        : "+f"(c[mt][ntj][0]), "+f"(c[mt][ntj][1]),
                          "+f"(c[mt][ntj][2]), "+f"(c[mt][ntj][3])
                        : "r"(af[mt][0]), "r"(af[mt][1]), "r"(af[mt][2]), "r"(af[mt][3]),
                          "r"(bf[ntj][0]), "r"(bf[ntj][1]));
                }
        }
        if (more) {
            int nx = cur ^ 1;
            __half* Aw = Abase + nx * TBM * TSH;
            __half* Bw = Bbase + nx * TBNE * TSH;
            #pragma unroll
            for (int i = 0; i < 4; i++) {
                __half* ap = Aw + (r0 + 32 * i) * TSH + c4;
                if (HIN) {
                    *(uint2*)ap = pah[i];
                } else {
                    ((__half2*)ap)[0] = __floats2half2_rn(pa[i].x, pa[i].y);
                    ((__half2*)ap)[1] = __floats2half2_rn(pa[i].z, pa[i].w);
                }
            }
            #pragma unroll
            for (int i = 0; i < NTJ; i++) {
                __half2* bp = (__half2*)(Bw + (r0 + 32 * i) * TSH + c4);
                bp[0] = __floats2half2_rn(pb[i].x, pb[i].y);
                bp[1] = __floats2half2_rn(pb[i].z, pb[i].w);
            }
            __syncthreads();
        }
    }

    // ---- C store ----
    #pragma unroll
    for (int mt = 0; mt < 4; mt++) {
        int row0 = bm + wm + mt * 16 + g;
        #pragma unroll
        for (int ntj = 0; ntj < NTJ; ntj++) {
            int col = bn + wn + ntj * 8 + t4 * 2;
            if (HOUT) {
                __half* Ch = (__half*)Cout;
                if (row0 < M && col + 1 < N)
                    *(__half2*)(Ch + (size_t)row0 * N + col) =
                        __floats2half2_rn(c[mt][ntj][0], c[mt][ntj][1]);
                if (row0 + 8 < M && col + 1 < N)
                    *(__half2*)(Ch + (size_t)(row0 + 8) * N + col) =
                        __floats2half2_rn(c[mt][ntj][2], c[mt][ntj][3]);
            } else {
                float* Cf = (float*)Cout;
                if (row0 < M && col + 1 < N) {
                    Cf[(size_t)row0 * N + col]     = c[mt][ntj][0];
                    Cf[(size_t)row0 * N + col + 1] = c[mt][ntj][1];
                }
                if (row0 + 8 < M && col + 1 < N) {
                    Cf[(size_t)(row0 + 8) * N + col]     = c[mt][ntj][2];
                    Cf[(size_t)(row0 + 8) * N + col + 1] = c[mt][ntj][3];
                }
            }
        }
    }

    // ---- fused attention-coefficient partials ----
    int head = (bn + wn) >> 6;
    if (head < heads) {
        float asac[4][2] = {}, adac[4][2] = {};
        #pragma unroll
        for (int mt = 0; mt < 4; mt++)
            #pragma unroll
            for (int ntj = 0; ntj < NTJ; ntj++) {
                int colb = bn + wn + ntj * 8 + t4 * 2;
                if (colb + 1 < N) {
                    float s0 = avs[colb], s1 = avs[colb + 1];
                    float d0 = avd[colb], d1 = avd[colb + 1];
                    asac[mt][0] += c[mt][ntj][0] * s0 + c[mt][ntj][1] * s1;
                    adac[mt][0] += c[mt][ntj][0] * d0 + c[mt][ntj][1] * d1;
                    asac[mt][1] += c[mt][ntj][2] * s0 + c[mt][ntj][3] * s1;
                    adac[mt][1] += c[mt][ntj][2] * d0 + c[mt][ntj][3] * d1;
                }
            }
        #pragma unroll
        for (int mt = 0; mt < 4; mt++)
            #pragma unroll
            for (int hf = 0; hf < 2; hf++) {
                float v = asac[mt][hf];
                float w = adac[mt][hf];
                v += __shfl_xor_sync(0xFFFFFFFFu, v, 1);
                v += __shfl_xor_sync(0xFFFFFFFFu, v, 2);
                w += __shfl_xor_sync(0xFFFFFFFFu, w, 1);
                w += __shfl_xor_sync(0xFFFFFFFFu, w, 2);
                int row = bm + wm + mt * 16 + g + hf * 8;
                if (t4 == 0 && row < M) {
                    atomicAdd(&as_out[row * heads + head], v);
                    atomicAdd(&ad_out[row * heads + head], w);
                }
            }
    }
}

// ---------------- softmax layer 1: warp per dst node, 4 heads ----------------
__global__ __launch_bounds__(256) void k_softmax1()
{
    int w = (blockIdx.x * blockDim.x + threadIdx.x) >> 5;
    int lane = threadIdx.x & 31;
    if (w >= NN) return;
    int beg = g_rowptr[w], end = g_rowptr[w + 1];
    const float4* as4 = (const float4*)g_as1;
    float4 adv = ((const float4*)g_ad1)[w];
    float4 mx = make_float4(-1e30f, -1e30f, -1e30f, -1e30f);
    for (int i = beg + lane; i < end; i += 32) {
        float4 e = as4[g_srcidx[i]];
        e.x += adv.x; e.y += adv.y; e.z += adv.z; e.w += adv.w;
        e.x = (e.x > 0.f) ? e.x : NEG_SLOPE * e.x;
        e.y = (e.y > 0.f) ? e.y : NEG_SLOPE * e.y;
        e.z = (e.z > 0.f) ? e.z : NEG_SLOPE * e.z;
        e.w = (e.w > 0.f) ? e.w : NEG_SLOPE * e.w;
        g_alpha1[i] = e;
        mx.x = fmaxf(mx.x, e.x); mx.y = fmaxf(mx.y, e.y);
        mx.z = fmaxf(mx.z, e.z); mx.w = fmaxf(mx.w, e.w);
    }
    #pragma unroll
    for (int o = 16; o > 0; o >>= 1) {
        mx.x = fmaxf(mx.x, __shfl_xor_sync(0xFFFFFFFFu, mx.x, o));
        mx.y = fmaxf(mx.y, __shfl_xor_sync(0xFFFFFFFFu, mx.y, o));
        mx.z = fmaxf(mx.z, __shfl_xor_sync(0xFFFFFFFFu, mx.z, o));
        mx.w = fmaxf(mx.w, __shfl_xor_sync(0xFFFFFFFFu, mx.w, o));
    }
    float4 sum = make_float4(0.f, 0.f, 0.f, 0.f);
    for (int i = beg + lane; i < end; i += 32) {
        float4 e = g_alpha1[i];
        e.x = __expf(e.x - mx.x); e.y = __expf(e.y - mx.y);
        e.z = __expf(e.z - mx.z); e.w = __expf(e.w - mx.w);
        g_alpha1[i] = e;
        sum.x += e.x; sum.y += e.y; sum.z += e.z; sum.w += e.w;
    }
    #pragma unroll
    for (int o = 16; o > 0; o >>= 1) {
        sum.x += __shfl_xor_sync(0xFFFFFFFFu, sum.x, o);
        sum.y += __shfl_xor_sync(0xFFFFFFFFu, sum.y, o);
        sum.z += __shfl_xor_sync(0xFFFFFFFFu, sum.z, o);
        sum.w += __shfl_xor_sync(0xFFFFFFFFu, sum.w, o);
    }
    if (lane == 0)
        g_rd1[w] = make_float4(1.f / sum.x, 1.f / sum.y, 1.f / sum.z, 1.f / sum.w);
}

// ---------------- softmax layer 2 --------------------------------------------
__global__ __launch_bounds__(256) void k_softmax2()
{
    int w = (blockIdx.x * blockDim.x + threadIdx.x) >> 5;
    int lane = threadIdx.x & 31;
    if (w >= NN) return;
    int beg = g_rowptr[w], end = g_rowptr[w + 1];
    float adv = g_ad2[w];
    float mx = -1e30f;
    for (int i = beg + lane; i < end; i += 32) {
        float e = g_as2[g_srcidx[i]] + adv;
        e = (e > 0.f) ? e : NEG_SLOPE * e;
        g_alpha2[i] = e;
        mx = fmaxf(mx, e);
    }
    #pragma unroll
    for (int o = 16; o > 0; o >>= 1)
        mx = fmaxf(mx, __shfl_xor_sync(0xFFFFFFFFu, mx, o));
    float sum = 0.f;
    for (int i = beg + lane; i < end; i += 32) {
        float e = __expf(g_alpha2[i] - mx);
        g_alpha2[i] = e;
        sum += e;
    }
    #pragma unroll
    for (int o = 16; o > 0; o >>= 1)
        sum += __shfl_xor_sync(0xFFFFFFFFu, sum, o);
    if (lane == 0) g_rd2[w] = 1.f / sum;
}

// ---- aggregation layer 1: 64 threads per dst row, fp16 gathers, fp16 out ----
__global__ __launch_bounds__(256) void k_agg1(const float* __restrict__ b1)
{
    int row = blockIdx.x * 4 + (threadIdx.x >> 6);
    if (row >= NN) return;
    int q = threadIdx.x & 63;
    int head = q >> 4;
    int beg = g_rowptr[row], end = g_rowptr[row + 1];
    float4 rdv = g_rd1[row];
    float rd = (head == 0) ? rdv.x : (head == 1) ? rdv.y : (head == 2) ? rdv.z : rdv.w;
    float4 acc0 = make_float4(0.f, 0.f, 0.f, 0.f);
    float4 acc1 = make_float4(0.f, 0.f, 0.f, 0.f);
    int i = beg;
    for (; i + 2 <= end; i += 2) {
        int s0 = g_srcidx[i], s1 = g_srcidx[i + 1];
        float4 a40 = g_alpha1[i], a41 = g_alpha1[i + 1];
        float a0 = (head == 0) ? a40.x : (head == 1) ? a40.y : (head == 2) ? a40.z : a40.w;
        float a1 = (head == 0) ? a41.x : (head == 1) ? a41.y : (head == 2) ? a41.z : a41.w;
        const __half2* p0 = (const __half2*)(g_h1h + (size_t)s0 * HC1 + q * 4);
        const __half2* p1 = (const __half2*)(g_h1h + (size_t)s1 * HC1 + q * 4);
        float2 h0a = __half22float2(p0[0]), h0b = __half22float2(p0[1]);
        float2 h1a = __half22float2(p1[0]), h1b = __half22float2(p1[1]);
        acc0.x += a0 * h0a.x; acc0.y += a0 * h0a.y; acc0.z += a0 * h0b.x; acc0.w += a0 * h0b.y;
        acc1.x += a1 * h1a.x; acc1.y += a1 * h1a.y; acc1.z += a1 * h1b.x; acc1.w += a1 * h1b.y;
    }
    if (i < end) {
        int s0 = g_srcidx[i];
        float4 a40 = g_alpha1[i];
        float a0 = (head == 0) ? a40.x : (head == 1) ? a40.y : (head == 2) ? a40.z : a40.w;
        const __half2* p0 = (const __half2*)(g_h1h + (size_t)s0 * HC1 + q * 4);
        float2 h0a = __half22float2(p0[0]), h0b = __half22float2(p0[1]);
        acc0.x += a0 * h0a.x; acc0.y += a0 * h0a.y; acc0.z += a0 * h0b.x; acc0.w += a0 * h0b.y;
    }
    float4 acc = make_float4((acc0.x + acc1.x) * rd, (acc0.y + acc1.y) * rd,
                             (acc0.z + acc1.z) * rd, (acc0.w + acc1.w) * rd);
    float4 bb = *(const float4*)(b1 + q * 4);
    acc.x += bb.x; acc.y += bb.y; acc.z += bb.z; acc.w += bb.w;
    acc.x = (acc.x > 0.f) ? acc.x : expm1f(acc.x);
    acc.y = (acc.y > 0.f) ? acc.y : expm1f(acc.y);
    acc.z = (acc.z > 0.f) ? acc.z : expm1f(acc.z);
    acc.w = (acc.w > 0.f) ? acc.w : expm1f(acc.w);
    __half2* xp = (__half2*)(g_x2h + (size_t)row * HC1 + q * 4);
    xp[0] = __floats2half2_rn(acc.x, acc.y);
    xp[1] = __floats2half2_rn(acc.z, acc.w);
}

// ---- aggregation layer 2: 16 threads per dst row, fp16 gathers --------------
__global__ __launch_bounds__(256) void k_agg2(const float* __restrict__ b2,
                                              float* __restrict__ out)
{
    int row = blockIdx.x * 16 + (threadIdx.x >> 4);
    if (row >= NN) return;
    int q = threadIdx.x & 15;
    int beg = g_rowptr[row], end = g_rowptr[row + 1];
    float rd = g_rd2[row];
    float4 acc0 = make_float4(0.f, 0.f, 0.f, 0.f);
    float4 acc1 = make_float4(0.f, 0.f, 0.f, 0.f);
    int i = beg;
    for (; i + 2 <= end; i += 2) {
        int s0 = g_srcidx[i], s1 = g_srcidx[i + 1];
        float a0 = g_alpha2[i], a1 = g_alpha2[i + 1];
        const __half2* p0 = (const __half2*)(g_h2h + (size_t)s0 * OC + q * 4);
        const __half2* p1 = (const __half2*)(g_h2h + (size_t)s1 * OC + q * 4);
        float2 h0a = __half22float2(p0[0]), h0b = __half22float2(p0[1]);
        float2 h1a = __half22float2(p1[0]), h1b = __half22float2(p1[1]);
        acc0.x += a0 * h0a.x; acc0.y += a0 * h0a.y; acc0.z += a0 * h0b.x; acc0.w += a0 * h0b.y;
        acc1.x += a1 * h1a.x; acc1.y += a1 * h1a.y; acc1.z += a1 * h1b.x; acc1.w += a1 * h1b.y;
    }
    if (i < end) {
        int s0 = g_srcidx[i];
        float a0 = g_alpha2[i];
        const __half2* p0 = (const __half2*)(g_h2h + (size_t)s0 * OC + q * 4);
        float2 h0a = __half22float2(p0[0]), h0b = __half22float2(p0[1]);
        acc0.x += a0 * h0a.x; acc0.y += a0 * h0a.y; acc0.z += a0 * h0b.x; acc0.w += a0 * h0b.y;
    }
    float4 bb = *(const float4*)(b2 + q * 4);
    float4 acc = make_float4((acc0.x + acc1.x) * rd + bb.x, (acc0.y + acc1.y) * rd + bb.y,
                             (acc0.z + acc1.z) * rd + bb.z, (acc0.w + acc1.w) * rd + bb.w);
    *(float4*)(out + (size_t)row * OC + q * 4) = acc;
}

// =============================================================================
extern "C" void kernel_launch(void* const* d_in, const int* in_sizes, int n_in,
                              void* d_out, int out_size)
{
    const float* x     = (const float*)d_in[0];
    const int*   ei    = (const int*)d_in[1];
    const float* W1    = (const float*)d_in[2];
    const float* a_s1  = (const float*)d_in[3];
    const float* a_d1  = (const float*)d_in[4];
    const float* b1    = (const float*)d_in[5];
    const float* W2    = (const float*)d_in[6];
    const float* a_s2  = (const float*)d_in[7];
    const float* a_d2  = (const float*)d_in[8];
    const float* b2    = (const float*)d_in[9];
    float*       out   = (float*)d_out;

    __half *h1h, *x2h, *h2h;
    float *as1, *ad1, *as2, *ad2;
    cudaGetSymbolAddress((void**)&h1h, g_h1h);
    cudaGetSymbolAddress((void**)&x2h, g_x2h);
    cudaGetSymbolAddress((void**)&h2h, g_h2h);
    cudaGetSymbolAddress((void**)&as1, g_as1);
    cudaGetSymbolAddress((void**)&ad1, g_ad1);
    cudaGetSymbolAddress((void**)&as2, g_as2);
    cudaGetSymbolAddress((void**)&ad2, g_ad2);

    const int SMEM_L1 = (2 * TBM * TSH + 2 * 128 * TSH) * 2;   // NTJ=4
    const int SMEM_L2 = (2 * TBM * TSH + 2 * 64  * TSH) * 2;   // NTJ=2
    cudaFuncSetAttribute((const void*)k_h16gemm<4, false, true>,
                         cudaFuncAttributeMaxDynamicSharedMemorySize, SMEM_L1);
    cudaFuncSetAttribute((const void*)k_h16gemm<2, true, true>,
                         cudaFuncAttributeMaxDynamicSharedMemorySize, SMEM_L2);

    cudaStream_t s2;
    cudaStreamCreate(&s2);
    cudaEvent_t evFork, evJoin;
    cudaEventCreateWithFlags(&evFork, cudaEventDisableTiming);
    cudaEventCreateWithFlags(&evJoin, cudaEventDisableTiming);

    // ---- fork: CSR build on s2, concurrent with GEMM1 ----
    cudaEventRecord(evFork, 0);
    cudaStreamWaitEvent(s2, evFork, 0);
    k_zero_deg<<<(NN + 255) / 256, 256, 0, s2>>>();
    k_count<<<(EP + 255) / 256, 256, 0, s2>>>(ei);
    k_scan1<<<NTILES, SCAN_T, 0, s2>>>();
    k_scan3m<<<NTILES, SCAN_T, 0, s2>>>();
    k_scatter<<<(EP + 255) / 256, 256, 0, s2>>>(ei);
    cudaEventRecord(evJoin, s2);

    // ---- main stream: attn zero + GEMM1 (fp32 in, fp16 out) ----
    k_zero_attn<<<(NN + 255) / 256, 256>>>();
    {
        dim3 grid(HC1 / 128, (NN + TBM - 1) / TBM);
        k_h16gemm<4, false, true><<<grid, 256, SMEM_L1>>>(x, W1, h1h, NN, HC1, INC,
                                                          a_s1, a_d1, as1, ad1, H1);
    }

    // ---- join ----
    cudaStreamWaitEvent(0, evJoin, 0);
    k_softmax1<<<(NN * 32 + 255) / 256, 256>>>();
    k_agg1<<<(NN + 3) / 4, 256>>>(b1);

    // ---- layer 2 (fp16 in, fp16 out, 64-wide tile) ----
    {
        dim3 grid(OC / 64, (NN + TBM - 1) / TBM);
        k_h16gemm<2, true, true><<<grid, 256, SMEM_L2>>>(x2h, W2, h2h, NN, OC, HC1,
                                                         a_s2, a_d2, as2, ad2, 1);
    }
    k_softmax2<<<(NN * 32 + 255) / 256, 256>>>();
    k_agg2<<<(NN + 15) / 16, 256>>>(b2, out);
}

// round 17
// speedup vs baseline: 1.6577x; 1.0071x over previous
#include <cuda_runtime.h>
#include <cuda_fp16.h>
#include <math.h>

// ---------------- problem constants ----------------
#define NN    50000
#define EE    800000
#define EP    850000          // EE + NN self loops
#define INC   1024
#define H1    4
#define C1    64
#define HC1   256             // H1*C1
#define OC    64
#define NEG_SLOPE 0.2f

#define SCAN_T 512
#define NTILES ((NN + SCAN_T - 1) / SCAN_T)

// ---------------- scratch (device globals) ----------------
__device__ __half  g_h1h[(size_t)NN * HC1];   // layer1 features (agg path), fp16
__device__ __half  g_x2h[(size_t)NN * HC1];   // elu(agg1+b1), fp16 (GEMM2 A input)
__device__ float   g_as1[NN * H1];
__device__ float   g_ad1[NN * H1];
__device__ float4  g_alpha1[EP];              // per-edge exp values (4 heads), CSR order
__device__ float4  g_rd1[NN];                 // reciprocal softmax denominators

__device__ __half  g_h2h[(size_t)NN * OC];    // layer2 features, fp16
__device__ float   g_as2[NN];
__device__ float   g_ad2[NN];
__device__ float   g_alpha2[EP];
__device__ float   g_rd2[NN];

// CSR
__device__ int g_deg[NN];
__device__ int g_rowptr[NN + 1];
__device__ int g_cursor[NN];
__device__ int g_srcidx[EP];
__device__ int g_bsum[NTILES];

// ================= init + CSR construction =================
__global__ void k_zero_attn() {
    int i = blockIdx.x * blockDim.x + threadIdx.x;
    if (i >= NN) return;
    g_as2[i] = 0.f; g_ad2[i] = 0.f;
    float4 z = make_float4(0.f, 0.f, 0.f, 0.f);
    ((float4*)g_as1)[i] = z;
    ((float4*)g_ad1)[i] = z;
}
__global__ void k_zero_deg() {
    int i = blockIdx.x * blockDim.x + threadIdx.x;
    if (i < NN) g_deg[i] = 0;
}
__global__ void k_count(const int* __restrict__ ei) {
    int e = blockIdx.x * blockDim.x + threadIdx.x;
    if (e >= EP) return;
    int dn = (e < EE) ? ei[EE + e] : (e - EE);
    atomicAdd(&g_deg[dn], 1);
}
__global__ __launch_bounds__(SCAN_T) void k_scan1() {
    __shared__ int s[SCAN_T];
    int tid = threadIdx.x;
    int i = blockIdx.x * SCAN_T + tid;
    int v = (i < NN) ? g_deg[i] : 0;
    s[tid] = v;
    __syncthreads();
    #pragma unroll
    for (int off = 1; off < SCAN_T; off <<= 1) {
        int t = (tid >= off) ? s[tid - off] : 0;
        __syncthreads();
        s[tid] += t;
        __syncthreads();
    }
    if (i < NN) g_rowptr[i + 1] = s[tid];
    if (tid == SCAN_T - 1) g_bsum[blockIdx.x] = s[tid];
}
__global__ __launch_bounds__(SCAN_T) void k_scan3m() {
    __shared__ int off_s;
    int blk = blockIdx.x;
    if (threadIdx.x < 32) {
        int lane = threadIdx.x;
        int s = 0;
        for (int j = lane; j < blk; j += 32) s += g_bsum[j];
        #pragma unroll
        for (int o = 16; o > 0; o >>= 1) s += __shfl_xor_sync(0xFFFFFFFFu, s, o);
        if (lane == 0) off_s = s;
    }
    __syncthreads();
    int off = off_s;
    int i = blk * SCAN_T + threadIdx.x;
    if (i < NN) {
        int r = g_rowptr[i + 1] + off;
        g_rowptr[i + 1] = r;
        g_cursor[i] = r - g_deg[i];
    }
    if (i == 0) g_rowptr[0] = 0;
}
__global__ void k_scatter(const int* __restrict__ ei) {
    int e = blockIdx.x * blockDim.x + threadIdx.x;
    if (e >= EP) return;
    int s, dn;
    if (e < EE) { s = ei[e]; dn = ei[EE + e]; }
    else        { s = e - EE; dn = s; }
    int pos = atomicAdd(&g_cursor[dn], 1);
    g_srcidx[pos] = s;
}

// ============= FP16 GEMM (m16n8k16, ldmatrix) + fused attention epilogue =====
#define TBM 128
#define TBK 32
#define TSH 40

__device__ __forceinline__ void ldsm_x4(unsigned& r0, unsigned& r1,
                                        unsigned& r2, unsigned& r3, unsigned addr) {
    asm volatile("ldmatrix.sync.aligned.m8n8.x4.shared.b16 {%0,%1,%2,%3}, [%4];"
                 : "=r"(r0), "=r"(r1), "=r"(r2), "=r"(r3) : "r"(addr));
}
__device__ __forceinline__ void ldsm_x2(unsigned& r0, unsigned& r1, unsigned addr) {
    asm volatile("ldmatrix.sync.aligned.m8n8.x2.shared.b16 {%0,%1}, [%2];"
                 : "=r"(r0), "=r"(r1) : "r"(addr));
}

template<int NTJ, bool HIN, bool HOUT>
__global__ __launch_bounds__(256, 2) void k_h16gemm(
    const void* __restrict__ Ain, const float* __restrict__ B,
    void* __restrict__ Cout, int M, int N, int K,
    const float* __restrict__ avs, const float* __restrict__ avd,
    float* __restrict__ as_out, float* __restrict__ ad_out, int heads)
{
    const int TBNE = 32 * NTJ;              // 128 or 64
    extern __shared__ __half smem_h[];
    __half* Abase = smem_h;                         // [2][TBM][TSH]
    __half* Bbase = smem_h + 2 * TBM * TSH;         // [2][TBNE][TSH]

    int tid = threadIdx.x;
    int bm = blockIdx.y * TBM, bn = blockIdx.x * (4 * 8 * NTJ);
    int wid = tid >> 5, lane = tid & 31;
    int wm = (wid >> 2) * 64;
    int wn = (wid & 3) * (8 * NTJ);
    int g  = lane >> 2;
    int t4 = lane & 3;

    int r0 = tid >> 3;
    int c4 = (tid & 7) * 4;

    int lane7 = lane & 7;
    int seg   = lane >> 3;
    unsigned sA = (unsigned)__cvta_generic_to_shared(Abase);
    unsigned sB = (unsigned)__cvta_generic_to_shared(Bbase);
    unsigned aAddr[4];
    #pragma unroll
    for (int mt = 0; mt < 4; mt++) {
        int row = wm + mt * 16 + (seg & 1) * 8 + lane7;
        aAddr[mt] = sA + (unsigned)((row * TSH + (seg >> 1) * 8) * 2);
    }
    unsigned bAddr[NTJ];
    #pragma unroll
    for (int ntj = 0; ntj < NTJ; ntj++) {
        int col = wn + ntj * 8 + lane7;
        bAddr[ntj] = sB + (unsigned)((col * TSH + (seg & 1) * 8) * 2);
    }
    const unsigned ABUF = (unsigned)(TBM * TSH * 2);
    const unsigned BBUF = (unsigned)(TBNE * TSH * 2);

    float c[4][NTJ][4];
    #pragma unroll
    for (int i = 0; i < 4; i++)
        #pragma unroll
        for (int j = 0; j < NTJ; j++)
            #pragma unroll
            for (int r = 0; r < 4; r++) c[i][j][r] = 0.f;

    const float4 zero4 = make_float4(0.f, 0.f, 0.f, 0.f);
    const uint2  zero2 = make_uint2(0u, 0u);
    float4 pa[4], pb[NTJ];
    uint2  pah[4];
    int nt = K / TBK;

    #pragma unroll
    for (int i = 0; i < 4; i++) {
        int ar = bm + r0 + 32 * i;
        if (HIN) {
            const __half* Ah = (const __half*)Ain;
            pah[i] = (ar < M) ? *(const uint2*)(Ah + (size_t)ar * K + c4) : zero2;
        } else {
            const float* Af = (const float*)Ain;
            pa[i] = (ar < M) ? *(const float4*)(Af + (size_t)ar * K + c4) : zero4;
        }
    }
    #pragma unroll
    for (int i = 0; i < NTJ; i++) {
        int br = bn + r0 + 32 * i;
        pb[i] = (br < N) ? *(const float4*)(B + (size_t)br * K + c4) : zero4;
    }
    {
        #pragma unroll
        for (int i = 0; i < 4; i++) {
            __half* ap = Abase + (r0 + 32 * i) * TSH + c4;
            if (HIN) {
                *(uint2*)ap = pah[i];
            } else {
                ((__half2*)ap)[0] = __floats2half2_rn(pa[i].x, pa[i].y);
                ((__half2*)ap)[1] = __floats2half2_rn(pa[i].z, pa[i].w);
            }
        }
        #pragma unroll
        for (int i = 0; i < NTJ; i++) {
            __half2* bp = (__half2*)(Bbase + (r0 + 32 * i) * TSH + c4);
            bp[0] = __floats2half2_rn(pb[i].x, pb[i].y);
            bp[1] = __floats2half2_rn(pb[i].z, pb[i].w);
        }
    }
    __syncthreads();

    for (int t = 0; t < nt; t++) {
        int cur = t & 1;
        bool more = (t + 1 < nt);
        if (more) {
            int k0 = (t + 1) * TBK;
            #pragma unroll
            for (int i = 0; i < 4; i++) {
                int ar = bm + r0 + 32 * i;
                if (HIN) {
                    const __half* Ah = (const __half*)Ain;
                    pah[i] = (ar < M) ? *(const uint2*)(Ah + (size_t)ar * K + k0 + c4) : zero2;
                } else {
                    const float* Af = (const float*)Ain;
                    pa[i] = (ar < M) ? *(const float4*)(Af + (size_t)ar * K + k0 + c4) : zero4;
                }
            }
            #pragma unroll
            for (int i = 0; i < NTJ; i++) {
                int br = bn + r0 + 32 * i;
                pb[i] = (br < N) ? *(const float4*)(B + (size_t)br * K + k0 + c4) : zero4;
            }
        }
        unsigned aOff = cur * ABUF;
        unsigned bOff = cur * BBUF;
        #pragma unroll
        for (int kc = 0; kc < 2; kc++) {
            unsigned kb = kc * 32;
            unsigned af[4][4], bf[NTJ][2];
            #pragma unroll
            for (int mt = 0; mt < 4; mt++)
                ldsm_x4(af[mt][0], af[mt][1], af[mt][2], af[mt][3],
                        aAddr[mt] + aOff + kb);
            #pragma unroll
            for (int ntj = 0; ntj < NTJ; ntj++)
                ldsm_x2(bf[ntj][0], bf[ntj][1], bAddr[ntj] + bOff + kb);
            #pragma unroll
            for (int mt = 0; mt < 4; mt++)
                #pragma unroll
                for (int ntj = 0; ntj < NTJ; ntj++) {
                    asm volatile(
                        "mma.sync.aligned.m16n8k16.row.col.f32.f16.f16.f32 "
                        "{%0,%1,%2,%3}, {%4,%5,%6,%7}, {%8,%9}, {%0,%1,%2,%3};"
                        : "+f"(c[mt][ntj][0]), "+f"(c[mt][ntj][1]),
                          "+f"(c[mt][ntj][2]), "+f"(c[mt][ntj][3])
                        : "r"(af[mt][0]), "r"(af[mt][1]), "r"(af[mt][2]), "r"(af[mt][3]),
                          "r"(bf[ntj][0]), "r"(bf[ntj][1]));
                }
        }
        if (more) {
            int nx = cur ^ 1;
            __half* Aw = Abase + nx * TBM * TSH;
            __half* Bw = Bbase + nx * TBNE * TSH;
            #pragma unroll
            for (int i = 0; i < 4; i++) {
                __half* ap = Aw + (r0 + 32 * i) * TSH + c4;
                if (HIN) {
                    *(uint2*)ap = pah[i];
                } else {
                    ((__half2*)ap)[0] = __floats2half2_rn(pa[i].x, pa[i].y);
                    ((__half2*)ap)[1] = __floats2half2_rn(pa[i].z, pa[i].w);
                }
            }
            #pragma unroll
            for (int i = 0; i < NTJ; i++) {
                __half2* bp = (__half2*)(Bw + (r0 + 32 * i) * TSH + c4);
                bp[0] = __floats2half2_rn(pb[i].x, pb[i].y);
                bp[1] = __floats2half2_rn(pb[i].z, pb[i].w);
            }
            __syncthreads();
        }
    }

    // ---- C store ----
    #pragma unroll
    for (int mt = 0; mt < 4; mt++) {
        int row0 = bm + wm + mt * 16 + g;
        #pragma unroll
        for (int ntj = 0; ntj < NTJ; ntj++) {
            int col = bn + wn + ntj * 8 + t4 * 2;
            if (HOUT) {
                __half* Ch = (__half*)Cout;
                if (row0 < M && col + 1 < N)
                    *(__half2*)(Ch + (size_t)row0 * N + col) =
                        __floats2half2_rn(c[mt][ntj][0], c[mt][ntj][1]);
                if (row0 + 8 < M && col + 1 < N)
                    *(__half2*)(Ch + (size_t)(row0 + 8) * N + col) =
                        __floats2half2_rn(c[mt][ntj][2], c[mt][ntj][3]);
            } else {
                float* Cf = (float*)Cout;
                if (row0 < M && col + 1 < N) {
                    Cf[(size_t)row0 * N + col]     = c[mt][ntj][0];
                    Cf[(size_t)row0 * N + col + 1] = c[mt][ntj][1];
                }
                if (row0 + 8 < M && col + 1 < N) {
                    Cf[(size_t)(row0 + 8) * N + col]     = c[mt][ntj][2];
                    Cf[(size_t)(row0 + 8) * N + col + 1] = c[mt][ntj][3];
                }
            }
        }
    }

    // ---- fused attention-coefficient partials ----
    int head = (bn + wn) >> 6;
    if (head < heads) {
        float asac[4][2] = {}, adac[4][2] = {};
        #pragma unroll
        for (int mt = 0; mt < 4; mt++)
            #pragma unroll
            for (int ntj = 0; ntj < NTJ; ntj++) {
                int colb = bn + wn + ntj * 8 + t4 * 2;
                if (colb + 1 < N) {
                    float s0 = avs[colb], s1 = avs[colb + 1];
                    float d0 = avd[colb], d1 = avd[colb + 1];
                    asac[mt][0] += c[mt][ntj][0] * s0 + c[mt][ntj][1] * s1;
                    adac[mt][0] += c[mt][ntj][0] * d0 + c[mt][ntj][1] * d1;
                    asac[mt][1] += c[mt][ntj][2] * s0 + c[mt][ntj][3] * s1;
                    adac[mt][1] += c[mt][ntj][2] * d0 + c[mt][ntj][3] * d1;
                }
            }
        #pragma unroll
        for (int mt = 0; mt < 4; mt++)
            #pragma unroll
            for (int hf = 0; hf < 2; hf++) {
                float v = asac[mt][hf];
                float w = adac[mt][hf];
                v += __shfl_xor_sync(0xFFFFFFFFu, v, 1);
                v += __shfl_xor_sync(0xFFFFFFFFu, v, 2);
                w += __shfl_xor_sync(0xFFFFFFFFu, w, 1);
                w += __shfl_xor_sync(0xFFFFFFFFu, w, 2);
                int row = bm + wm + mt * 16 + g + hf * 8;
                if (t4 == 0 && row < M) {
                    atomicAdd(&as_out[row * heads + head], v);
                    atomicAdd(&ad_out[row * heads + head], w);
                }
            }
    }
}

// ---- softmax layer 1: 8 lanes per dst node (4 rows per warp), 4 heads -------
__global__ __launch_bounds__(256) void k_softmax1()
{
    int w = (blockIdx.x * blockDim.x + threadIdx.x) >> 3;
    int lane8 = threadIdx.x & 7;
    if (w >= NN) return;
    int beg = g_rowptr[w], end = g_rowptr[w + 1];
    const float4* as4 = (const float4*)g_as1;
    float4 adv = ((const float4*)g_ad1)[w];
    float4 mx = make_float4(-1e30f, -1e30f, -1e30f, -1e30f);
    for (int i = beg + lane8; i < end; i += 8) {
        float4 e = as4[g_srcidx[i]];
        e.x += adv.x; e.y += adv.y; e.z += adv.z; e.w += adv.w;
        e.x = (e.x > 0.f) ? e.x : NEG_SLOPE * e.x;
        e.y = (e.y > 0.f) ? e.y : NEG_SLOPE * e.y;
        e.z = (e.z > 0.f) ? e.z : NEG_SLOPE * e.z;
        e.w = (e.w > 0.f) ? e.w : NEG_SLOPE * e.w;
        g_alpha1[i] = e;
        mx.x = fmaxf(mx.x, e.x); mx.y = fmaxf(mx.y, e.y);
        mx.z = fmaxf(mx.z, e.z); mx.w = fmaxf(mx.w, e.w);
    }
    #pragma unroll
    for (int o = 4; o > 0; o >>= 1) {
        mx.x = fmaxf(mx.x, __shfl_xor_sync(0xFFFFFFFFu, mx.x, o));
        mx.y = fmaxf(mx.y, __shfl_xor_sync(0xFFFFFFFFu, mx.y, o));
        mx.z = fmaxf(mx.z, __shfl_xor_sync(0xFFFFFFFFu, mx.z, o));
        mx.w = fmaxf(mx.w, __shfl_xor_sync(0xFFFFFFFFu, mx.w, o));
    }
    float4 sum = make_float4(0.f, 0.f, 0.f, 0.f);
    for (int i = beg + lane8; i < end; i += 8) {
        float4 e = g_alpha1[i];
        e.x = __expf(e.x - mx.x); e.y = __expf(e.y - mx.y);
        e.z = __expf(e.z - mx.z); e.w = __expf(e.w - mx.w);
        g_alpha1[i] = e;
        sum.x += e.x; sum.y += e.y; sum.z += e.z; sum.w += e.w;
    }
    #pragma unroll
    for (int o = 4; o > 0; o >>= 1) {
        sum.x += __shfl_xor_sync(0xFFFFFFFFu, sum.x, o);
        sum.y += __shfl_xor_sync(0xFFFFFFFFu, sum.y, o);
        sum.z += __shfl_xor_sync(0xFFFFFFFFu, sum.z, o);
        sum.w += __shfl_xor_sync(0xFFFFFFFFu, sum.w, o);
    }
    if (lane8 == 0)
        g_rd1[w] = make_float4(1.f / sum.x, 1.f / sum.y, 1.f / sum.z, 1.f / sum.w);
}

// ---- softmax layer 2: 8 lanes per dst node ----------------------------------
__global__ __launch_bounds__(256) void k_softmax2()
{
    int w = (blockIdx.x * blockDim.x + threadIdx.x) >> 3;
    int lane8 = threadIdx.x & 7;
    if (w >= NN) return;
    int beg = g_rowptr[w], end = g_rowptr[w + 1];
    float adv = g_ad2[w];
    float mx = -1e30f;
    for (int i = beg + lane8; i < end; i += 8) {
        float e = g_as2[g_srcidx[i]] + adv;
        e = (e > 0.f) ? e : NEG_SLOPE * e;
        g_alpha2[i] = e;
        mx = fmaxf(mx, e);
    }
    #pragma unroll
    for (int o = 4; o > 0; o >>= 1)
        mx = fmaxf(mx, __shfl_xor_sync(0xFFFFFFFFu, mx, o));
    float sum = 0.f;
    for (int i = beg + lane8; i < end; i += 8) {
        float e = __expf(g_alpha2[i] - mx);
        g_alpha2[i] = e;
        sum += e;
    }
    #pragma unroll
    for (int o = 4; o > 0; o >>= 1)
        sum += __shfl_xor_sync(0xFFFFFFFFu, sum, o);
    if (lane8 == 0) g_rd2[w] = 1.f / sum;
}

// ---- aggregation layer 1: 64 threads per dst row, fp16 gathers, fp16 out ----
__global__ __launch_bounds__(256) void k_agg1(const float* __restrict__ b1)
{
    int row = blockIdx.x * 4 + (threadIdx.x >> 6);
    if (row >= NN) return;
    int q = threadIdx.x & 63;
    int head = q >> 4;
    int beg = g_rowptr[row], end = g_rowptr[row + 1];
    float4 rdv = g_rd1[row];
    float rd = (head == 0) ? rdv.x : (head == 1) ? rdv.y : (head == 2) ? rdv.z : rdv.w;
    float4 acc0 = make_float4(0.f, 0.f, 0.f, 0.f);
    float4 acc1 = make_float4(0.f, 0.f, 0.f, 0.f);
    int i = beg;
    for (; i + 2 <= end; i += 2) {
        int s0 = g_srcidx[i], s1 = g_srcidx[i + 1];
        float4 a40 = g_alpha1[i], a41 = g_alpha1[i + 1];
        float a0 = (head == 0) ? a40.x : (head == 1) ? a40.y : (head == 2) ? a40.z : a40.w;
        float a1 = (head == 0) ? a41.x : (head == 1) ? a41.y : (head == 2) ? a41.z : a41.w;
        const __half2* p0 = (const __half2*)(g_h1h + (size_t)s0 * HC1 + q * 4);
        const __half2* p1 = (const __half2*)(g_h1h + (size_t)s1 * HC1 + q * 4);
        float2 h0a = __half22float2(p0[0]), h0b = __half22float2(p0[1]);
        float2 h1a = __half22float2(p1[0]), h1b = __half22float2(p1[1]);
        acc0.x += a0 * h0a.x; acc0.y += a0 * h0a.y; acc0.z += a0 * h0b.x; acc0.w += a0 * h0b.y;
        acc1.x += a1 * h1a.x; acc1.y += a1 * h1a.y; acc1.z += a1 * h1b.x; acc1.w += a1 * h1b.y;
    }
    if (i < end) {
        int s0 = g_srcidx[i];
        float4 a40 = g_alpha1[i];
        float a0 = (head == 0) ? a40.x : (head == 1) ? a40.y : (head == 2) ? a40.z : a40.w;
        const __half2* p0 = (const __half2*)(g_h1h + (size_t)s0 * HC1 + q * 4);
        float2 h0a = __half22float2(p0[0]), h0b = __half22float2(p0[1]);
        acc0.x += a0 * h0a.x; acc0.y += a0 * h0a.y; acc0.z += a0 * h0b.x; acc0.w += a0 * h0b.y;
    }
    float4 acc = make_float4((acc0.x + acc1.x) * rd, (acc0.y + acc1.y) * rd,
                             (acc0.z + acc1.z) * rd, (acc0.w + acc1.w) * rd);
    float4 bb = *(const float4*)(b1 + q * 4);
    acc.x += bb.x; acc.y += bb.y; acc.z += bb.z; acc.w += bb.w;
    acc.x = (acc.x > 0.f) ? acc.x : expm1f(acc.x);
    acc.y = (acc.y > 0.f) ? acc.y : expm1f(acc.y);
    acc.z = (acc.z > 0.f) ? acc.z : expm1f(acc.z);
    acc.w = (acc.w > 0.f) ? acc.w : expm1f(acc.w);
    __half2* xp = (__half2*)(g_x2h + (size_t)row * HC1 + q * 4);
    xp[0] = __floats2half2_rn(acc.x, acc.y);
    xp[1] = __floats2half2_rn(acc.z, acc.w);
}

// ---- aggregation layer 2: 16 threads per dst row, fp16 gathers --------------
__global__ __launch_bounds__(256) void k_agg2(const float* __restrict__ b2,
                                              float* __restrict__ out)
{
    int row = blockIdx.x * 16 + (threadIdx.x >> 4);
    if (row >= NN) return;
    int q = threadIdx.x & 15;
    int beg = g_rowptr[row], end = g_rowptr[row + 1];
    float rd = g_rd2[row];
    float4 acc0 = make_float4(0.f, 0.f, 0.f, 0.f);
    float4 acc1 = make_float4(0.f, 0.f, 0.f, 0.f);
    int i = beg;
    for (; i + 2 <= end; i += 2) {
        int s0 = g_srcidx[i], s1 = g_srcidx[i + 1];
        float a0 = g_alpha2[i], a1 = g_alpha2[i + 1];
        const __half2* p0 = (const __half2*)(g_h2h + (size_t)s0 * OC + q * 4);
        const __half2* p1 = (const __half2*)(g_h2h + (size_t)s1 * OC + q * 4);
        float2 h0a = __half22float2(p0[0]), h0b = __half22float2(p0[1]);
        float2 h1a = __half22float2(p1[0]), h1b = __half22float2(p1[1]);
        acc0.x += a0 * h0a.x; acc0.y += a0 * h0a.y; acc0.z += a0 * h0b.x; acc0.w += a0 * h0b.y;
        acc1.x += a1 * h1a.x; acc1.y += a1 * h1a.y; acc1.z += a1 * h1b.x; acc1.w += a1 * h1b.y;
    }
    if (i < end) {
        int s0 = g_srcidx[i];
        float a0 = g_alpha2[i];
        const __half2* p0 = (const __half2*)(g_h2h + (size_t)s0 * OC + q * 4);
        float2 h0a = __half22float2(p0[0]), h0b = __half22float2(p0[1]);
        acc0.x += a0 * h0a.x; acc0.y += a0 * h0a.y; acc0.z += a0 * h0b.x; acc0.w += a0 * h0b.y;
    }
    float4 bb = *(const float4*)(b2 + q * 4);
    float4 acc = make_float4((acc0.x + acc1.x) * rd + bb.x, (acc0.y + acc1.y) * rd + bb.y,
                             (acc0.z + acc1.z) * rd + bb.z, (acc0.w + acc1.w) * rd + bb.w);
    *(float4*)(out + (size_t)row * OC + q * 4) = acc;
}

// =============================================================================
extern "C" void kernel_launch(void* const* d_in, const int* in_sizes, int n_in,
                              void* d_out, int out_size)
{
    const float* x     = (const float*)d_in[0];
    const int*   ei    = (const int*)d_in[1];
    const float* W1    = (const float*)d_in[2];
    const float* a_s1  = (const float*)d_in[3];
    const float* a_d1  = (const float*)d_in[4];
    const float* b1    = (const float*)d_in[5];
    const float* W2    = (const float*)d_in[6];
    const float* a_s2  = (const float*)d_in[7];
    const float* a_d2  = (const float*)d_in[8];
    const float* b2    = (const float*)d_in[9];
    float*       out   = (float*)d_out;

    __half *h1h, *x2h, *h2h;
    float *as1, *ad1, *as2, *ad2;
    cudaGetSymbolAddress((void**)&h1h, g_h1h);
    cudaGetSymbolAddress((void**)&x2h, g_x2h);
    cudaGetSymbolAddress((void**)&h2h, g_h2h);
    cudaGetSymbolAddress((void**)&as1, g_as1);
    cudaGetSymbolAddress((void**)&ad1, g_ad1);
    cudaGetSymbolAddress((void**)&as2, g_as2);
    cudaGetSymbolAddress((void**)&ad2, g_ad2);

    const int SMEM_L1 = (2 * TBM * TSH + 2 * 128 * TSH) * 2;   // NTJ=4
    const int SMEM_L2 = (2 * TBM * TSH + 2 * 64  * TSH) * 2;   // NTJ=2
    cudaFuncSetAttribute((const void*)k_h16gemm<4, false, true>,
                         cudaFuncAttributeMaxDynamicSharedMemorySize, SMEM_L1);
    cudaFuncSetAttribute((const void*)k_h16gemm<2, true, true>,
                         cudaFuncAttributeMaxDynamicSharedMemorySize, SMEM_L2);

    cudaStream_t s2;
    cudaStreamCreate(&s2);
    cudaEvent_t evFork, evJoin;
    cudaEventCreateWithFlags(&evFork, cudaEventDisableTiming);
    cudaEventCreateWithFlags(&evJoin, cudaEventDisableTiming);

    // ---- fork: CSR build on s2, concurrent with GEMM1 ----
    cudaEventRecord(evFork, 0);
    cudaStreamWaitEvent(s2, evFork, 0);
    k_zero_deg<<<(NN + 255) / 256, 256, 0, s2>>>();
    k_count<<<(EP + 255) / 256, 256, 0, s2>>>(ei);
    k_scan1<<<NTILES, SCAN_T, 0, s2>>>();
    k_scan3m<<<NTILES, SCAN_T, 0, s2>>>();
    k_scatter<<<(EP + 255) / 256, 256, 0, s2>>>(ei);
    cudaEventRecord(evJoin, s2);

    // ---- main stream: attn zero + GEMM1 (fp32 in, fp16 out) ----
    k_zero_attn<<<(NN + 255) / 256, 256>>>();
    {
        dim3 grid(HC1 / 128, (NN + TBM - 1) / TBM);
        k_h16gemm<4, false, true><<<grid, 256, SMEM_L1>>>(x, W1, h1h, NN, HC1, INC,
                                                          a_s1, a_d1, as1, ad1, H1);
    }

    // ---- join ----
    cudaStreamWaitEvent(0, evJoin, 0);
    k_softmax1<<<(NN * 8 + 255) / 256, 256>>>();
    k_agg1<<<(NN + 3) / 4, 256>>>(b1);

    // ---- layer 2 (fp16 in, fp16 out, 64-wide tile) ----
    {
        dim3 grid(OC / 64, (NN + TBM - 1) / TBM);
        k_h16gemm<2, true, true><<<grid, 256, SMEM_L2>>>(x2h, W2, h2h, NN, OC, HC1,
                                                         a_s2, a_d2, as2, ad2, 1);
    }
    k_softmax2<<<(NN * 8 + 255) / 256, 256>>>();
    k_agg2<<<(NN + 15) / 16, 256>>>(b2, out);
}